// round 2
// baseline (speedup 1.0000x reference)
#include <cuda_runtime.h>
#include <cuda_bf16.h>
#include <math.h>

// Problem constants
#define Bb   4
#define Nn   4096
#define Vv   512
#define Dd   512
#define Hh   8
#define DH   64
#define Ll   4
#define WS   128
#define Rr   256
#define Cc   10
#define FF   2048
#define NW   (Nn / WS)           // 32
#define SCALE 0.125f             // 64^-0.5
#define KFIN ((long)Nn * Vv)     // 2097152 per batch row
#define NCHUNK 2048              // KFIN / 1024

// ---------------- scratch (device globals; no allocation) ----------------
__device__ float g_h  [(size_t)Bb * Nn * Dd];
__device__ float g_y  [(size_t)Bb * Nn * Dd];
__device__ float g_q  [(size_t)Bb * Nn * Hh * DH];
__device__ float g_kv [(size_t)Bb * Nn * 2 * Hh * DH];
__device__ float g_p  [(size_t)Bb * Hh * Nn * Rr];
__device__ float g_gk [(size_t)Bb * Hh * Rr * DH];
__device__ float g_gv [(size_t)Bb * Hh * Rr * DH];
__device__ float g_gkn[(size_t)Bb * Hh * Rr * DH];
__device__ float g_gvn[(size_t)Bb * Hh * Rr * DH];
__device__ float g_lk [(size_t)Bb * Hh * Nn * DH];
__device__ float g_lv [(size_t)Bb * Hh * Nn * DH];
__device__ float g_sim[(size_t)Bb * Hh * Nn * (WS + Rr)];
__device__ float g_o  [(size_t)Bb * Nn * Hh * DH];
__device__ float g_f1 [(size_t)Bb * Nn * FF];
__device__ float g_log[(size_t)Bb * Nn * Vv];
__device__ float g_part[(size_t)Bb * NCHUNK * Cc];

// ---------------- helpers ----------------
__device__ __forceinline__ float gelu_f(float x) {
    const float k0 = 0.7978845608028654f, k1 = 0.044715f;
    return 0.5f * x * (1.f + tanhf(k0 * (x + k1 * x * x * x)));
}

// ---------------- generic strided batched SGEMM ----------------
// C[m,n] (op) = alpha * sum_k A[m*sAm + k*sAk] * B[k*sBk + n*sBn]  (+ bias[n]) (+gelu)
// blockIdx.z decomposed into (d0,d1,d2) with per-matrix batch strides.
#define BM 128
#define BN 128
#define BKG 8

__global__ __launch_bounds__(256) void sgemm(
    const float* __restrict__ A, const float* __restrict__ B,
    const float* __restrict__ bias, float* __restrict__ C,
    int M, int N, int K,
    long sAm, long sAk, long sBk, long sBn, long sCm,
    int D1, int D2,
    long a0, long a1, long a2,
    long b0, long b1, long b2,
    long c0, long c1, long c2,
    float alpha, int accumulate, int act)
{
    int z  = blockIdx.z;
    int d2 = z % D2;
    int t  = z / D2;
    int d1 = t % D1;
    int d0 = t / D1;
    A += (long)d0 * a0 + (long)d1 * a1 + (long)d2 * a2;
    B += (long)d0 * b0 + (long)d1 * b1 + (long)d2 * b2;
    C += (long)d0 * c0 + (long)d1 * c1 + (long)d2 * c2;

    __shared__ float As[BKG][BM];
    __shared__ float Bs[BKG][BN];

    int tid = threadIdx.x;
    int tx = tid % 16, ty = tid / 16;
    int mBase = blockIdx.y * BM;
    int nBase = blockIdx.x * BN;

    float acc[8][8];
#pragma unroll
    for (int i = 0; i < 8; i++)
#pragma unroll
        for (int j = 0; j < 8; j++) acc[i][j] = 0.f;

    for (int k0 = 0; k0 < K; k0 += BKG) {
#pragma unroll
        for (int i = 0; i < 4; i++) {
            int e = tid + i * 256;
            int m = e % BM, kk = e / BM;
            int gm = mBase + m;
            float v = 0.f;
            if (gm < M) v = A[(long)gm * sAm + (long)(k0 + kk) * sAk];
            As[kk][m] = v;
        }
#pragma unroll
        for (int i = 0; i < 4; i++) {
            int e = tid + i * 256;
            int n = e % BN, kk = e / BN;
            int gn = nBase + n;
            float v = 0.f;
            if (gn < N) v = B[(long)(k0 + kk) * sBk + (long)gn * sBn];
            Bs[kk][n] = v;
        }
        __syncthreads();
#pragma unroll
        for (int kk = 0; kk < BKG; kk++) {
            float ra[8], rb[8];
#pragma unroll
            for (int i = 0; i < 8; i++) ra[i] = As[kk][ty * 8 + i];
#pragma unroll
            for (int j = 0; j < 8; j++) rb[j] = Bs[kk][tx * 8 + j];
#pragma unroll
            for (int i = 0; i < 8; i++)
#pragma unroll
                for (int j = 0; j < 8; j++)
                    acc[i][j] = fmaf(ra[i], rb[j], acc[i][j]);
        }
        __syncthreads();
    }

#pragma unroll
    for (int i = 0; i < 8; i++) {
        int gm = mBase + ty * 8 + i;
        if (gm >= M) continue;
#pragma unroll
        for (int j = 0; j < 8; j++) {
            int gn = nBase + tx * 8 + j;
            if (gn >= N) continue;
            float v = alpha * acc[i][j];
            if (bias) v += bias[gn];
            if (act) v = gelu_f(v);
            long off = (long)gm * sCm + gn;
            if (accumulate) C[off] += v; else C[off] = v;
        }
    }
}

// ---------------- LayerNorm, D=512, block per row ----------------
__global__ __launch_bounds__(256) void ln512(
    const float* __restrict__ in, const float* __restrict__ g,
    const float* __restrict__ b, float* __restrict__ out)
{
    long row = blockIdx.x;
    const float* x = in + row * Dd;
    float* o = out + row * Dd;
    int tid = threadIdx.x;
    float v0 = x[tid], v1 = x[tid + 256];

    __shared__ float red[256];
    red[tid] = v0 + v1;
    __syncthreads();
    for (int s = 128; s > 0; s >>= 1) { if (tid < s) red[tid] += red[tid + s]; __syncthreads(); }
    float mu = red[0] * (1.f / Dd);
    __syncthreads();
    float d0 = v0 - mu, d1 = v1 - mu;
    red[tid] = d0 * d0 + d1 * d1;
    __syncthreads();
    for (int s = 128; s > 0; s >>= 1) { if (tid < s) red[tid] += red[tid + s]; __syncthreads(); }
    float rs = rsqrtf(red[0] * (1.f / Dd) + 1e-5f);
    o[tid]       = d0 * rs * g[tid]       + b[tid];
    o[tid + 256] = d1 * rs * g[tid + 256] + b[tid + 256];
}

// ---------------- LayerNorm, D=64, warp per row, strided input ----------------
// row = warp; decompose row -> (d0,d1,d2); input offset = d0*s0+d1*s1+d2*s2; output contiguous
__global__ __launch_bounds__(128) void ln64(
    const float* __restrict__ in, const float* __restrict__ g,
    const float* __restrict__ b, float* __restrict__ out,
    int D1, int D2, long s0, long s1, long s2)
{
    long warp = ((long)blockIdx.x * blockDim.x + threadIdx.x) >> 5;
    int lane = threadIdx.x & 31;
    long d2 = warp % D2;
    long t  = warp / D2;
    long d1 = t % D1;
    long d0 = t / D1;
    const float* x = in + d0 * s0 + d1 * s1 + d2 * s2;
    float v0 = x[lane], v1 = x[lane + 32];
    float s = v0 + v1;
#pragma unroll
    for (int o = 16; o; o >>= 1) s += __shfl_xor_sync(0xffffffffu, s, o);
    float mu = s * (1.f / 64.f);
    float q0 = v0 - mu, q1 = v1 - mu;
    float q = q0 * q0 + q1 * q1;
#pragma unroll
    for (int o = 16; o; o >>= 1) q += __shfl_xor_sync(0xffffffffu, q, o);
    float rs = rsqrtf(q * (1.f / 64.f) + 1e-5f);
    float* o = out + warp * 64;
    o[lane]      = q0 * rs * g[lane]      + b[lane];
    o[lane + 32] = q1 * rs * g[lane + 32] + b[lane + 32];
}

// ---------------- embedding ----------------
__global__ void embed(const int* __restrict__ x, const float* __restrict__ tok,
                      const float* __restrict__ pos, float* __restrict__ h)
{
    long i = (long)blockIdx.x * blockDim.x + threadIdx.x;
    if (i >= (long)Bb * Nn * Dd) return;
    int d = i % Dd;
    long bn = i / Dd;
    int n = bn % Nn;
    int tokid = x[bn];
    h[i] = tok[(long)tokid * Dd + d] + pos[(long)n * Dd + d];
}

// ---------------- softmax over axis=2 (n) of p (BH, N, R) ----------------
__global__ __launch_bounds__(256) void softmax_col(float* __restrict__ p)
{
    int r = threadIdx.x;                 // 0..255
    float* base = p + (long)blockIdx.x * Nn * Rr + r;
    float m = -1e30f;
    for (int n = 0; n < Nn; n++) m = fmaxf(m, base[(long)n * Rr]);
    float s = 0.f;
    for (int n = 0; n < Nn; n++) s += __expf(base[(long)n * Rr] - m);
    float inv = 1.f / s;
    for (int n = 0; n < Nn; n++) {
        long off = (long)n * Rr;
        base[off] = __expf(base[off] - m) * inv;
    }
}

// ---------------- softmax over rows of length 384 ----------------
__global__ __launch_bounds__(128) void softmax_row384(float* __restrict__ s)
{
    float* r = s + (long)blockIdx.x * (WS + Rr);
    int tid = threadIdx.x;
    float v0 = r[tid], v1 = r[tid + 128], v2 = r[tid + 256];
    __shared__ float red[128];
    red[tid] = fmaxf(v0, fmaxf(v1, v2));
    __syncthreads();
    for (int st = 64; st > 0; st >>= 1) { if (tid < st) red[tid] = fmaxf(red[tid], red[tid + st]); __syncthreads(); }
    float m = red[0];
    __syncthreads();
    float e0 = __expf(v0 - m), e1 = __expf(v1 - m), e2 = __expf(v2 - m);
    red[tid] = e0 + e1 + e2;
    __syncthreads();
    for (int st = 64; st > 0; st >>= 1) { if (tid < st) red[tid] += red[tid + st]; __syncthreads(); }
    float inv = 1.f / red[0];
    r[tid] = e0 * inv; r[tid + 128] = e1 * inv; r[tid + 256] = e2 * inv;
}

// ---------------- final head: split-K partials (deterministic) ----------------
__global__ __launch_bounds__(256) void head_partial(
    const float* __restrict__ logits, const float* __restrict__ Wfin,
    float* __restrict__ part)
{
    int b = blockIdx.y;
    long k0 = (long)blockIdx.x * 1024;
    const float* lrow = logits + (long)b * KFIN;
    float acc[Cc];
#pragma unroll
    for (int c = 0; c < Cc; c++) acc[c] = 0.f;
    for (int i = threadIdx.x; i < 1024; i += 256) {
        long k = k0 + i;
        float l = lrow[k];
        const float* w = Wfin + k * Cc;
#pragma unroll
        for (int c = 0; c < Cc; c++) acc[c] = fmaf(l, w[c], acc[c]);
    }
#pragma unroll
    for (int c = 0; c < Cc; c++)
#pragma unroll
        for (int o = 16; o; o >>= 1) acc[c] += __shfl_xor_sync(0xffffffffu, acc[c], o);
    __shared__ float sm[8][Cc];
    int warp = threadIdx.x >> 5, lane = threadIdx.x & 31;
    if (lane == 0)
#pragma unroll
        for (int c = 0; c < Cc; c++) sm[warp][c] = acc[c];
    __syncthreads();
    if (threadIdx.x < Cc) {
        float s = 0.f;
#pragma unroll
        for (int w = 0; w < 8; w++) s += sm[w][threadIdx.x];
        part[((long)b * NCHUNK + blockIdx.x) * Cc + threadIdx.x] = s;
    }
}

__global__ void head_reduce(const float* __restrict__ part,
                            const float* __restrict__ bfin, float* __restrict__ out)
{
    int t = threadIdx.x;
    if (t < Bb * Cc) {
        int b = t / Cc, c = t % Cc;
        float s = bfin[c];
        for (int j = 0; j < NCHUNK; j++) s += part[((long)b * NCHUNK + j) * Cc + c];
        out[b * Cc + c] = s;
    }
}

// ---------------- host launcher ----------------
static void launch_gemm(const float* A, const float* B, const float* bias, float* C,
                        int M, int N, int K,
                        long sAm, long sAk, long sBk, long sBn, long sCm,
                        int D0, int D1, int D2,
                        long a0, long a1, long a2,
                        long b0, long b1, long b2,
                        long c0, long c1, long c2,
                        float alpha, int accum, int act)
{
    dim3 grid((N + BN - 1) / BN, (M + BM - 1) / BM, D0 * D1 * D2);
    sgemm<<<grid, 256>>>(A, B, bias, C, M, N, K, sAm, sAk, sBk, sBn, sCm,
                         D1, D2, a0, a1, a2, b0, b1, b2, c0, c1, c2,
                         alpha, accum, act);
}

extern "C" void kernel_launch(void* const* d_in, const int* in_sizes, int n_in,
                              void* d_out, int out_size)
{
    const int*   x_in    = (const int*)  d_in[0];
    const float* tok_emb = (const float*)d_in[1];
    const float* pos_emb = (const float*)d_in[2];
    const float* ln1_g   = (const float*)d_in[3];
    const float* ln1_b   = (const float*)d_in[4];
    const float* Wq      = (const float*)d_in[5];
    const float* Wkv     = (const float*)d_in[6];
    const float* Wp      = (const float*)d_in[7];
    const float* lln_g   = (const float*)d_in[8];
    const float* lln_b   = (const float*)d_in[9];
    const float* gln_g   = (const float*)d_in[10];
    const float* gln_b   = (const float*)d_in[11];
    const float* Wo      = (const float*)d_in[12];
    const float* bo      = (const float*)d_in[13];
    const float* ln2_g   = (const float*)d_in[14];
    const float* ln2_b   = (const float*)d_in[15];
    const float* W1      = (const float*)d_in[16];
    const float* b1      = (const float*)d_in[17];
    const float* W2      = (const float*)d_in[18];
    const float* b2      = (const float*)d_in[19];
    const float* lnf_g   = (const float*)d_in[20];
    const float* lnf_b   = (const float*)d_in[21];
    const float* Wlog    = (const float*)d_in[22];
    const float* blog    = (const float*)d_in[23];
    const float* Wfin    = (const float*)d_in[24];
    const float* bfin    = (const float*)d_in[25];
    float* out = (float*)d_out;

    float *ph, *py, *pq, *pkv, *pp, *pgk, *pgv, *pgkn, *pgvn, *plk, *plv, *psim, *po, *pf1, *plog, *ppart;
    cudaGetSymbolAddress((void**)&ph,   g_h);
    cudaGetSymbolAddress((void**)&py,   g_y);
    cudaGetSymbolAddress((void**)&pq,   g_q);
    cudaGetSymbolAddress((void**)&pkv,  g_kv);
    cudaGetSymbolAddress((void**)&pp,   g_p);
    cudaGetSymbolAddress((void**)&pgk,  g_gk);
    cudaGetSymbolAddress((void**)&pgv,  g_gv);
    cudaGetSymbolAddress((void**)&pgkn, g_gkn);
    cudaGetSymbolAddress((void**)&pgvn, g_gvn);
    cudaGetSymbolAddress((void**)&plk,  g_lk);
    cudaGetSymbolAddress((void**)&plv,  g_lv);
    cudaGetSymbolAddress((void**)&psim, g_sim);
    cudaGetSymbolAddress((void**)&po,   g_o);
    cudaGetSymbolAddress((void**)&pf1,  g_f1);
    cudaGetSymbolAddress((void**)&plog, g_log);
    cudaGetSymbolAddress((void**)&ppart,g_part);

    const long BND = (long)Bb * Nn * Dd;          // 8388608
    const int  MBN = Bb * Nn;                     // 16384

    // embedding
    embed<<<(BND + 255) / 256, 256>>>(x_in, tok_emb, pos_emb, ph);

    for (int l = 0; l < Ll; l++) {
        const float* wq  = Wq  + (long)l * Dd * Hh * DH;
        const float* wkv = Wkv + (long)l * Dd * 2 * Hh * DH;
        const float* wp  = Wp  + (long)l * DH * Rr;
        const float* wo  = Wo  + (long)l * Hh * DH * Dd;
        const float* w1  = W1  + (long)l * Dd * FF;
        const float* w2  = W2  + (long)l * FF * Dd;

        // y = LN1(h)
        ln512<<<MBN, 256>>>(ph, ln1_g + l * Dd, ln1_b + l * Dd, py);

        // q = y @ Wq * SCALE   (B*N, 512) x (512, 512)
        launch_gemm(py, wq, nullptr, pq, MBN, Hh * DH, Dd,
                    Dd, 1, Hh * DH, 1, Hh * DH,
                    1, 1, 1, 0,0,0, 0,0,0, 0,0,0, SCALE, 0, 0);

        // kv = y @ Wkv   (B*N, 512) x (512, 1024)
        launch_gemm(py, wkv, nullptr, pkv, MBN, 2 * Hh * DH, Dd,
                    Dd, 1, 2 * Hh * DH, 1, 2 * Hh * DH,
                    1, 1, 1, 0,0,0, 0,0,0, 0,0,0, 1.f, 0, 0);

        // p = k @ Wp   per (b,h): (4096 x 64) x (64 x 256)
        launch_gemm(pkv, wp, nullptr, pp, Nn, Rr, DH,
                    2L * Hh * DH, 1, Rr, 1, Rr,
                    Bb, Hh, 1,
                    (long)Nn * 2 * Hh * DH, DH, 0,
                    0, 0, 0,
                    (long)Hh * Nn * Rr, (long)Nn * Rr, 0,
                    1.f, 0, 0);

        // softmax over n
        softmax_col<<<Bb * Hh, Rr>>>(pp);

        // gk = p^T @ k   per (b,h): (256 x 4096) x (4096 x 64)
        launch_gemm(pp, pkv, nullptr, pgk, Rr, DH, Nn,
                    1, Rr, 2L * Hh * DH, 1, DH,
                    Bb, Hh, 1,
                    (long)Hh * Nn * Rr, (long)Nn * Rr, 0,
                    (long)Nn * 2 * Hh * DH, DH, 0,
                    (long)Hh * Rr * DH, (long)Rr * DH, 0,
                    1.f, 0, 0);
        // gv = p^T @ v
        launch_gemm(pp, pkv + Hh * DH, nullptr, pgv, Rr, DH, Nn,
                    1, Rr, 2L * Hh * DH, 1, DH,
                    Bb, Hh, 1,
                    (long)Hh * Nn * Rr, (long)Nn * Rr, 0,
                    (long)Nn * 2 * Hh * DH, DH, 0,
                    (long)Hh * Rr * DH, (long)Rr * DH, 0,
                    1.f, 0, 0);

        // gln on gk, gv  (rows = B*H*R = 8192, contiguous)
        ln64<<<(Bb * Hh * Rr) / 4, 128>>>(pgk, gln_g + l * DH, gln_b + l * DH, pgkn,
                                          1, Bb * Hh * Rr, 0, 0, DH);
        ln64<<<(Bb * Hh * Rr) / 4, 128>>>(pgv, gln_g + l * DH, gln_b + l * DH, pgvn,
                                          1, Bb * Hh * Rr, 0, 0, DH);

        // lk = lln(k) -> (B,H,N,64) contiguous; input strided out of kv buffer
        ln64<<<(Bb * Hh * Nn) / 4, 128>>>(pkv, lln_g + l * DH, lln_b + l * DH, plk,
                                          Hh, Nn, (long)Nn * 2 * Hh * DH, DH, 2L * Hh * DH);
        ln64<<<(Bb * Hh * Nn) / 4, 128>>>(pkv + Hh * DH, lln_g + l * DH, lln_b + l * DH, plv,
                                          Hh, Nn, (long)Nn * 2 * Hh * DH, DH, 2L * Hh * DH);

        // sim_l = lq @ lk^T   per (b,h,w): (128 x 64) x (64 x 128)
        launch_gemm(pq, plk, nullptr, psim, WS, WS, DH,
                    Hh * DH, 1, 1, DH, WS + Rr,
                    Bb, Hh, NW,
                    (long)Nn * Hh * DH, DH, (long)WS * Hh * DH,
                    (long)Hh * Nn * DH, (long)Nn * DH, (long)WS * DH,
                    (long)Hh * Nn * (WS + Rr), (long)Nn * (WS + Rr), (long)WS * (WS + Rr),
                    1.f, 0, 0);

        // sim_g = lq @ gkn^T  per (b,h): (4096 x 64) x (64 x 256)
        launch_gemm(pq, pgkn, nullptr, psim + WS, Nn, Rr, DH,
                    Hh * DH, 1, 1, DH, WS + Rr,
                    Bb, Hh, 1,
                    (long)Nn * Hh * DH, DH, 0,
                    (long)Hh * Rr * DH, (long)Rr * DH, 0,
                    (long)Hh * Nn * (WS + Rr), (long)Nn * (WS + Rr), 0,
                    1.f, 0, 0);

        // softmax over 384-wide rows
        softmax_row384<<<Bb * Hh * Nn, 128>>>(psim);

        // o = a_l @ lv   per (b,h,w): (128 x 128) x (128 x 64) -> write obuf
        launch_gemm(psim, plv, nullptr, po, WS, DH, WS,
                    WS + Rr, 1, DH, 1, Hh * DH,
                    Bb, Hh, NW,
                    (long)Hh * Nn * (WS + Rr), (long)Nn * (WS + Rr), (long)WS * (WS + Rr),
                    (long)Hh * Nn * DH, (long)Nn * DH, (long)WS * DH,
                    (long)Nn * Hh * DH, DH, (long)WS * Hh * DH,
                    1.f, 0, 0);

        // o += a_g @ gvn  per (b,h): (4096 x 256) x (256 x 64) -> accumulate obuf
        launch_gemm(psim + WS, pgvn, nullptr, po, Nn, DH, Rr,
                    WS + Rr, 1, DH, 1, Hh * DH,
                    Bb, Hh, 1,
                    (long)Hh * Nn * (WS + Rr), (long)Nn * (WS + Rr), 0,
                    (long)Hh * Rr * DH, (long)Rr * DH, 0,
                    (long)Nn * Hh * DH, DH, 0,
                    1.f, 1, 0);

        // h += o @ Wo + bo
        launch_gemm(po, wo, bo + l * Dd, ph, MBN, Dd, Hh * DH,
                    Hh * DH, 1, Dd, 1, Dd,
                    1, 1, 1, 0,0,0, 0,0,0, 0,0,0, 1.f, 1, 0);

        // y = LN2(h)
        ln512<<<MBN, 256>>>(ph, ln2_g + l * Dd, ln2_b + l * Dd, py);

        // f1 = gelu(y @ W1 + b1)
        launch_gemm(py, w1, b1 + (long)l * FF, pf1, MBN, FF, Dd,
                    Dd, 1, FF, 1, FF,
                    1, 1, 1, 0,0,0, 0,0,0, 0,0,0, 1.f, 0, 1);

        // h += f1 @ W2 + b2
        launch_gemm(pf1, w2, b2 + l * Dd, ph, MBN, Dd, FF,
                    FF, 1, Dd, 1, Dd,
                    1, 1, 1, 0,0,0, 0,0,0, 0,0,0, 1.f, 1, 0);
    }

    // final LN + vocab projection
    ln512<<<MBN, 256>>>(ph, lnf_g, lnf_b, py);
    launch_gemm(py, Wlog, blog, plog, MBN, Vv, Dd,
                Dd, 1, Vv, 1, Vv,
                1, 1, 1, 0,0,0, 0,0,0, 0,0,0, 1.f, 0, 0);

    // head: out[b,c] = bfin[c] + sum_k logits[b,k] * Wfin[k,c]
    {
        dim3 grid(NCHUNK, Bb);
        head_partial<<<grid, 256>>>(plog, Wfin, ppart);
        head_reduce<<<1, 64>>>(ppart, bfin, out);
    }
}

// round 5
// speedup vs baseline: 1.8031x; 1.8031x over previous
#include <cuda_runtime.h>
#include <cuda_bf16.h>
#include <math.h>
#include <stdint.h>

// Problem constants
#define Bb   4
#define Nn   4096
#define Vv   512
#define Dd   512
#define Hh   8
#define DH   64
#define Ll   4
#define WS   128
#define Rr   256
#define Cc   10
#define FF   2048
#define NW   (Nn / WS)           // 32
#define SCALE 0.125f             // 64^-0.5
#define KFIN ((long)Nn * Vv)     // 2097152 per batch row
#define NCHUNK 2048              // KFIN / 1024

// ---------------- scratch (device globals; no allocation) ----------------
__device__ float g_h  [(size_t)Bb * Nn * Dd];
__device__ float g_y  [(size_t)Bb * Nn * Dd];
__device__ float g_q  [(size_t)Bb * Nn * Hh * DH];
__device__ float g_kv [(size_t)Bb * Nn * 2 * Hh * DH];
__device__ float g_p  [(size_t)Bb * Hh * Nn * Rr];
__device__ float g_gk [(size_t)Bb * Hh * Rr * DH];
__device__ float g_gv [(size_t)Bb * Hh * Rr * DH];
__device__ float g_gkn[(size_t)Bb * Hh * Rr * DH];
__device__ float g_gvn[(size_t)Bb * Hh * Rr * DH];
__device__ float g_lk [(size_t)Bb * Hh * Nn * DH];
__device__ float g_lv [(size_t)Bb * Hh * Nn * DH];
__device__ float g_sim[(size_t)Bb * Hh * Nn * (WS + Rr)];
__device__ float g_o  [(size_t)Bb * Nn * Hh * DH];
__device__ float g_f1 [(size_t)Bb * Nn * FF];
__device__ float g_log[(size_t)Bb * Nn * Vv];
__device__ float g_part[(size_t)Bb * NCHUNK * Cc];

// ---------------- helpers ----------------
__device__ __forceinline__ float gelu_f(float x) {
    const float k0 = 0.7978845608028654f, k1 = 0.044715f;
    return 0.5f * x * (1.f + tanhf(k0 * (x + k1 * x * x * x)));
}

__device__ __forceinline__ uint32_t smem_u32(const void* p) {
    uint32_t a;
    asm("{ .reg .u64 t; cvta.to.shared.u64 t, %1; cvt.u32.u64 %0, t; }" : "=r"(a) : "l"(p));
    return a;
}

#define LDMATRIX_X4(r0, r1, r2, r3, addr) \
    asm volatile("ldmatrix.sync.aligned.m8n8.x4.shared.b16 {%0,%1,%2,%3}, [%4];" \
        : "=r"(r0), "=r"(r1), "=r"(r2), "=r"(r3) : "r"(addr))

#define MMA_BF16(c, a, b0v, b1v) \
    asm volatile("mma.sync.aligned.m16n8k16.row.col.f32.bf16.bf16.f32 " \
        "{%0,%1,%2,%3}, {%4,%5,%6,%7}, {%8,%9}, {%0,%1,%2,%3};" \
        : "+f"((c)[0]), "+f"((c)[1]), "+f"((c)[2]), "+f"((c)[3]) \
        : "r"((a)[0]), "r"((a)[1]), "r"((a)[2]), "r"((a)[3]), "r"(b0v), "r"(b1v))

__device__ __forceinline__ void split_bf16(float v, unsigned short& hi, unsigned short& lo) {
    __nv_bfloat16 h = __float2bfloat16_rn(v);
    float rem = v - __bfloat162float(h);
    __nv_bfloat16 l = __float2bfloat16_rn(rem);
    hi = __bfloat16_as_ushort(h);
    lo = __bfloat16_as_ushort(l);
}

// ---------------- bf16 split-2 batched strided GEMM (mma.sync) ----------------
// C[m,n] = alpha * sum_k A[m*sAm+k*sAk]*B[k*sBk+n*sBn] (+bias)(+gelu)(+=)
// Tile 128x128, chunk K=32. 8 warps = 2(M) x 4(N); warp tile 64x32.
#define PADK 40   // bf16 elems per smem row (32 data + 8 pad); 80B rows

__global__ __launch_bounds__(256, 2) void tc_gemm(
    const float* __restrict__ A, const float* __restrict__ B,
    const float* __restrict__ bias, float* __restrict__ C,
    int M, int N, int K,
    long sAm, long sAk, long sBk, long sBn, long sCm,
    int D1, int D2,
    long a0, long a1, long a2,
    long b0, long b1, long b2,
    long c0, long c1, long c2,
    float alpha, int accumulate, int act)
{
    __shared__ __align__(16) __nv_bfloat16 sAhi[128 * PADK];
    __shared__ __align__(16) __nv_bfloat16 sAlo[128 * PADK];
    __shared__ __align__(16) __nv_bfloat16 sBhi[128 * PADK];
    __shared__ __align__(16) __nv_bfloat16 sBlo[128 * PADK];

    int z  = blockIdx.z;
    int d2 = z % D2;
    int t  = z / D2;
    int d1 = t % D1;
    int d0 = t / D1;
    A += (long)d0 * a0 + (long)d1 * a1 + (long)d2 * a2;
    B += (long)d0 * b0 + (long)d1 * b1 + (long)d2 * b2;
    C += (long)d0 * c0 + (long)d1 * c1 + (long)d2 * c2;

    int tid  = threadIdx.x;
    int lane = tid & 31;
    int wid  = tid >> 5;
    int wm   = wid & 1;          // 0..1  -> m offset wm*64
    int wn   = wid >> 1;         // 0..3  -> n offset wn*32
    int mBase = blockIdx.y * 128;
    int nBase = blockIdx.x * 128;

    const int aKfast = (sAk == 1);
    const int bKfast = (sBk == 1);
    const int nChunks = (K + 31) >> 5;

    float acc[4][4][4];
#pragma unroll
    for (int i = 0; i < 4; i++)
#pragma unroll
        for (int j = 0; j < 4; j++)
#pragma unroll
            for (int e = 0; e < 4; e++) acc[i][j][e] = 0.f;

    for (int ch = 0; ch < nChunks; ch++) {
        int k0 = ch << 5;

        // ---- load A tile (128 x 32) ----
        if (aKfast) {
#pragma unroll
            for (int i = 0; i < 8; i++) {
                int e = tid + i * 256;            // pair index: 2048 pairs
                int m = e >> 4, kp = e & 15, k = kp * 2;
                int gm = mBase + m;
                float v0 = 0.f, v1 = 0.f;
                if (gm < M) {
                    long base = (long)gm * sAm + (long)(k0 + k);
                    if (k0 + k     < K) v0 = A[base];
                    if (k0 + k + 1 < K) v1 = A[base + 1];
                }
                unsigned short h0, l0, h1, l1;
                split_bf16(v0, h0, l0);
                split_bf16(v1, h1, l1);
                int off = m * PADK + k;
                *(uint32_t*)&sAhi[off] = (uint32_t)h0 | ((uint32_t)h1 << 16);
                *(uint32_t*)&sAlo[off] = (uint32_t)l0 | ((uint32_t)l1 << 16);
            }
        } else {
#pragma unroll
            for (int i = 0; i < 16; i++) {
                int e = tid + i * 256;            // 4096 elems
                int m = e & 127, k = e >> 7;
                int gm = mBase + m, gk = k0 + k;
                float v = 0.f;
                if (gm < M && gk < K) v = A[(long)gm * sAm + (long)gk * sAk];
                unsigned short h, l;
                split_bf16(v, h, l);
                int off = m * PADK + k;
                sAhi[off] = __ushort_as_bfloat16(h);
                sAlo[off] = __ushort_as_bfloat16(l);
            }
        }
        // ---- load B tile (n-major: sB*[n][k] = B[k][n]) ----
        if (bKfast) {
#pragma unroll
            for (int i = 0; i < 8; i++) {
                int e = tid + i * 256;
                int n = e >> 4, kp = e & 15, k = kp * 2;
                int gn = nBase + n;
                float v0 = 0.f, v1 = 0.f;
                if (gn < N) {
                    long base = (long)(k0 + k) * 1 + (long)gn * sBn;
                    if (k0 + k     < K) v0 = B[base];
                    if (k0 + k + 1 < K) v1 = B[base + 1];
                }
                unsigned short h0, l0, h1, l1;
                split_bf16(v0, h0, l0);
                split_bf16(v1, h1, l1);
                int off = n * PADK + k;
                *(uint32_t*)&sBhi[off] = (uint32_t)h0 | ((uint32_t)h1 << 16);
                *(uint32_t*)&sBlo[off] = (uint32_t)l0 | ((uint32_t)l1 << 16);
            }
        } else {
#pragma unroll
            for (int i = 0; i < 16; i++) {
                int e = tid + i * 256;
                int n = e & 127, k = e >> 7;
                int gn = nBase + n, gk = k0 + k;
                float v = 0.f;
                if (gn < N && gk < K) v = B[(long)gk * sBk + (long)gn * sBn];
                unsigned short h, l;
                split_bf16(v, h, l);
                int off = n * PADK + k;
                sBhi[off] = __ushort_as_bfloat16(h);
                sBlo[off] = __ushort_as_bfloat16(l);
            }
        }
        __syncthreads();

        // ---- compute: 3 split passes (AhiBhi, AloBhi, AhiBlo) ----
        int lrow = lane & 15;
        int lcol = (lane >> 4) * 8;
#pragma unroll
        for (int seg = 0; seg < 3; seg++) {
            const __nv_bfloat16* sa = (seg == 1) ? sAlo : sAhi;
            const __nv_bfloat16* sb = (seg == 2) ? sBlo : sBhi;
#pragma unroll
            for (int kk = 0; kk < 2; kk++) {
                int kc = kk * 16 + lcol;
                uint32_t af[4][4];
#pragma unroll
                for (int mf = 0; mf < 4; mf++) {
                    int row = wm * 64 + mf * 16 + lrow;
                    uint32_t addr = smem_u32(&sa[row * PADK + kc]);
                    LDMATRIX_X4(af[mf][0], af[mf][1], af[mf][2], af[mf][3], addr);
                }
                uint32_t bf[2][4];
#pragma unroll
                for (int g = 0; g < 2; g++) {
                    int nrow = wn * 32 + g * 16 + lrow;
                    uint32_t addr = smem_u32(&sb[nrow * PADK + kc]);
                    LDMATRIX_X4(bf[g][0], bf[g][1], bf[g][2], bf[g][3], addr);
                }
#pragma unroll
                for (int mf = 0; mf < 4; mf++) {
#pragma unroll
                    for (int nf = 0; nf < 4; nf++) {
                        int g = nf >> 1, o = nf & 1;
                        MMA_BF16(acc[mf][nf], af[mf], bf[g][o], bf[g][o + 2]);
                    }
                }
            }
        }
        __syncthreads();
    }

    // ---- epilogue ----
    int grp = lane >> 2, ct = lane & 3;
#pragma unroll
    for (int mf = 0; mf < 4; mf++) {
#pragma unroll
        for (int nf = 0; nf < 4; nf++) {
            int gr = mBase + wm * 64 + mf * 16 + grp;
            int gc = nBase + wn * 32 + nf * 8 + ct * 2;
#pragma unroll
            for (int e = 0; e < 4; e++) {
                int r = gr + ((e >> 1) ? 8 : 0);
                int c = gc + (e & 1);
                if (r < M && c < N) {
                    float v = alpha * acc[mf][nf][e];
                    if (bias) v += bias[c];
                    if (act) v = gelu_f(v);
                    long off = (long)r * sCm + c;
                    if (accumulate) C[off] += v; else C[off] = v;
                }
            }
        }
    }
}

// ---------------- LayerNorm, D=512, block per row ----------------
__global__ __launch_bounds__(256) void ln512(
    const float* __restrict__ in, const float* __restrict__ g,
    const float* __restrict__ b, float* __restrict__ out)
{
    long row = blockIdx.x;
    const float* x = in + row * Dd;
    float* o = out + row * Dd;
    int tid = threadIdx.x;
    float v0 = x[tid], v1 = x[tid + 256];

    __shared__ float red[256];
    red[tid] = v0 + v1;
    __syncthreads();
    for (int s = 128; s > 0; s >>= 1) { if (tid < s) red[tid] += red[tid + s]; __syncthreads(); }
    float mu = red[0] * (1.f / Dd);
    __syncthreads();
    float d0 = v0 - mu, d1 = v1 - mu;
    red[tid] = d0 * d0 + d1 * d1;
    __syncthreads();
    for (int s = 128; s > 0; s >>= 1) { if (tid < s) red[tid] += red[tid + s]; __syncthreads(); }
    float rs = rsqrtf(red[0] * (1.f / Dd) + 1e-5f);
    o[tid]       = d0 * rs * g[tid]       + b[tid];
    o[tid + 256] = d1 * rs * g[tid + 256] + b[tid + 256];
}

// ---------------- LayerNorm, D=64, warp per row, strided input ----------------
__global__ __launch_bounds__(128) void ln64(
    const float* __restrict__ in, const float* __restrict__ g,
    const float* __restrict__ b, float* __restrict__ out,
    int D1, int D2, long s0, long s1, long s2)
{
    long warp = ((long)blockIdx.x * blockDim.x + threadIdx.x) >> 5;
    int lane = threadIdx.x & 31;
    long d2 = warp % D2;
    long t  = warp / D2;
    long d1 = t % D1;
    long d0 = t / D1;
    const float* x = in + d0 * s0 + d1 * s1 + d2 * s2;
    float v0 = x[lane], v1 = x[lane + 32];
    float s = v0 + v1;
#pragma unroll
    for (int o = 16; o; o >>= 1) s += __shfl_xor_sync(0xffffffffu, s, o);
    float mu = s * (1.f / 64.f);
    float q0 = v0 - mu, q1 = v1 - mu;
    float q = q0 * q0 + q1 * q1;
#pragma unroll
    for (int o = 16; o; o >>= 1) q += __shfl_xor_sync(0xffffffffu, q, o);
    float rs = rsqrtf(q * (1.f / 64.f) + 1e-5f);
    float* o = out + warp * 64;
    o[lane]      = q0 * rs * g[lane]      + b[lane];
    o[lane + 32] = q1 * rs * g[lane + 32] + b[lane + 32];
}

// ---------------- embedding ----------------
__global__ void embed(const int* __restrict__ x, const float* __restrict__ tok,
                      const float* __restrict__ pos, float* __restrict__ h)
{
    long i = (long)blockIdx.x * blockDim.x + threadIdx.x;
    if (i >= (long)Bb * Nn * Dd) return;
    int d = i % Dd;
    long bn = i / Dd;
    int n = bn % Nn;
    int tokid = x[bn];
    h[i] = tok[(long)tokid * Dd + d] + pos[(long)n * Dd + d];
}

// ---------------- softmax over axis=2 (n) of p (BH, N, R) ----------------
__global__ __launch_bounds__(256) void softmax_col(float* __restrict__ p)
{
    int blk = blockIdx.x;
    int rb  = blk % (Rr / 64);
    int bh  = blk / (Rr / 64);
    int c   = threadIdx.x % 64;
    int stripe = threadIdx.x / 64;
    float* base = p + (long)bh * Nn * Rr + rb * 64 + c;
    const int CH = Nn / 4;
    int n0 = stripe * CH;

    float m = -1e30f, s = 0.f;
    for (int n = n0; n < n0 + CH; n++) {
        float v = base[(long)n * Rr];
        float nm = fmaxf(m, v);
        s = s * __expf(m - nm) + __expf(v - nm);
        m = nm;
    }
    __shared__ float sm[4][64], ss[4][64];
    sm[stripe][c] = m; ss[stripe][c] = s;
    __syncthreads();
    float M = -1e30f;
#pragma unroll
    for (int j = 0; j < 4; j++) M = fmaxf(M, sm[j][c]);
    float S = 0.f;
#pragma unroll
    for (int j = 0; j < 4; j++) S += ss[j][c] * __expf(sm[j][c] - M);
    float inv = 1.f / S;
    for (int n = n0; n < n0 + CH; n++) {
        long off = (long)n * Rr;
        base[off] = __expf(base[off] - M) * inv;
    }
}

// ---------------- softmax over rows of length 384 ----------------
__global__ __launch_bounds__(128) void softmax_row384(float* __restrict__ s)
{
    float* r = s + (long)blockIdx.x * (WS + Rr);
    int tid = threadIdx.x;
    float v0 = r[tid], v1 = r[tid + 128], v2 = r[tid + 256];
    __shared__ float red[128];
    red[tid] = fmaxf(v0, fmaxf(v1, v2));
    __syncthreads();
    for (int st = 64; st > 0; st >>= 1) { if (tid < st) red[tid] = fmaxf(red[tid], red[tid + st]); __syncthreads(); }
    float m = red[0];
    __syncthreads();
    float e0 = __expf(v0 - m), e1 = __expf(v1 - m), e2 = __expf(v2 - m);
    red[tid] = e0 + e1 + e2;
    __syncthreads();
    for (int st = 64; st > 0; st >>= 1) { if (tid < st) red[tid] += red[tid + st]; __syncthreads(); }
    float inv = 1.f / red[0];
    r[tid] = e0 * inv; r[tid + 128] = e1 * inv; r[tid + 256] = e2 * inv;
}

// ---------------- final head: split-K partials (deterministic) ----------------
__global__ __launch_bounds__(256) void head_partial(
    const float* __restrict__ logits, const float* __restrict__ Wfin,
    float* __restrict__ part)
{
    int b = blockIdx.y;
    long k0 = (long)blockIdx.x * 1024;
    const float* lrow = logits + (long)b * KFIN;
    float acc[Cc];
#pragma unroll
    for (int c = 0; c < Cc; c++) acc[c] = 0.f;
    for (int i = threadIdx.x; i < 1024; i += 256) {
        long k = k0 + i;
        float l = lrow[k];
        const float* w = Wfin + k * Cc;
#pragma unroll
        for (int c = 0; c < Cc; c++) acc[c] = fmaf(l, w[c], acc[c]);
    }
#pragma unroll
    for (int c = 0; c < Cc; c++)
#pragma unroll
        for (int o = 16; o; o >>= 1) acc[c] += __shfl_xor_sync(0xffffffffu, acc[c], o);
    __shared__ float sm[8][Cc];
    int warp = threadIdx.x >> 5, lane = threadIdx.x & 31;
    if (lane == 0)
#pragma unroll
        for (int c = 0; c < Cc; c++) sm[warp][c] = acc[c];
    __syncthreads();
    if (threadIdx.x < Cc) {
        float s = 0.f;
#pragma unroll
        for (int w = 0; w < 8; w++) s += sm[w][threadIdx.x];
        part[((long)b * NCHUNK + blockIdx.x) * Cc + threadIdx.x] = s;
    }
}

__global__ void head_reduce(const float* __restrict__ part,
                            const float* __restrict__ bfin, float* __restrict__ out)
{
    int t = threadIdx.x;
    if (t < Bb * Cc) {
        int b = t / Cc, c = t % Cc;
        float s = bfin[c];
        for (int j = 0; j < NCHUNK; j++) s += part[((long)b * NCHUNK + j) * Cc + c];
        out[b * Cc + c] = s;
    }
}

// ---------------- host launcher ----------------
static void launch_gemm(const float* A, const float* B, const float* bias, float* C,
                        int M, int N, int K,
                        long sAm, long sAk, long sBk, long sBn, long sCm,
                        int D0, int D1, int D2,
                        long a0, long a1, long a2,
                        long b0, long b1, long b2,
                        long c0, long c1, long c2,
                        float alpha, int accum, int act)
{
    dim3 grid((N + 127) / 128, (M + 127) / 128, D0 * D1 * D2);
    tc_gemm<<<grid, 256>>>(A, B, bias, C, M, N, K, sAm, sAk, sBk, sBn, sCm,
                           D1, D2, a0, a1, a2, b0, b1, b2, c0, c1, c2,
                           alpha, accum, act);
}

extern "C" void kernel_launch(void* const* d_in, const int* in_sizes, int n_in,
                              void* d_out, int out_size)
{
    const int*   x_in    = (const int*)  d_in[0];
    const float* tok_emb = (const float*)d_in[1];
    const float* pos_emb = (const float*)d_in[2];
    const float* ln1_g   = (const float*)d_in[3];
    const float* ln1_b   = (const float*)d_in[4];
    const float* Wq      = (const float*)d_in[5];
    const float* Wkv     = (const float*)d_in[6];
    const float* Wp      = (const float*)d_in[7];
    const float* lln_g   = (const float*)d_in[8];
    const float* lln_b   = (const float*)d_in[9];
    const float* gln_g   = (const float*)d_in[10];
    const float* gln_b   = (const float*)d_in[11];
    const float* Wo      = (const float*)d_in[12];
    const float* bo      = (const float*)d_in[13];
    const float* ln2_g   = (const float*)d_in[14];
    const float* ln2_b   = (const float*)d_in[15];
    const float* W1      = (const float*)d_in[16];
    const float* b1      = (const float*)d_in[17];
    const float* W2      = (const float*)d_in[18];
    const float* b2      = (const float*)d_in[19];
    const float* lnf_g   = (const float*)d_in[20];
    const float* lnf_b   = (const float*)d_in[21];
    const float* Wlog    = (const float*)d_in[22];
    const float* blog    = (const float*)d_in[23];
    const float* Wfin    = (const float*)d_in[24];
    const float* bfin    = (const float*)d_in[25];
    float* out = (float*)d_out;

    float *ph, *py, *pq, *pkv, *pp, *pgk, *pgv, *pgkn, *pgvn, *plk, *plv, *psim, *po, *pf1, *plog, *ppart;
    cudaGetSymbolAddress((void**)&ph,   g_h);
    cudaGetSymbolAddress((void**)&py,   g_y);
    cudaGetSymbolAddress((void**)&pq,   g_q);
    cudaGetSymbolAddress((void**)&pkv,  g_kv);
    cudaGetSymbolAddress((void**)&pp,   g_p);
    cudaGetSymbolAddress((void**)&pgk,  g_gk);
    cudaGetSymbolAddress((void**)&pgv,  g_gv);
    cudaGetSymbolAddress((void**)&pgkn, g_gkn);
    cudaGetSymbolAddress((void**)&pgvn, g_gvn);
    cudaGetSymbolAddress((void**)&plk,  g_lk);
    cudaGetSymbolAddress((void**)&plv,  g_lv);
    cudaGetSymbolAddress((void**)&psim, g_sim);
    cudaGetSymbolAddress((void**)&po,   g_o);
    cudaGetSymbolAddress((void**)&pf1,  g_f1);
    cudaGetSymbolAddress((void**)&plog, g_log);
    cudaGetSymbolAddress((void**)&ppart,g_part);

    const long BND = (long)Bb * Nn * Dd;          // 8388608
    const int  MBN = Bb * Nn;                     // 16384

    // embedding
    embed<<<(BND + 255) / 256, 256>>>(x_in, tok_emb, pos_emb, ph);

    for (int l = 0; l < Ll; l++) {
        const float* wq  = Wq  + (long)l * Dd * Hh * DH;
        const float* wkv = Wkv + (long)l * Dd * 2 * Hh * DH;
        const float* wp  = Wp  + (long)l * DH * Rr;
        const float* wo  = Wo  + (long)l * Hh * DH * Dd;
        const float* w1  = W1  + (long)l * Dd * FF;
        const float* w2  = W2  + (long)l * FF * Dd;

        // y = LN1(h)
        ln512<<<MBN, 256>>>(ph, ln1_g + l * Dd, ln1_b + l * Dd, py);

        // q = y @ Wq * SCALE
        launch_gemm(py, wq, nullptr, pq, MBN, Hh * DH, Dd,
                    Dd, 1, Hh * DH, 1, Hh * DH,
                    1, 1, 1, 0,0,0, 0,0,0, 0,0,0, SCALE, 0, 0);

        // kv = y @ Wkv
        launch_gemm(py, wkv, nullptr, pkv, MBN, 2 * Hh * DH, Dd,
                    Dd, 1, 2 * Hh * DH, 1, 2 * Hh * DH,
                    1, 1, 1, 0,0,0, 0,0,0, 0,0,0, 1.f, 0, 0);

        // p = k @ Wp   per (b,h)
        launch_gemm(pkv, wp, nullptr, pp, Nn, Rr, DH,
                    2L * Hh * DH, 1, Rr, 1, Rr,
                    Bb, Hh, 1,
                    (long)Nn * 2 * Hh * DH, DH, 0,
                    0, 0, 0,
                    (long)Hh * Nn * Rr, (long)Nn * Rr, 0,
                    1.f, 0, 0);

        // softmax over n
        softmax_col<<<Bb * Hh * (Rr / 64), 256>>>(pp);

        // gk = p^T @ k   per (b,h)
        launch_gemm(pp, pkv, nullptr, pgk, Rr, DH, Nn,
                    1, Rr, 2L * Hh * DH, 1, DH,
                    Bb, Hh, 1,
                    (long)Hh * Nn * Rr, (long)Nn * Rr, 0,
                    (long)Nn * 2 * Hh * DH, DH, 0,
                    (long)Hh * Rr * DH, (long)Rr * DH, 0,
                    1.f, 0, 0);
        // gv = p^T @ v
        launch_gemm(pp, pkv + Hh * DH, nullptr, pgv, Rr, DH, Nn,
                    1, Rr, 2L * Hh * DH, 1, DH,
                    Bb, Hh, 1,
                    (long)Hh * Nn * Rr, (long)Nn * Rr, 0,
                    (long)Nn * 2 * Hh * DH, DH, 0,
                    (long)Hh * Rr * DH, (long)Rr * DH, 0,
                    1.f, 0, 0);

        // gln on gk, gv
        ln64<<<(Bb * Hh * Rr) / 4, 128>>>(pgk, gln_g + l * DH, gln_b + l * DH, pgkn,
                                          1, Bb * Hh * Rr, 0, 0, DH);
        ln64<<<(Bb * Hh * Rr) / 4, 128>>>(pgv, gln_g + l * DH, gln_b + l * DH, pgvn,
                                          1, Bb * Hh * Rr, 0, 0, DH);

        // lk = lln(k), lv = lln(v)
        ln64<<<(Bb * Hh * Nn) / 4, 128>>>(pkv, lln_g + l * DH, lln_b + l * DH, plk,
                                          Hh, Nn, (long)Nn * 2 * Hh * DH, DH, 2L * Hh * DH);
        ln64<<<(Bb * Hh * Nn) / 4, 128>>>(pkv + Hh * DH, lln_g + l * DH, lln_b + l * DH, plv,
                                          Hh, Nn, (long)Nn * 2 * Hh * DH, DH, 2L * Hh * DH);

        // sim_l = lq @ lk^T   per (b,h,w)
        launch_gemm(pq, plk, nullptr, psim, WS, WS, DH,
                    Hh * DH, 1, 1, DH, WS + Rr,
                    Bb, Hh, NW,
                    (long)Nn * Hh * DH, DH, (long)WS * Hh * DH,
                    (long)Hh * Nn * DH, (long)Nn * DH, (long)WS * DH,
                    (long)Hh * Nn * (WS + Rr), (long)Nn * (WS + Rr), (long)WS * (WS + Rr),
                    1.f, 0, 0);

        // sim_g = lq @ gkn^T  per (b,h)
        launch_gemm(pq, pgkn, nullptr, psim + WS, Nn, Rr, DH,
                    Hh * DH, 1, 1, DH, WS + Rr,
                    Bb, Hh, 1,
                    (long)Nn * Hh * DH, DH, 0,
                    (long)Hh * Rr * DH, (long)Rr * DH, 0,
                    (long)Hh * Nn * (WS + Rr), (long)Nn * (WS + Rr), 0,
                    1.f, 0, 0);

        // softmax over 384-wide rows
        softmax_row384<<<Bb * Hh * Nn, 128>>>(psim);

        // o = a_l @ lv   per (b,h,w)
        launch_gemm(psim, plv, nullptr, po, WS, DH, WS,
                    WS + Rr, 1, DH, 1, Hh * DH,
                    Bb, Hh, NW,
                    (long)Hh * Nn * (WS + Rr), (long)Nn * (WS + Rr), (long)WS * (WS + Rr),
                    (long)Hh * Nn * DH, (long)Nn * DH, (long)WS * DH,
                    (long)Nn * Hh * DH, DH, (long)WS * Hh * DH,
                    1.f, 0, 0);

        // o += a_g @ gvn  per (b,h)
        launch_gemm(psim + WS, pgvn, nullptr, po, Nn, DH, Rr,
                    WS + Rr, 1, DH, 1, Hh * DH,
                    Bb, Hh, 1,
                    (long)Hh * Nn * (WS + Rr), (long)Nn * (WS + Rr), 0,
                    (long)Hh * Rr * DH, (long)Rr * DH, 0,
                    (long)Nn * Hh * DH, DH, 0,
                    1.f, 1, 0);

        // h += o @ Wo + bo
        launch_gemm(po, wo, bo + l * Dd, ph, MBN, Dd, Hh * DH,
                    Hh * DH, 1, Dd, 1, Dd,
                    1, 1, 1, 0,0,0, 0,0,0, 0,0,0, 1.f, 1, 0);

        // y = LN2(h)
        ln512<<<MBN, 256>>>(ph, ln2_g + l * Dd, ln2_b + l * Dd, py);

        // f1 = gelu(y @ W1 + b1)
        launch_gemm(py, w1, b1 + (long)l * FF, pf1, MBN, FF, Dd,
                    Dd, 1, FF, 1, FF,
                    1, 1, 1, 0,0,0, 0,0,0, 0,0,0, 1.f, 0, 1);

        // h += f1 @ W2 + b2
        launch_gemm(pf1, w2, b2 + l * Dd, ph, MBN, Dd, FF,
                    FF, 1, Dd, 1, Dd,
                    1, 1, 1, 0,0,0, 0,0,0, 0,0,0, 1.f, 1, 0);
    }

    // final LN + vocab projection
    ln512<<<MBN, 256>>>(ph, lnf_g, lnf_b, py);
    launch_gemm(py, Wlog, blog, plog, MBN, Vv, Dd,
                Dd, 1, Vv, 1, Vv,
                1, 1, 1, 0,0,0, 0,0,0, 0,0,0, 1.f, 0, 0);

    // head
    {
        dim3 grid(NCHUNK, Bb);
        head_partial<<<grid, 256>>>(plog, Wfin, ppart);
        head_reduce<<<1, 64>>>(ppart, bfin, out);
    }
}

// round 7
// speedup vs baseline: 2.6014x; 1.4427x over previous
#include <cuda_runtime.h>
#include <cuda_bf16.h>
#include <math.h>
#include <stdint.h>

typedef unsigned short u16;

// Problem constants
#define Bb   4
#define Nn   4096
#define Vv   512
#define Dd   512
#define Hh   8
#define DH   64
#define Ll   4
#define WS   128
#define Rr   256
#define Cc   10
#define FF   2048
#define NW   (Nn / WS)
#define SCALE 0.125f
#define KFIN ((long)Nn * Vv)
#define NCHUNK 2048

// flags
#define F_ACC   1
#define F_GELU  2
#define F_WANTC 4

// ---------------- scratch (device globals; no allocation) ----------------
__device__ float g_h   [(size_t)Bb * Nn * Dd];
__device__ float g_kv  [(size_t)Bb * Nn * 2 * Hh * DH];
__device__ float g_p   [(size_t)Bb * Hh * Nn * Rr];
__device__ float g_gkv [(size_t)2 * Bb * Hh * Rr * DH];   // gk | gv
__device__ float g_gvn [(size_t)Bb * Hh * Rr * DH];
__device__ float g_lv  [(size_t)Bb * Hh * Nn * DH];
__device__ float g_sim [(size_t)Bb * Hh * Nn * (WS + Rr)];
__device__ float g_o   [(size_t)Bb * Nn * Hh * DH];
__device__ float g_log [(size_t)Bb * Nn * Vv];
__device__ float g_part[(size_t)Bb * NCHUNK * Cc];

// bf16 hi/lo planes
__device__ u16 g_yAhi [8388608],  g_yAlo [8388608];   // 16384x512
__device__ u16 g_qAhi [8388608],  g_qAlo [8388608];   // 16384x512
__device__ u16 g_kvAhi[16777216], g_kvAlo[16777216];  // 16384x1024
__device__ u16 g_kvThi[16777216], g_kvTlo[16777216];  // 4 x 1024x4096
__device__ u16 g_pThi [33554432], g_pTlo [33554432];  // 32 x 256x4096
__device__ u16 g_lkhi [8388608],  g_lklo [8388608];   // 32 x 4096x64
__device__ u16 g_gknhi[524288],   g_gknlo[524288];    // 32 x 256x64
__device__ u16 g_lvThi[8388608],  g_lvTlo[8388608];   // 32 x 64x4096
__device__ u16 g_gvThi[524288],   g_gvTlo[524288];    // 32 x 64x256
__device__ u16 g_simhi[50331648], g_simlo[50331648];  // 131072x384
__device__ u16 g_poAhi[8388608],  g_poAlo[8388608];   // 16384x512
__device__ u16 g_f1Ahi[33554432], g_f1Alo[33554432];  // 16384x2048
__device__ u16 g_wBhi [1048576],  g_wBlo [1048576];   // max weight plane

// ---------------- helpers ----------------
__device__ __forceinline__ float gelu_f(float x) {
    const float k0 = 0.7978845608028654f, k1 = 0.044715f;
    return 0.5f * x * (1.f + tanhf(k0 * (x + k1 * x * x * x)));
}
__device__ __forceinline__ uint32_t smem_u32(const void* p) {
    uint32_t a;
    asm("{ .reg .u64 t; cvta.to.shared.u64 t, %1; cvt.u32.u64 %0, t; }" : "=r"(a) : "l"(p));
    return a;
}
__device__ __forceinline__ void split_bf16(float v, u16& hi, u16& lo) {
    __nv_bfloat16 h = __float2bfloat16_rn(v);
    float rem = v - __bfloat162float(h);
    __nv_bfloat16 l = __float2bfloat16_rn(rem);
    hi = __bfloat16_as_ushort(h);
    lo = __bfloat16_as_ushort(l);
}

#define LDMATRIX_X4(r0, r1, r2, r3, addr) \
    asm volatile("ldmatrix.sync.aligned.m8n8.x4.shared.b16 {%0,%1,%2,%3}, [%4];" \
        : "=r"(r0), "=r"(r1), "=r"(r2), "=r"(r3) : "r"(addr))

#define MMA_BF16(c, a, b0v, b1v) \
    asm volatile("mma.sync.aligned.m16n8k16.row.col.f32.bf16.bf16.f32 " \
        "{%0,%1,%2,%3}, {%4,%5,%6,%7}, {%8,%9}, {%0,%1,%2,%3};" \
        : "+f"((c)[0]), "+f"((c)[1]), "+f"((c)[2]), "+f"((c)[3]) \
        : "r"((a)[0]), "r"((a)[1]), "r"((a)[2]), "r"((a)[3]), "r"(b0v), "r"(b1v))

// ---------------- GEMM on pre-split bf16 planes ----------------
// A plane [m][k] (row stride lda), B plane [n][k] (row stride ldb).
// C[m,n] = alpha * sum_k (Ahi+Alo)[m][k] * (Bhi+Blo)[n][k]  (3-term product)
// Tile 128x128, chunk K=32. M must be multiple of 128; K multiple of 32.
#define PADK 40

__global__ __launch_bounds__(256, 2) void tc_gemm(
    const u16* __restrict__ Ahi, const u16* __restrict__ Alo,
    const u16* __restrict__ Bhi, const u16* __restrict__ Blo,
    const float* __restrict__ bias, float* __restrict__ C,
    u16* __restrict__ Chi, u16* __restrict__ Clo,
    int M, int N, int K, int lda, int ldb, long sCm,
    int D1, int D2,
    long a0, long a1, long a2,
    long b0, long b1, long b2,
    long c0, long c1, long c2,
    float alpha, int flags)
{
    __shared__ __align__(16) u16 sAhi[128 * PADK];
    __shared__ __align__(16) u16 sAlo[128 * PADK];
    __shared__ __align__(16) u16 sBhi[128 * PADK];
    __shared__ __align__(16) u16 sBlo[128 * PADK];

    int z  = blockIdx.z;
    int d2 = z % D2;
    int t  = z / D2;
    int d1 = t % D1;
    int d0 = t / D1;
    long aOff = (long)d0 * a0 + (long)d1 * a1 + (long)d2 * a2;
    long bOff = (long)d0 * b0 + (long)d1 * b1 + (long)d2 * b2;
    long cOff = (long)d0 * c0 + (long)d1 * c1 + (long)d2 * c2;

    int tid  = threadIdx.x;
    int lane = tid & 31;
    int wid  = tid >> 5;
    int wm   = wid & 1;
    int wn   = wid >> 1;
    int mBase = blockIdx.y * 128;
    int nBase = blockIdx.x * 128;

    const int nChunks = K >> 5;

    float acc[4][4][4];
#pragma unroll
    for (int i = 0; i < 4; i++)
#pragma unroll
        for (int j = 0; j < 4; j++)
#pragma unroll
            for (int e = 0; e < 4; e++) acc[i][j][e] = 0.f;

    for (int ch = 0; ch < nChunks; ch++) {
        int k0 = ch << 5;
        // A tile: 128x32, 512 uint4 vectors per plane, 2 per thread
#pragma unroll
        for (int v = 0; v < 2; v++) {
            int vec = tid + v * 256;
            int row = vec >> 2, kq = (vec & 3) << 3;
            long off = aOff + (long)(mBase + row) * lda + k0 + kq;
            uint4 dh = *(const uint4*)(Ahi + off);
            uint4 dl = *(const uint4*)(Alo + off);
            int so = row * PADK + kq;
            *(uint4*)&sAhi[so] = dh;
            *(uint4*)&sAlo[so] = dl;
        }
        // B tile (guard rows >= N)
#pragma unroll
        for (int v = 0; v < 2; v++) {
            int vec = tid + v * 256;
            int row = vec >> 2, kq = (vec & 3) << 3;
            uint4 dh = make_uint4(0,0,0,0), dl = make_uint4(0,0,0,0);
            if (nBase + row < N) {
                long off = bOff + (long)(nBase + row) * ldb + k0 + kq;
                dh = *(const uint4*)(Bhi + off);
                dl = *(const uint4*)(Blo + off);
            }
            int so = row * PADK + kq;
            *(uint4*)&sBhi[so] = dh;
            *(uint4*)&sBlo[so] = dl;
        }
        __syncthreads();

        int lrow = lane & 15;
        int lcol = (lane >> 4) * 8;
#pragma unroll
        for (int seg = 0; seg < 3; seg++) {
            const u16* sa = (seg == 1) ? sAlo : sAhi;
            const u16* sb = (seg == 2) ? sBlo : sBhi;
#pragma unroll
            for (int kk = 0; kk < 2; kk++) {
                int kc = kk * 16 + lcol;
                uint32_t af[4][4];
#pragma unroll
                for (int mf = 0; mf < 4; mf++) {
                    int row = wm * 64 + mf * 16 + lrow;
                    uint32_t addr = smem_u32(&sa[row * PADK + kc]);
                    LDMATRIX_X4(af[mf][0], af[mf][1], af[mf][2], af[mf][3], addr);
                }
                uint32_t bfr[2][4];
#pragma unroll
                for (int g = 0; g < 2; g++) {
                    int nrow = wn * 32 + g * 16 + lrow;
                    uint32_t addr = smem_u32(&sb[nrow * PADK + kc]);
                    LDMATRIX_X4(bfr[g][0], bfr[g][1], bfr[g][2], bfr[g][3], addr);
                }
#pragma unroll
                for (int mf = 0; mf < 4; mf++) {
#pragma unroll
                    for (int nf = 0; nf < 4; nf++) {
                        int g = nf >> 1, o = nf & 1;
                        MMA_BF16(acc[mf][nf], af[mf], bfr[g][o], bfr[g][o + 2]);
                    }
                }
            }
        }
        __syncthreads();
    }

    // epilogue
    int grp = lane >> 2, ct = lane & 3;
#pragma unroll
    for (int mf = 0; mf < 4; mf++) {
#pragma unroll
        for (int nf = 0; nf < 4; nf++) {
            int gr = mBase + wm * 64 + mf * 16 + grp;
            int gc = nBase + wn * 32 + nf * 8 + ct * 2;
#pragma unroll
            for (int e = 0; e < 4; e++) {
                int r = gr + ((e >> 1) ? 8 : 0);
                int c = gc + (e & 1);
                if (c < N) {
                    float v = alpha * acc[mf][nf][e];
                    if (bias) v += bias[c];
                    if (flags & F_GELU) v = gelu_f(v);
                    long off = cOff + (long)r * sCm + c;
                    if (flags & F_ACC) v += C[off];
                    if (flags & F_WANTC) C[off] = v;
                    if (Chi) {
                        u16 hh, ll;
                        split_bf16(v, hh, ll);
                        Chi[off] = hh; Clo[off] = ll;
                    }
                }
            }
        }
    }
}

// ---------------- split-transpose: out[n][k] = in[k][n] ----------------
// in: [inRows][inCols] contiguous per batch; out plane [inCols][inRows]
__global__ __launch_bounds__(256) void split_t(
    const float* __restrict__ in, u16* __restrict__ hi, u16* __restrict__ lo,
    int inRows, int inCols, long inBatch, long outBatch)
{
    __shared__ float tbuf[32][33];
    int z = blockIdx.z;
    const float* src = in + (long)z * inBatch;
    int kb = blockIdx.x * 32;
    int nb = blockIdx.y * 32;
    int tx = threadIdx.x & 31, ty = threadIdx.x >> 5;  // 32 x 8
#pragma unroll
    for (int j = 0; j < 4; j++) {
        int r = ty + j * 8;
        tbuf[r][tx] = src[(long)(kb + r) * inCols + nb + tx];
    }
    __syncthreads();
    u16* h = hi + (long)z * outBatch;
    u16* l = lo + (long)z * outBatch;
#pragma unroll
    for (int j = 0; j < 4; j++) {
        int r = ty + j * 8;
        float v = tbuf[tx][r];
        u16 hh, ll;
        split_bf16(v, hh, ll);
        long o = (long)(nb + r) * inRows + kb + tx;
        h[o] = hh; l[o] = ll;
    }
}

// ---------------- LayerNorm D=512 -> planes ----------------
__global__ __launch_bounds__(256) void ln512p(
    const float* __restrict__ in, const float* __restrict__ g,
    const float* __restrict__ b, u16* __restrict__ oHi, u16* __restrict__ oLo)
{
    long row = blockIdx.x;
    const float* x = in + row * Dd;
    int tid = threadIdx.x;
    float v0 = x[tid], v1 = x[tid + 256];
    __shared__ float red[256];
    red[tid] = v0 + v1;
    __syncthreads();
    for (int s = 128; s > 0; s >>= 1) { if (tid < s) red[tid] += red[tid + s]; __syncthreads(); }
    float mu = red[0] * (1.f / Dd);
    __syncthreads();
    float d0 = v0 - mu, d1 = v1 - mu;
    red[tid] = d0 * d0 + d1 * d1;
    __syncthreads();
    for (int s = 128; s > 0; s >>= 1) { if (tid < s) red[tid] += red[tid + s]; __syncthreads(); }
    float rs = rsqrtf(red[0] * (1.f / Dd) + 1e-5f);
    float r0 = d0 * rs * g[tid] + b[tid];
    float r1 = d1 * rs * g[tid + 256] + b[tid + 256];
    u16 h0, l0, h1, l1;
    split_bf16(r0, h0, l0);
    split_bf16(r1, h1, l1);
    long o = row * Dd;
    oHi[o + tid] = h0;       oLo[o + tid] = l0;
    oHi[o + tid + 256] = h1; oLo[o + tid + 256] = l1;
}

// ---------------- LayerNorm D=64, warp/row; float and/or plane out ----------------
__global__ __launch_bounds__(128) void ln64(
    const float* __restrict__ in, const float* __restrict__ g,
    const float* __restrict__ b, float* __restrict__ outF,
    u16* __restrict__ oHi, u16* __restrict__ oLo,
    int D1, int D2, long s0, long s1, long s2)
{
    long warp = ((long)blockIdx.x * blockDim.x + threadIdx.x) >> 5;
    int lane = threadIdx.x & 31;
    long d2 = warp % D2;
    long t  = warp / D2;
    long d1 = t % D1;
    long d0 = t / D1;
    const float* x = in + d0 * s0 + d1 * s1 + d2 * s2;
    float v0 = x[lane], v1 = x[lane + 32];
    float s = v0 + v1;
#pragma unroll
    for (int o = 16; o; o >>= 1) s += __shfl_xor_sync(0xffffffffu, s, o);
    float mu = s * (1.f / 64.f);
    float q0 = v0 - mu, q1 = v1 - mu;
    float q = q0 * q0 + q1 * q1;
#pragma unroll
    for (int o = 16; o; o >>= 1) q += __shfl_xor_sync(0xffffffffu, q, o);
    float rs = rsqrtf(q * (1.f / 64.f) + 1e-5f);
    float r0 = q0 * rs * g[lane] + b[lane];
    float r1 = q1 * rs * g[lane + 32] + b[lane + 32];
    long o = warp * 64;
    if (outF) { outF[o + lane] = r0; outF[o + lane + 32] = r1; }
    if (oHi) {
        u16 h0, l0, h1, l1;
        split_bf16(r0, h0, l0);
        split_bf16(r1, h1, l1);
        oHi[o + lane] = h0;      oLo[o + lane] = l0;
        oHi[o + lane + 32] = h1; oLo[o + lane + 32] = l1;
    }
}

// ---------------- embedding ----------------
__global__ void embed(const int* __restrict__ x, const float* __restrict__ tok,
                      const float* __restrict__ pos, float* __restrict__ h)
{
    long i = (long)blockIdx.x * blockDim.x + threadIdx.x;
    if (i >= (long)Bb * Nn * Dd) return;
    int d = i % Dd;
    long bn = i / Dd;
    int n = bn % Nn;
    int tokid = x[bn];
    h[i] = tok[(long)tokid * Dd + d] + pos[(long)n * Dd + d];
}

// ---------------- softmax over axis=2 (n) of p (BH, N, R), in-place float ----------------
__global__ __launch_bounds__(256) void softmax_col(float* __restrict__ p)
{
    int blk = blockIdx.x;
    int rb  = blk % (Rr / 64);
    int bh  = blk / (Rr / 64);
    int c   = threadIdx.x % 64;
    int stripe = threadIdx.x / 64;
    float* base = p + (long)bh * Nn * Rr + rb * 64 + c;
    const int CH = Nn / 4;
    int n0 = stripe * CH;

    float m = -1e30f, s = 0.f;
    for (int n = n0; n < n0 + CH; n++) {
        float v = base[(long)n * Rr];
        float nm = fmaxf(m, v);
        s = s * __expf(m - nm) + __expf(v - nm);
        m = nm;
    }
    __shared__ float sm[4][64], ss[4][64];
    sm[stripe][c] = m; ss[stripe][c] = s;
    __syncthreads();
    float M = -1e30f;
#pragma unroll
    for (int j = 0; j < 4; j++) M = fmaxf(M, sm[j][c]);
    float S = 0.f;
#pragma unroll
    for (int j = 0; j < 4; j++) S += ss[j][c] * __expf(sm[j][c] - M);
    float inv = 1.f / S;
    for (int n = n0; n < n0 + CH; n++) {
        long off = (long)n * Rr;
        base[off] = __expf(base[off] - M) * inv;
    }
}

// ---------------- softmax over 384-wide rows -> planes ----------------
__global__ __launch_bounds__(128) void softmax_row384(
    const float* __restrict__ s, u16* __restrict__ oHi, u16* __restrict__ oLo)
{
    const float* r = s + (long)blockIdx.x * (WS + Rr);
    int tid = threadIdx.x;
    float v0 = r[tid], v1 = r[tid + 128], v2 = r[tid + 256];
    __shared__ float red[128];
    red[tid] = fmaxf(v0, fmaxf(v1, v2));
    __syncthreads();
    for (int st = 64; st > 0; st >>= 1) { if (tid < st) red[tid] = fmaxf(red[tid], red[tid + st]); __syncthreads(); }
    float m = red[0];
    __syncthreads();
    float e0 = __expf(v0 - m), e1 = __expf(v1 - m), e2 = __expf(v2 - m);
    red[tid] = e0 + e1 + e2;
    __syncthreads();
    for (int st = 64; st > 0; st >>= 1) { if (tid < st) red[tid] += red[tid + st]; __syncthreads(); }
    float inv = 1.f / red[0];
    long o = (long)blockIdx.x * (WS + Rr);
    u16 h, l;
    split_bf16(e0 * inv, h, l); oHi[o + tid] = h;       oLo[o + tid] = l;
    split_bf16(e1 * inv, h, l); oHi[o + tid + 128] = h; oLo[o + tid + 128] = l;
    split_bf16(e2 * inv, h, l); oHi[o + tid + 256] = h; oLo[o + tid + 256] = l;
}

// ---------------- final head ----------------
__global__ __launch_bounds__(256) void head_partial(
    const float* __restrict__ logits, const float* __restrict__ Wfin,
    float* __restrict__ part)
{
    int b = blockIdx.y;
    long k0 = (long)blockIdx.x * 1024;
    const float* lrow = logits + (long)b * KFIN;
    float acc[Cc];
#pragma unroll
    for (int c = 0; c < Cc; c++) acc[c] = 0.f;
    for (int i = threadIdx.x; i < 1024; i += 256) {
        long k = k0 + i;
        float l = lrow[k];
        const float* w = Wfin + k * Cc;
#pragma unroll
        for (int c = 0; c < Cc; c++) acc[c] = fmaf(l, w[c], acc[c]);
    }
#pragma unroll
    for (int c = 0; c < Cc; c++)
#pragma unroll
        for (int o = 16; o; o >>= 1) acc[c] += __shfl_xor_sync(0xffffffffu, acc[c], o);
    __shared__ float sm[8][Cc];
    int warp = threadIdx.x >> 5, lane = threadIdx.x & 31;
    if (lane == 0)
#pragma unroll
        for (int c = 0; c < Cc; c++) sm[warp][c] = acc[c];
    __syncthreads();
    if (threadIdx.x < Cc) {
        float s = 0.f;
#pragma unroll
        for (int w = 0; w < 8; w++) s += sm[w][threadIdx.x];
        part[((long)b * NCHUNK + blockIdx.x) * Cc + threadIdx.x] = s;
    }
}

__global__ void head_reduce(const float* __restrict__ part,
                            const float* __restrict__ bfin, float* __restrict__ out)
{
    int t = threadIdx.x;
    if (t < Bb * Cc) {
        int b = t / Cc, c = t % Cc;
        float s = bfin[c];
        for (int j = 0; j < NCHUNK; j++) s += part[((long)b * NCHUNK + j) * Cc + c];
        out[b * Cc + c] = s;
    }
}

// ---------------- host ----------------
static void gemm(const u16* Ahi, const u16* Alo, int lda,
                 const u16* Bhi, const u16* Blo, int ldb,
                 const float* bias, float* C, u16* Chi, u16* Clo, long sCm,
                 int M, int N, int K,
                 int D0, int D1, int D2,
                 long a0, long a1, long a2,
                 long b0, long b1, long b2,
                 long c0, long c1, long c2,
                 float alpha, int flags)
{
    dim3 grid((N + 127) / 128, M / 128, D0 * D1 * D2);
    tc_gemm<<<grid, 256>>>(Ahi, Alo, Bhi, Blo, bias, C, Chi, Clo,
                           M, N, K, lda, ldb, sCm, D1, D2,
                           a0, a1, a2, b0, b1, b2, c0, c1, c2, alpha, flags);
}

#define SYM(p, s) cudaGetSymbolAddress((void**)&p, s)

extern "C" void kernel_launch(void* const* d_in, const int* in_sizes, int n_in,
                              void* d_out, int out_size)
{
    const int*   x_in    = (const int*)  d_in[0];
    const float* tok_emb = (const float*)d_in[1];
    const float* pos_emb = (const float*)d_in[2];
    const float* ln1_g   = (const float*)d_in[3];
    const float* ln1_b   = (const float*)d_in[4];
    const float* Wq      = (const float*)d_in[5];
    const float* Wkv     = (const float*)d_in[6];
    const float* Wp      = (const float*)d_in[7];
    const float* lln_g   = (const float*)d_in[8];
    const float* lln_b   = (const float*)d_in[9];
    const float* gln_g   = (const float*)d_in[10];
    const float* gln_b   = (const float*)d_in[11];
    const float* Wo      = (const float*)d_in[12];
    const float* bo      = (const float*)d_in[13];
    const float* ln2_g   = (const float*)d_in[14];
    const float* ln2_b   = (const float*)d_in[15];
    const float* W1      = (const float*)d_in[16];
    const float* b1      = (const float*)d_in[17];
    const float* W2      = (const float*)d_in[18];
    const float* b2      = (const float*)d_in[19];
    const float* lnf_g   = (const float*)d_in[20];
    const float* lnf_b   = (const float*)d_in[21];
    const float* Wlog    = (const float*)d_in[22];
    const float* blog    = (const float*)d_in[23];
    const float* Wfin    = (const float*)d_in[24];
    const float* bfin    = (const float*)d_in[25];
    float* out = (float*)d_out;

    float *ph, *pkv, *pp, *pgkv, *pgvn, *plv, *psim, *po, *plog, *ppart;
    SYM(ph, g_h); SYM(pkv, g_kv); SYM(pp, g_p); SYM(pgkv, g_gkv);
    SYM(pgvn, g_gvn); SYM(plv, g_lv); SYM(psim, g_sim); SYM(po, g_o);
    SYM(plog, g_log); SYM(ppart, g_part);

    u16 *yAh,*yAl,*qAh,*qAl,*kvAh,*kvAl,*kvTh,*kvTl,*pTh,*pTl,*lkh,*lkl,
        *gknh,*gknl,*lvTh,*lvTl,*gvTh,*gvTl,*simh,*siml,*poAh,*poAl,
        *f1h,*f1l,*wBh,*wBl;
    SYM(yAh, g_yAhi);  SYM(yAl, g_yAlo);
    SYM(qAh, g_qAhi);  SYM(qAl, g_qAlo);
    SYM(kvAh, g_kvAhi); SYM(kvAl, g_kvAlo);
    SYM(kvTh, g_kvThi); SYM(kvTl, g_kvTlo);
    SYM(pTh, g_pThi);  SYM(pTl, g_pTlo);
    SYM(lkh, g_lkhi);  SYM(lkl, g_lklo);
    SYM(gknh, g_gknhi); SYM(gknl, g_gknlo);
    SYM(lvTh, g_lvThi); SYM(lvTl, g_lvTlo);
    SYM(gvTh, g_gvThi); SYM(gvTl, g_gvTlo);
    SYM(simh, g_simhi); SYM(siml, g_simlo);
    SYM(poAh, g_poAhi); SYM(poAl, g_poAlo);
    SYM(f1h, g_f1Ahi); SYM(f1l, g_f1Alo);
    SYM(wBh, g_wBhi);  SYM(wBl, g_wBlo);

    const long BND = (long)Bb * Nn * Dd;
    const int  MBN = Bb * Nn;
    const long GKV = (long)Bb * Hh * Rr * DH;   // 524288

    embed<<<(BND + 255) / 256, 256>>>(x_in, tok_emb, pos_emb, ph);

    for (int l = 0; l < Ll; l++) {
        const float* wq  = Wq  + (long)l * Dd * Hh * DH;
        const float* wkv = Wkv + (long)l * Dd * 2 * Hh * DH;
        const float* wp  = Wp  + (long)l * DH * Rr;
        const float* wo  = Wo  + (long)l * Hh * DH * Dd;
        const float* w1  = W1  + (long)l * Dd * FF;
        const float* w2  = W2  + (long)l * FF * Dd;

        // y = LN1(h) -> planes
        ln512p<<<MBN, 256>>>(ph, ln1_g + l * Dd, ln1_b + l * Dd, yAh, yAl);

        // q = y @ Wq * SCALE -> qA planes
        split_t<<<dim3(16, 16, 1), 256>>>(wq, wBh, wBl, 512, 512, 0, 0);
        gemm(yAh, yAl, 512, wBh, wBl, 512, nullptr, nullptr, qAh, qAl, 512,
             MBN, 512, 512, 1, 1, 1, 0,0,0, 0,0,0, 0,0,0, SCALE, 0);

        // kv = y @ Wkv -> float + kvA planes
        split_t<<<dim3(16, 32, 1), 256>>>(wkv, wBh, wBl, 512, 1024, 0, 0);
        gemm(yAh, yAl, 512, wBh, wBl, 512, nullptr, pkv, kvAh, kvAl, 1024,
             MBN, 1024, 512, 1, 1, 1, 0,0,0, 0,0,0, 0,0,0, 1.f, F_WANTC);

        // p = k @ Wp per (b,h) -> float
        split_t<<<dim3(2, 8, 1), 256>>>(wp, wBh, wBl, 64, 256, 0, 0);
        gemm(kvAh, kvAl, 1024, wBh, wBl, 64, nullptr, pp, nullptr, nullptr, Rr,
             Nn, Rr, DH, Bb, Hh, 1,
             (long)Nn * 1024, 64, 0,
             0, 0, 0,
             (long)Hh * Nn * Rr, (long)Nn * Rr, 0,
             1.f, F_WANTC);

        softmax_col<<<Bb * Hh * (Rr / 64), 256>>>(pp);

        // pT planes (32 batches of [4096][256] -> [256][4096])
        split_t<<<dim3(128, 8, 32), 256>>>(pp, pTh, pTl, Nn, Rr, (long)Nn * Rr, (long)Nn * Rr);
        // kvT planes (4 batches of [4096][1024] -> [1024][4096])
        split_t<<<dim3(128, 32, 4), 256>>>(pkv, kvTh, kvTl, Nn, 1024, (long)Nn * 1024, (long)Nn * 1024);

        // gk|gv = p^T @ {k,v} per (b,h,kv) -> g_gkv float
        gemm(pTh, pTl, Nn, kvTh, kvTl, Nn, nullptr, pgkv, nullptr, nullptr, DH,
             Rr, DH, Nn, Bb, Hh, 2,
             (long)Hh * Rr * Nn, (long)Rr * Nn, 0,
             (long)1024 * Nn, (long)64 * Nn, (long)512 * Nn,
             (long)Hh * Rr * DH, (long)Rr * DH, GKV,
             1.f, F_WANTC);

        // gkn planes; gvn float -> transpose planes
        ln64<<<(Bb * Hh * Rr) / 4, 128>>>(pgkv, gln_g + l * DH, gln_b + l * DH,
                                          nullptr, gknh, gknl, 1, Bb * Hh * Rr, 0, 0, DH);
        ln64<<<(Bb * Hh * Rr) / 4, 128>>>(pgkv + GKV, gln_g + l * DH, gln_b + l * DH,
                                          pgvn, nullptr, nullptr, 1, Bb * Hh * Rr, 0, 0, DH);
        split_t<<<dim3(8, 2, 32), 256>>>(pgvn, gvTh, gvTl, Rr, DH, (long)Rr * DH, (long)Rr * DH);

        // lk planes; lv float -> transpose planes
        ln64<<<(Bb * Hh * Nn) / 4, 128>>>(pkv, lln_g + l * DH, lln_b + l * DH,
                                          nullptr, lkh, lkl,
                                          Hh, Nn, (long)Nn * 1024, DH, 1024);
        ln64<<<(Bb * Hh * Nn) / 4, 128>>>(pkv + Hh * DH, lln_g + l * DH, lln_b + l * DH,
                                          plv, nullptr, nullptr,
                                          Hh, Nn, (long)Nn * 1024, DH, 1024);
        split_t<<<dim3(128, 2, 32), 256>>>(plv, lvTh, lvTl, Nn, DH, (long)Nn * DH, (long)Nn * DH);

        // sim_l per (b,h,w) -> g_sim[:, :128]
        gemm(qAh, qAl, 512, lkh, lkl, 64, nullptr, psim, nullptr, nullptr, WS + Rr,
             WS, WS, DH, Bb, Hh, NW,
             (long)Nn * 512, 64, (long)WS * 512,
             (long)Hh * Nn * 64, (long)Nn * 64, (long)WS * 64,
             (long)Hh * Nn * (WS + Rr), (long)Nn * (WS + Rr), (long)WS * (WS + Rr),
             1.f, F_WANTC);

        // sim_g per (b,h) -> g_sim[:, 128:]
        gemm(qAh, qAl, 512, gknh, gknl, 64, nullptr, psim + WS, nullptr, nullptr, WS + Rr,
             Nn, Rr, DH, Bb, Hh, 1,
             (long)Nn * 512, 64, 0,
             (long)Hh * Rr * 64, (long)Rr * 64, 0,
             (long)Hh * Nn * (WS + Rr), (long)Nn * (WS + Rr), 0,
             1.f, F_WANTC);

        // softmax -> simA planes
        softmax_row384<<<Bb * Hh * Nn, 128>>>(psim, simh, siml);

        // o = a_l @ lv per (b,h,w) -> g_o float
        gemm(simh, siml, WS + Rr, lvTh, lvTl, Nn, nullptr, po, nullptr, nullptr, 512,
             WS, DH, WS, Bb, Hh, NW,
             (long)Hh * Nn * (WS + Rr), (long)Nn * (WS + Rr), (long)WS * (WS + Rr),
             (long)Hh * DH * Nn, (long)DH * Nn, WS,
             (long)Nn * 512, 64, (long)WS * 512,
             1.f, F_WANTC);

        // o += a_g @ gvn per (b,h) -> poA planes (accumulated from g_o)
        gemm(simh + WS, siml + WS, WS + Rr, gvTh, gvTl, Rr, nullptr, po, poAh, poAl, 512,
             Nn, DH, Rr, Bb, Hh, 1,
             (long)Hh * Nn * (WS + Rr), (long)Nn * (WS + Rr), 0,
             (long)Hh * DH * Rr, (long)DH * Rr, 0,
             (long)Nn * 512, 64, 0,
             1.f, F_ACC);

        // h += o @ Wo + bo
        split_t<<<dim3(16, 16, 1), 256>>>(wo, wBh, wBl, 512, 512, 0, 0);
        gemm(poAh, poAl, 512, wBh, wBl, 512, bo + l * Dd, ph, nullptr, nullptr, 512,
             MBN, 512, 512, 1, 1, 1, 0,0,0, 0,0,0, 0,0,0, 1.f, F_ACC | F_WANTC);

        // y = LN2(h) -> planes
        ln512p<<<MBN, 256>>>(ph, ln2_g + l * Dd, ln2_b + l * Dd, yAh, yAl);

        // f1 = gelu(y @ W1 + b1) -> f1A planes
        split_t<<<dim3(16, 64, 1), 256>>>(w1, wBh, wBl, 512, 2048, 0, 0);
        gemm(yAh, yAl, 512, wBh, wBl, 512, b1 + (long)l * FF, nullptr, f1h, f1l, 2048,
             MBN, 2048, 512, 1, 1, 1, 0,0,0, 0,0,0, 0,0,0, 1.f, F_GELU);

        // h += f1 @ W2 + b2
        split_t<<<dim3(64, 16, 1), 256>>>(w2, wBh, wBl, 2048, 512, 0, 0);
        gemm(f1h, f1l, 2048, wBh, wBl, 2048, b2 + l * Dd, ph, nullptr, nullptr, 512,
             MBN, 512, 2048, 1, 1, 1, 0,0,0, 0,0,0, 0,0,0, 1.f, F_ACC | F_WANTC);
    }

    // final LN + vocab projection
    ln512p<<<MBN, 256>>>(ph, lnf_g, lnf_b, yAh, yAl);
    split_t<<<dim3(16, 16, 1), 256>>>(Wlog, wBh, wBl, 512, 512, 0, 0);
    gemm(yAh, yAl, 512, wBh, wBl, 512, blog, plog, nullptr, nullptr, 512,
         MBN, 512, 512, 1, 1, 1, 0,0,0, 0,0,0, 0,0,0, 1.f, F_WANTC);

    // head
    {
        dim3 grid(NCHUNK, Bb);
        head_partial<<<grid, 256>>>(plog, Wfin, ppart);
        head_reduce<<<1, 64>>>(ppart, bfin, out);
    }
}

// round 9
// speedup vs baseline: 3.1487x; 1.2104x over previous
#include <cuda_runtime.h>
#include <cuda_bf16.h>
#include <math.h>
#include <stdint.h>

typedef unsigned short u16;

// Problem constants
#define Bb   4
#define Nn   4096
#define Vv   512
#define Dd   512
#define Hh   8
#define DH   64
#define Ll   4
#define WS   128
#define Rr   256
#define Cc   10
#define FF   2048
#define NW   (Nn / WS)
#define SCALE 0.125f
#define KFIN ((long)Nn * Vv)
#define NCHUNK 2048

// flags
#define F_ACC   1
#define F_GELU  2
#define F_WANTC 4

// ---------------- scratch (device globals; no allocation) ----------------
__device__ float g_h   [(size_t)Bb * Nn * Dd];
__device__ float g_kv  [(size_t)Bb * Nn * 2 * Hh * DH];
__device__ float g_p   [(size_t)Bb * Hh * Nn * Rr];
__device__ float g_gkv [(size_t)2 * Bb * Hh * Rr * DH];   // gk | gv
__device__ float g_gvn [(size_t)Bb * Hh * Rr * DH];
__device__ float g_lv  [(size_t)Bb * Hh * Nn * DH];
__device__ float g_sim [(size_t)Bb * Hh * Nn * (WS + Rr)];
__device__ float g_o   [(size_t)Bb * Nn * Hh * DH];
__device__ float g_log [(size_t)Bb * Nn * Vv];
__device__ float g_part[(size_t)Bb * NCHUNK * Cc];

// bf16 hi/lo planes
__device__ u16 g_yAhi [8388608],  g_yAlo [8388608];   // 16384x512
__device__ u16 g_qAhi [8388608],  g_qAlo [8388608];   // 16384x512
__device__ u16 g_kvAhi[16777216], g_kvAlo[16777216];  // 16384x1024
__device__ u16 g_kvThi[16777216], g_kvTlo[16777216];  // 4 x 1024x4096
__device__ u16 g_pThi [33554432], g_pTlo [33554432];  // 32 x 256x4096
__device__ u16 g_lkhi [8388608],  g_lklo [8388608];   // 32 x 4096x64
__device__ u16 g_gknhi[524288],   g_gknlo[524288];    // 32 x 256x64
__device__ u16 g_lvThi[8388608],  g_lvTlo[8388608];   // 32 x 64x4096
__device__ u16 g_gvThi[524288],   g_gvTlo[524288];    // 32 x 64x256
__device__ u16 g_simhi[50331648], g_simlo[50331648];  // 131072x384
__device__ u16 g_poAhi[8388608],  g_poAlo[8388608];   // 16384x512
__device__ u16 g_f1Ahi[33554432], g_f1Alo[33554432];  // 16384x2048
__device__ u16 g_wBhi [1048576],  g_wBlo [1048576];   // max weight plane

// ---------------- helpers ----------------
__device__ __forceinline__ float gelu_f(float x) {
    const float k0 = 0.7978845608028654f, k1 = 0.044715f;
    return 0.5f * x * (1.f + tanhf(k0 * (x + k1 * x * x * x)));
}
__device__ __forceinline__ uint32_t smem_u32(const void* p) {
    uint32_t a;
    asm("{ .reg .u64 t; cvta.to.shared.u64 t, %1; cvt.u32.u64 %0, t; }" : "=r"(a) : "l"(p));
    return a;
}
__device__ __forceinline__ void split_bf16(float v, u16& hi, u16& lo) {
    __nv_bfloat16 h = __float2bfloat16_rn(v);
    float rem = v - __bfloat162float(h);
    __nv_bfloat16 l = __float2bfloat16_rn(rem);
    hi = __bfloat16_as_ushort(h);
    lo = __bfloat16_as_ushort(l);
}

#define LDMATRIX_X4(r0, r1, r2, r3, addr) \
    asm volatile("ldmatrix.sync.aligned.m8n8.x4.shared.b16 {%0,%1,%2,%3}, [%4];" \
        : "=r"(r0), "=r"(r1), "=r"(r2), "=r"(r3) : "r"(addr))

#define MMA_BF16(c, a, b0v, b1v) \
    asm volatile("mma.sync.aligned.m16n8k16.row.col.f32.bf16.bf16.f32 " \
        "{%0,%1,%2,%3}, {%4,%5,%6,%7}, {%8,%9}, {%0,%1,%2,%3};" \
        : "+f"((c)[0]), "+f"((c)[1]), "+f"((c)[2]), "+f"((c)[3]) \
        : "r"((a)[0]), "r"((a)[1]), "r"((a)[2]), "r"((a)[3]), "r"(b0v), "r"(b1v))

#define CP16(dst, src, sz) \
    asm volatile("cp.async.cg.shared.global [%0], [%1], 16, %2;" \
        :: "r"(dst), "l"(src), "r"(sz))
#define CP_COMMIT() asm volatile("cp.async.commit_group;")
#define CP_WAIT(n)  asm volatile("cp.async.wait_group %0;" :: "n"(n))

// ---------------- GEMM on pre-split bf16 planes ----------------
// A plane [m][k] (row stride lda), B plane [n][k] (row stride ldb).
// C = alpha*(Ahi+Alo)(Bhi+Blo)^T (3-term). M mult of 128, K mult of 32.
#define PADK 40
#define PLANE_B 10240           // 128*PADK*2
#define BUF_B   (4 * PLANE_B)   // 40960
#define TC_SMEM (2 * BUF_B)     // 81920

__device__ __forceinline__ void load_tiles(
    uint32_t cbase,
    const u16* __restrict__ Ahi, const u16* __restrict__ Alo,
    const u16* __restrict__ Bhi, const u16* __restrict__ Blo,
    long aOff, long bOff, int lda, int ldb,
    int mBase, int nBase, int N, int k0, int tid)
{
#pragma unroll
    for (int v = 0; v < 2; v++) {
        int vec = tid + v * 256;
        int row = vec >> 2, kq = (vec & 3) << 3;
        uint32_t d = cbase + (uint32_t)(row * PADK + kq) * 2;
        long offA = aOff + (long)(mBase + row) * lda + k0 + kq;
        CP16(d,               Ahi + offA, 16);
        CP16(d + PLANE_B,     Alo + offA, 16);
        int ok   = (nBase + row < N) ? 16 : 0;
        int brow = (nBase + row < N) ? row : 0;
        long offB = bOff + (long)(nBase + brow) * ldb + k0 + kq;
        CP16(d + 2 * PLANE_B, Bhi + offB, ok);
        CP16(d + 3 * PLANE_B, Blo + offB, ok);
    }
}

__global__ __launch_bounds__(256, 2) void tc_gemm(
    const u16* __restrict__ Ahi, const u16* __restrict__ Alo,
    const u16* __restrict__ Bhi, const u16* __restrict__ Blo,
    const float* __restrict__ bias, float* __restrict__ C,
    u16* __restrict__ Chi, u16* __restrict__ Clo,
    int M, int N, int K, int lda, int ldb, long sCm,
    int D1, int D2,
    long a0, long a1, long a2,
    long b0, long b1, long b2,
    long c0, long c1, long c2,
    float alpha, int flags)
{
    extern __shared__ __align__(16) char smem[];
    uint32_t sb = smem_u32(smem);

    int z  = blockIdx.z;
    int d2 = z % D2;
    int t  = z / D2;
    int d1 = t % D1;
    int d0 = t / D1;
    long aOff = (long)d0 * a0 + (long)d1 * a1 + (long)d2 * a2;
    long bOff = (long)d0 * b0 + (long)d1 * b1 + (long)d2 * b2;
    long cOff = (long)d0 * c0 + (long)d1 * c1 + (long)d2 * c2;

    int tid  = threadIdx.x;
    int lane = tid & 31;
    int wid  = tid >> 5;
    int wm   = wid & 1;
    int wn   = wid >> 1;
    int mBase = blockIdx.y * 128;
    int nBase = blockIdx.x * 128;

    const int nChunks = K >> 5;

    float acc[4][4][4];
#pragma unroll
    for (int i = 0; i < 4; i++)
#pragma unroll
        for (int j = 0; j < 4; j++)
#pragma unroll
            for (int e = 0; e < 4; e++) acc[i][j][e] = 0.f;

    // prologue: chunk 0 -> buf 0
    load_tiles(sb, Ahi, Alo, Bhi, Blo, aOff, bOff, lda, ldb, mBase, nBase, N, 0, tid);
    CP_COMMIT();

    int lrow = lane & 15;
    int lcol = (lane >> 4) * 8;

    for (int ch = 0; ch < nChunks; ch++) {
        if (ch + 1 < nChunks) {
            load_tiles(sb + ((ch + 1) & 1) * BUF_B, Ahi, Alo, Bhi, Blo,
                       aOff, bOff, lda, ldb, mBase, nBase, N, (ch + 1) << 5, tid);
            CP_COMMIT();
            CP_WAIT(1);
        } else {
            CP_WAIT(0);
        }
        __syncthreads();

        uint32_t cbase = sb + (ch & 1) * BUF_B;
#pragma unroll
        for (int kk = 0; kk < 2; kk++) {
            int kc = kk * 16 + lcol;
            uint32_t afh[4][4], afl[4][4], bh[2][4], bl[2][4];
#pragma unroll
            for (int mf = 0; mf < 4; mf++) {
                uint32_t ao = cbase + (uint32_t)((wm * 64 + mf * 16 + lrow) * PADK + kc) * 2;
                LDMATRIX_X4(afh[mf][0], afh[mf][1], afh[mf][2], afh[mf][3], ao);
                LDMATRIX_X4(afl[mf][0], afl[mf][1], afl[mf][2], afl[mf][3], ao + PLANE_B);
            }
#pragma unroll
            for (int g = 0; g < 2; g++) {
                uint32_t bo = cbase + 2 * PLANE_B
                            + (uint32_t)((wn * 32 + g * 16 + lrow) * PADK + kc) * 2;
                LDMATRIX_X4(bh[g][0], bh[g][1], bh[g][2], bh[g][3], bo);
            }
            // seg0: Ahi x Bhi, seg1: Alo x Bhi
#pragma unroll
            for (int mf = 0; mf < 4; mf++)
#pragma unroll
                for (int nf = 0; nf < 4; nf++) {
                    int g = nf >> 1, o = nf & 1;
                    MMA_BF16(acc[mf][nf], afh[mf], bh[g][o], bh[g][o + 2]);
                }
#pragma unroll
            for (int mf = 0; mf < 4; mf++)
#pragma unroll
                for (int nf = 0; nf < 4; nf++) {
                    int g = nf >> 1, o = nf & 1;
                    MMA_BF16(acc[mf][nf], afl[mf], bh[g][o], bh[g][o + 2]);
                }
            // seg2: Ahi x Blo
#pragma unroll
            for (int g = 0; g < 2; g++) {
                uint32_t bo = cbase + 3 * PLANE_B
                            + (uint32_t)((wn * 32 + g * 16 + lrow) * PADK + kc) * 2;
                LDMATRIX_X4(bl[g][0], bl[g][1], bl[g][2], bl[g][3], bo);
            }
#pragma unroll
            for (int mf = 0; mf < 4; mf++)
#pragma unroll
                for (int nf = 0; nf < 4; nf++) {
                    int g = nf >> 1, o = nf & 1;
                    MMA_BF16(acc[mf][nf], afh[mf], bl[g][o], bl[g][o + 2]);
                }
        }
        __syncthreads();
    }

    // epilogue
    int grp = lane >> 2, ct = lane & 3;
#pragma unroll
    for (int mf = 0; mf < 4; mf++) {
#pragma unroll
        for (int nf = 0; nf < 4; nf++) {
            int gr = mBase + wm * 64 + mf * 16 + grp;
            int gc = nBase + wn * 32 + nf * 8 + ct * 2;
#pragma unroll
            for (int e = 0; e < 4; e++) {
                int r = gr + ((e >> 1) ? 8 : 0);
                int c = gc + (e & 1);
                if (c < N) {
                    float v = alpha * acc[mf][nf][e];
                    if (bias) v += bias[c];
                    if (flags & F_GELU) v = gelu_f(v);
                    long off = cOff + (long)r * sCm + c;
                    if (flags & F_ACC) v += C[off];
                    if (flags & F_WANTC) C[off] = v;
                    if (Chi) {
                        u16 hh, ll;
                        split_bf16(v, hh, ll);
                        Chi[off] = hh; Clo[off] = ll;
                    }
                }
            }
        }
    }
}

// ---------------- split-transpose: out[n][k] = in[k][n] ----------------
__global__ __launch_bounds__(256) void split_t(
    const float* __restrict__ in, u16* __restrict__ hi, u16* __restrict__ lo,
    int inRows, int inCols, long inBatch, long outBatch)
{
    __shared__ float tbuf[32][33];
    int z = blockIdx.z;
    const float* src = in + (long)z * inBatch;
    int kb = blockIdx.x * 32;
    int nb = blockIdx.y * 32;
    int tx = threadIdx.x & 31, ty = threadIdx.x >> 5;
#pragma unroll
    for (int j = 0; j < 4; j++) {
        int r = ty + j * 8;
        tbuf[r][tx] = src[(long)(kb + r) * inCols + nb + tx];
    }
    __syncthreads();
    u16* h = hi + (long)z * outBatch;
    u16* l = lo + (long)z * outBatch;
#pragma unroll
    for (int j = 0; j < 4; j++) {
        int r = ty + j * 8;
        float v = tbuf[tx][r];
        u16 hh, ll;
        split_bf16(v, hh, ll);
        long o = (long)(nb + r) * inRows + kb + tx;
        h[o] = hh; l[o] = ll;
    }
}

// ---------------- LayerNorm D=512 -> planes ----------------
__global__ __launch_bounds__(256) void ln512p(
    const float* __restrict__ in, const float* __restrict__ g,
    const float* __restrict__ b, u16* __restrict__ oHi, u16* __restrict__ oLo)
{
    long row = blockIdx.x;
    const float* x = in + row * Dd;
    int tid = threadIdx.x;
    float v0 = x[tid], v1 = x[tid + 256];
    __shared__ float red[256];
    red[tid] = v0 + v1;
    __syncthreads();
    for (int s = 128; s > 0; s >>= 1) { if (tid < s) red[tid] += red[tid + s]; __syncthreads(); }
    float mu = red[0] * (1.f / Dd);
    __syncthreads();
    float d0 = v0 - mu, d1 = v1 - mu;
    red[tid] = d0 * d0 + d1 * d1;
    __syncthreads();
    for (int s = 128; s > 0; s >>= 1) { if (tid < s) red[tid] += red[tid + s]; __syncthreads(); }
    float rs = rsqrtf(red[0] * (1.f / Dd) + 1e-5f);
    float r0 = d0 * rs * g[tid] + b[tid];
    float r1 = d1 * rs * g[tid + 256] + b[tid + 256];
    u16 h0, l0, h1, l1;
    split_bf16(r0, h0, l0);
    split_bf16(r1, h1, l1);
    long o = row * Dd;
    oHi[o + tid] = h0;       oLo[o + tid] = l0;
    oHi[o + tid + 256] = h1; oLo[o + tid + 256] = l1;
}

// ---------------- LayerNorm D=64, warp/row ----------------
__global__ __launch_bounds__(128) void ln64(
    const float* __restrict__ in, const float* __restrict__ g,
    const float* __restrict__ b, float* __restrict__ outF,
    u16* __restrict__ oHi, u16* __restrict__ oLo,
    int D1, int D2, long s0, long s1, long s2)
{
    long warp = ((long)blockIdx.x * blockDim.x + threadIdx.x) >> 5;
    int lane = threadIdx.x & 31;
    long d2 = warp % D2;
    long t  = warp / D2;
    long d1 = t % D1;
    long d0 = t / D1;
    const float* x = in + d0 * s0 + d1 * s1 + d2 * s2;
    float v0 = x[lane], v1 = x[lane + 32];
    float s = v0 + v1;
#pragma unroll
    for (int o = 16; o; o >>= 1) s += __shfl_xor_sync(0xffffffffu, s, o);
    float mu = s * (1.f / 64.f);
    float q0 = v0 - mu, q1 = v1 - mu;
    float q = q0 * q0 + q1 * q1;
#pragma unroll
    for (int o = 16; o; o >>= 1) q += __shfl_xor_sync(0xffffffffu, q, o);
    float rs = rsqrtf(q * (1.f / 64.f) + 1e-5f);
    float r0 = q0 * rs * g[lane] + b[lane];
    float r1 = q1 * rs * g[lane + 32] + b[lane + 32];
    long o = warp * 64;
    if (outF) { outF[o + lane] = r0; outF[o + lane + 32] = r1; }
    if (oHi) {
        u16 h0, l0, h1, l1;
        split_bf16(r0, h0, l0);
        split_bf16(r1, h1, l1);
        oHi[o + lane] = h0;      oLo[o + lane] = l0;
        oHi[o + lane + 32] = h1; oLo[o + lane + 32] = l1;
    }
}

// ---------------- embedding ----------------
__global__ void embed(const int* __restrict__ x, const float* __restrict__ tok,
                      const float* __restrict__ pos, float* __restrict__ h)
{
    long i = (long)blockIdx.x * blockDim.x + threadIdx.x;
    if (i >= (long)Bb * Nn * Dd) return;
    int d = i % Dd;
    long bn = i / Dd;
    int n = bn % Nn;
    int tokid = x[bn];
    h[i] = tok[(long)tokid * Dd + d] + pos[(long)n * Dd + d];
}

// ---------------- softmax over axis=2 (n) of p (BH, N, R) ----------------
__global__ __launch_bounds__(256) void softmax_col(float* __restrict__ p)
{
    int blk = blockIdx.x;
    int rb  = blk % (Rr / 64);
    int bh  = blk / (Rr / 64);
    int c   = threadIdx.x % 64;
    int stripe = threadIdx.x / 64;
    float* base = p + (long)bh * Nn * Rr + rb * 64 + c;
    const int CH = Nn / 4;
    int n0 = stripe * CH;

    float m = -1e30f, s = 0.f;
    for (int n = n0; n < n0 + CH; n++) {
        float v = base[(long)n * Rr];
        float nm = fmaxf(m, v);
        s = s * __expf(m - nm) + __expf(v - nm);
        m = nm;
    }
    __shared__ float sm[4][64], ss[4][64];
    sm[stripe][c] = m; ss[stripe][c] = s;
    __syncthreads();
    float M = -1e30f;
#pragma unroll
    for (int j = 0; j < 4; j++) M = fmaxf(M, sm[j][c]);
    float S = 0.f;
#pragma unroll
    for (int j = 0; j < 4; j++) S += ss[j][c] * __expf(sm[j][c] - M);
    float inv = 1.f / S;
    for (int n = n0; n < n0 + CH; n++) {
        long off = (long)n * Rr;
        base[off] = __expf(base[off] - M) * inv;
    }
}

// ---------------- softmax over 384-wide rows -> planes ----------------
__global__ __launch_bounds__(128) void softmax_row384(
    const float* __restrict__ s, u16* __restrict__ oHi, u16* __restrict__ oLo)
{
    const float* r = s + (long)blockIdx.x * (WS + Rr);
    int tid = threadIdx.x;
    float v0 = r[tid], v1 = r[tid + 128], v2 = r[tid + 256];
    __shared__ float red[128];
    red[tid] = fmaxf(v0, fmaxf(v1, v2));
    __syncthreads();
    for (int st = 64; st > 0; st >>= 1) { if (tid < st) red[tid] = fmaxf(red[tid], red[tid + st]); __syncthreads(); }
    float m = red[0];
    __syncthreads();
    float e0 = __expf(v0 - m), e1 = __expf(v1 - m), e2 = __expf(v2 - m);
    red[tid] = e0 + e1 + e2;
    __syncthreads();
    for (int st = 64; st > 0; st >>= 1) { if (tid < st) red[tid] += red[tid + st]; __syncthreads(); }
    float inv = 1.f / red[0];
    long o = (long)blockIdx.x * (WS + Rr);
    u16 h, l;
    split_bf16(e0 * inv, h, l); oHi[o + tid] = h;       oLo[o + tid] = l;
    split_bf16(e1 * inv, h, l); oHi[o + tid + 128] = h; oLo[o + tid + 128] = l;
    split_bf16(e2 * inv, h, l); oHi[o + tid + 256] = h; oLo[o + tid + 256] = l;
}

// ---------------- final head ----------------
__global__ __launch_bounds__(256) void head_partial(
    const float* __restrict__ logits, const float* __restrict__ Wfin,
    float* __restrict__ part)
{
    int b = blockIdx.y;
    long k0 = (long)blockIdx.x * 1024;
    const float* lrow = logits + (long)b * KFIN;
    float acc[Cc];
#pragma unroll
    for (int c = 0; c < Cc; c++) acc[c] = 0.f;
    for (int i = threadIdx.x; i < 1024; i += 256) {
        long k = k0 + i;
        float l = lrow[k];
        const float* w = Wfin + k * Cc;
#pragma unroll
        for (int c = 0; c < Cc; c++) acc[c] = fmaf(l, w[c], acc[c]);
    }
#pragma unroll
    for (int c = 0; c < Cc; c++)
#pragma unroll
        for (int o = 16; o; o >>= 1) acc[c] += __shfl_xor_sync(0xffffffffu, acc[c], o);
    __shared__ float sm[8][Cc];
    int warp = threadIdx.x >> 5, lane = threadIdx.x & 31;
    if (lane == 0)
#pragma unroll
        for (int c = 0; c < Cc; c++) sm[warp][c] = acc[c];
    __syncthreads();
    if (threadIdx.x < Cc) {
        float s = 0.f;
#pragma unroll
        for (int w = 0; w < 8; w++) s += sm[w][threadIdx.x];
        part[((long)b * NCHUNK + blockIdx.x) * Cc + threadIdx.x] = s;
    }
}

__global__ void head_reduce(const float* __restrict__ part,
                            const float* __restrict__ bfin, float* __restrict__ out)
{
    int t = threadIdx.x;
    if (t < Bb * Cc) {
        int b = t / Cc, c = t % Cc;
        float s = bfin[c];
        for (int j = 0; j < NCHUNK; j++) s += part[((long)b * NCHUNK + j) * Cc + c];
        out[b * Cc + c] = s;
    }
}

// ---------------- host ----------------
static void gemm(const u16* Ahi, const u16* Alo, int lda,
                 const u16* Bhi, const u16* Blo, int ldb,
                 const float* bias, float* C, u16* Chi, u16* Clo, long sCm,
                 int M, int N, int K,
                 int D0, int D1, int D2,
                 long a0, long a1, long a2,
                 long b0, long b1, long b2,
                 long c0, long c1, long c2,
                 float alpha, int flags)
{
    dim3 grid((N + 127) / 128, M / 128, D0 * D1 * D2);
    tc_gemm<<<grid, 256, TC_SMEM>>>(Ahi, Alo, Bhi, Blo, bias, C, Chi, Clo,
                                    M, N, K, lda, ldb, sCm, D1, D2,
                                    a0, a1, a2, b0, b1, b2, c0, c1, c2, alpha, flags);
}

#define SYM(p, s) cudaGetSymbolAddress((void**)&p, s)

extern "C" void kernel_launch(void* const* d_in, const int* in_sizes, int n_in,
                              void* d_out, int out_size)
{
    const int*   x_in    = (const int*)  d_in[0];
    const float* tok_emb = (const float*)d_in[1];
    const float* pos_emb = (const float*)d_in[2];
    const float* ln1_g   = (const float*)d_in[3];
    const float* ln1_b   = (const float*)d_in[4];
    const float* Wq      = (const float*)d_in[5];
    const float* Wkv     = (const float*)d_in[6];
    const float* Wp      = (const float*)d_in[7];
    const float* lln_g   = (const float*)d_in[8];
    const float* lln_b   = (const float*)d_in[9];
    const float* gln_g   = (const float*)d_in[10];
    const float* gln_b   = (const float*)d_in[11];
    const float* Wo      = (const float*)d_in[12];
    const float* bo      = (const float*)d_in[13];
    const float* ln2_g   = (const float*)d_in[14];
    const float* ln2_b   = (const float*)d_in[15];
    const float* W1      = (const float*)d_in[16];
    const float* b1      = (const float*)d_in[17];
    const float* W2      = (const float*)d_in[18];
    const float* b2      = (const float*)d_in[19];
    const float* lnf_g   = (const float*)d_in[20];
    const float* lnf_b   = (const float*)d_in[21];
    const float* Wlog    = (const float*)d_in[22];
    const float* blog    = (const float*)d_in[23];
    const float* Wfin    = (const float*)d_in[24];
    const float* bfin    = (const float*)d_in[25];
    float* out = (float*)d_out;

    cudaFuncSetAttribute(tc_gemm, cudaFuncAttributeMaxDynamicSharedMemorySize, TC_SMEM);

    float *ph, *pkv, *pp, *pgkv, *pgvn, *plv, *psim, *po, *plog, *ppart;
    SYM(ph, g_h); SYM(pkv, g_kv); SYM(pp, g_p); SYM(pgkv, g_gkv);
    SYM(pgvn, g_gvn); SYM(plv, g_lv); SYM(psim, g_sim); SYM(po, g_o);
    SYM(plog, g_log); SYM(ppart, g_part);

    u16 *yAh,*yAl,*qAh,*qAl,*kvAh,*kvAl,*kvTh,*kvTl,*pTh,*pTl,*lkh,*lkl,
        *gknh,*gknl,*lvTh,*lvTl,*gvTh,*gvTl,*simh,*siml,*poAh,*poAl,
        *f1h,*f1l,*wBh,*wBl;
    SYM(yAh, g_yAhi);  SYM(yAl, g_yAlo);
    SYM(qAh, g_qAhi);  SYM(qAl, g_qAlo);
    SYM(kvAh, g_kvAhi); SYM(kvAl, g_kvAlo);
    SYM(kvTh, g_kvThi); SYM(kvTl, g_kvTlo);
    SYM(pTh, g_pThi);  SYM(pTl, g_pTlo);
    SYM(lkh, g_lkhi);  SYM(lkl, g_lklo);
    SYM(gknh, g_gknhi); SYM(gknl, g_gknlo);
    SYM(lvTh, g_lvThi); SYM(lvTl, g_lvTlo);
    SYM(gvTh, g_gvThi); SYM(gvTl, g_gvTlo);
    SYM(simh, g_simhi); SYM(siml, g_simlo);
    SYM(poAh, g_poAhi); SYM(poAl, g_poAlo);
    SYM(f1h, g_f1Ahi); SYM(f1l, g_f1Alo);
    SYM(wBh, g_wBhi);  SYM(wBl, g_wBlo);

    const long BND = (long)Bb * Nn * Dd;
    const int  MBN = Bb * Nn;
    const long GKV = (long)Bb * Hh * Rr * DH;   // 524288

    embed<<<(BND + 255) / 256, 256>>>(x_in, tok_emb, pos_emb, ph);

    for (int l = 0; l < Ll; l++) {
        const float* wq  = Wq  + (long)l * Dd * Hh * DH;
        const float* wkv = Wkv + (long)l * Dd * 2 * Hh * DH;
        const float* wp  = Wp  + (long)l * DH * Rr;
        const float* wo  = Wo  + (long)l * Hh * DH * Dd;
        const float* w1  = W1  + (long)l * Dd * FF;
        const float* w2  = W2  + (long)l * FF * Dd;

        // y = LN1(h) -> planes
        ln512p<<<MBN, 256>>>(ph, ln1_g + l * Dd, ln1_b + l * Dd, yAh, yAl);

        // q = y @ Wq * SCALE -> qA planes
        split_t<<<dim3(16, 16, 1), 256>>>(wq, wBh, wBl, 512, 512, 0, 0);
        gemm(yAh, yAl, 512, wBh, wBl, 512, nullptr, nullptr, qAh, qAl, 512,
             MBN, 512, 512, 1, 1, 1, 0,0,0, 0,0,0, 0,0,0, SCALE, 0);

        // kv = y @ Wkv -> float + kvA planes
        split_t<<<dim3(16, 32, 1), 256>>>(wkv, wBh, wBl, 512, 1024, 0, 0);
        gemm(yAh, yAl, 512, wBh, wBl, 512, nullptr, pkv, kvAh, kvAl, 1024,
             MBN, 1024, 512, 1, 1, 1, 0,0,0, 0,0,0, 0,0,0, 1.f, F_WANTC);

        // p = k @ Wp per (b,h) -> float
        split_t<<<dim3(2, 8, 1), 256>>>(wp, wBh, wBl, 64, 256, 0, 0);
        gemm(kvAh, kvAl, 1024, wBh, wBl, 64, nullptr, pp, nullptr, nullptr, Rr,
             Nn, Rr, DH, Bb, Hh, 1,
             (long)Nn * 1024, 64, 0,
             0, 0, 0,
             (long)Hh * Nn * Rr, (long)Nn * Rr, 0,
             1.f, F_WANTC);

        softmax_col<<<Bb * Hh * (Rr / 64), 256>>>(pp);

        // pT planes
        split_t<<<dim3(128, 8, 32), 256>>>(pp, pTh, pTl, Nn, Rr, (long)Nn * Rr, (long)Nn * Rr);
        // kvT planes
        split_t<<<dim3(128, 32, 4), 256>>>(pkv, kvTh, kvTl, Nn, 1024, (long)Nn * 1024, (long)Nn * 1024);

        // gk|gv = p^T @ {k,v} per (b,h,kv)
        gemm(pTh, pTl, Nn, kvTh, kvTl, Nn, nullptr, pgkv, nullptr, nullptr, DH,
             Rr, DH, Nn, Bb, Hh, 2,
             (long)Hh * Rr * Nn, (long)Rr * Nn, 0,
             (long)1024 * Nn, (long)64 * Nn, (long)512 * Nn,
             (long)Hh * Rr * DH, (long)Rr * DH, GKV,
             1.f, F_WANTC);

        // gkn planes; gvn float -> transpose planes
        ln64<<<(Bb * Hh * Rr) / 4, 128>>>(pgkv, gln_g + l * DH, gln_b + l * DH,
                                          nullptr, gknh, gknl, 1, Bb * Hh * Rr, 0, 0, DH);
        ln64<<<(Bb * Hh * Rr) / 4, 128>>>(pgkv + GKV, gln_g + l * DH, gln_b + l * DH,
                                          pgvn, nullptr, nullptr, 1, Bb * Hh * Rr, 0, 0, DH);
        split_t<<<dim3(8, 2, 32), 256>>>(pgvn, gvTh, gvTl, Rr, DH, (long)Rr * DH, (long)Rr * DH);

        // lk planes; lv float -> transpose planes
        ln64<<<(Bb * Hh * Nn) / 4, 128>>>(pkv, lln_g + l * DH, lln_b + l * DH,
                                          nullptr, lkh, lkl,
                                          Hh, Nn, (long)Nn * 1024, DH, 1024);
        ln64<<<(Bb * Hh * Nn) / 4, 128>>>(pkv + Hh * DH, lln_g + l * DH, lln_b + l * DH,
                                          plv, nullptr, nullptr,
                                          Hh, Nn, (long)Nn * 1024, DH, 1024);
        split_t<<<dim3(128, 2, 32), 256>>>(plv, lvTh, lvTl, Nn, DH, (long)Nn * DH, (long)Nn * DH);

        // sim_l per (b,h,w)
        gemm(qAh, qAl, 512, lkh, lkl, 64, nullptr, psim, nullptr, nullptr, WS + Rr,
             WS, WS, DH, Bb, Hh, NW,
             (long)Nn * 512, 64, (long)WS * 512,
             (long)Hh * Nn * 64, (long)Nn * 64, (long)WS * 64,
             (long)Hh * Nn * (WS + Rr), (long)Nn * (WS + Rr), (long)WS * (WS + Rr),
             1.f, F_WANTC);

        // sim_g per (b,h)
        gemm(qAh, qAl, 512, gknh, gknl, 64, nullptr, psim + WS, nullptr, nullptr, WS + Rr,
             Nn, Rr, DH, Bb, Hh, 1,
             (long)Nn * 512, 64, 0,
             (long)Hh * Rr * 64, (long)Rr * 64, 0,
             (long)Hh * Nn * (WS + Rr), (long)Nn * (WS + Rr), 0,
             1.f, F_WANTC);

        // softmax -> simA planes
        softmax_row384<<<Bb * Hh * Nn, 128>>>(psim, simh, siml);

        // o = a_l @ lv per (b,h,w)
        gemm(simh, siml, WS + Rr, lvTh, lvTl, Nn, nullptr, po, nullptr, nullptr, 512,
             WS, DH, WS, Bb, Hh, NW,
             (long)Hh * Nn * (WS + Rr), (long)Nn * (WS + Rr), (long)WS * (WS + Rr),
             (long)Hh * DH * Nn, (long)DH * Nn, WS,
             (long)Nn * 512, 64, (long)WS * 512,
             1.f, F_WANTC);

        // o += a_g @ gvn per (b,h) -> poA planes
        gemm(simh + WS, siml + WS, WS + Rr, gvTh, gvTl, Rr, nullptr, po, poAh, poAl, 512,
             Nn, DH, Rr, Bb, Hh, 1,
             (long)Hh * Nn * (WS + Rr), (long)Nn * (WS + Rr), 0,
             (long)Hh * DH * Rr, (long)DH * Rr, 0,
             (long)Nn * 512, 64, 0,
             1.f, F_ACC);

        // h += o @ Wo + bo
        split_t<<<dim3(16, 16, 1), 256>>>(wo, wBh, wBl, 512, 512, 0, 0);
        gemm(poAh, poAl, 512, wBh, wBl, 512, bo + l * Dd, ph, nullptr, nullptr, 512,
             MBN, 512, 512, 1, 1, 1, 0,0,0, 0,0,0, 0,0,0, 1.f, F_ACC | F_WANTC);

        // y = LN2(h) -> planes
        ln512p<<<MBN, 256>>>(ph, ln2_g + l * Dd, ln2_b + l * Dd, yAh, yAl);

        // f1 = gelu(y @ W1 + b1) -> f1A planes
        split_t<<<dim3(16, 64, 1), 256>>>(w1, wBh, wBl, 512, 2048, 0, 0);
        gemm(yAh, yAl, 512, wBh, wBl, 512, b1 + (long)l * FF, nullptr, f1h, f1l, 2048,
             MBN, 2048, 512, 1, 1, 1, 0,0,0, 0,0,0, 0,0,0, 1.f, F_GELU);

        // h += f1 @ W2 + b2
        split_t<<<dim3(64, 16, 1), 256>>>(w2, wBh, wBl, 2048, 512, 0, 0);
        gemm(f1h, f1l, 2048, wBh, wBl, 2048, b2 + l * Dd, ph, nullptr, nullptr, 512,
             MBN, 512, 2048, 1, 1, 1, 0,0,0, 0,0,0, 0,0,0, 1.f, F_ACC | F_WANTC);
    }

    // final LN + vocab projection
    ln512p<<<MBN, 256>>>(ph, lnf_g, lnf_b, yAh, yAl);
    split_t<<<dim3(16, 16, 1), 256>>>(Wlog, wBh, wBl, 512, 512, 0, 0);
    gemm(yAh, yAl, 512, wBh, wBl, 512, blog, plog, nullptr, nullptr, 512,
         MBN, 512, 512, 1, 1, 1, 0,0,0, 0,0,0, 0,0,0, 1.f, F_WANTC);

    // head
    {
        dim3 grid(NCHUNK, Bb);
        head_partial<<<grid, 256>>>(plog, Wfin, ppart);
        head_reduce<<<1, 64>>>(ppart, bfin, out);
    }
}

// round 10
// speedup vs baseline: 3.4544x; 1.0971x over previous
#include <cuda_runtime.h>
#include <cuda_bf16.h>
#include <math.h>
#include <stdint.h>

typedef unsigned short u16;

// Problem constants
#define Bb   4
#define Nn   4096
#define Vv   512
#define Dd   512
#define Hh   8
#define DH   64
#define Ll   4
#define WS   128
#define Rr   256
#define Cc   10
#define FF   2048
#define NW   (Nn / WS)
#define SCALE 0.125f
#define KFIN ((long)Nn * Vv)
#define NCHUNK 2048

// flags
#define F_ACC   1
#define F_GELU  2
#define F_WANTC 4

// ---------------- scratch (device globals; no allocation) ----------------
__device__ float g_h   [(size_t)Bb * Nn * Dd];
__device__ float g_kv  [(size_t)Bb * Nn * 2 * Hh * DH];
__device__ float g_p   [(size_t)Bb * Hh * Nn * Rr];
__device__ float g_gkv [(size_t)2 * Bb * Hh * Rr * DH];   // gk | gv
__device__ float g_gkp [(size_t)4 * 2 * Bb * Hh * Rr * DH]; // split-K partials
__device__ float g_gvn [(size_t)Bb * Hh * Rr * DH];
__device__ float g_lv  [(size_t)Bb * Hh * Nn * DH];
__device__ float g_sim [(size_t)Bb * Hh * Nn * (WS + Rr)];
__device__ float g_o   [(size_t)Bb * Nn * Hh * DH];
__device__ float g_log [(size_t)Bb * Nn * Vv];
__device__ float g_part[(size_t)Bb * NCHUNK * Cc];
__device__ float g_pM  [Bb * Hh * Rr];
__device__ float g_pI  [Bb * Hh * Rr];

// bf16 hi/lo planes
__device__ u16 g_yAhi [8388608],  g_yAlo [8388608];
__device__ u16 g_qAhi [8388608],  g_qAlo [8388608];
__device__ u16 g_kvAhi[16777216], g_kvAlo[16777216];
__device__ u16 g_kvThi[16777216], g_kvTlo[16777216];
__device__ u16 g_pThi [33554432], g_pTlo [33554432];
__device__ u16 g_lkhi [8388608],  g_lklo [8388608];
__device__ u16 g_gknhi[524288],   g_gknlo[524288];
__device__ u16 g_lvThi[8388608],  g_lvTlo[8388608];
__device__ u16 g_gvThi[524288],   g_gvTlo[524288];
__device__ u16 g_simhi[50331648], g_simlo[50331648];
__device__ u16 g_poAhi[8388608],  g_poAlo[8388608];
__device__ u16 g_f1Ahi[33554432], g_f1Alo[33554432];
__device__ u16 g_wBhi [1048576],  g_wBlo [1048576];

// ---------------- helpers ----------------
__device__ __forceinline__ float gelu_f(float x) {
    const float k0 = 0.7978845608028654f, k1 = 0.044715f;
    return 0.5f * x * (1.f + tanhf(k0 * (x + k1 * x * x * x)));
}
__device__ __forceinline__ uint32_t smem_u32(const void* p) {
    uint32_t a;
    asm("{ .reg .u64 t; cvta.to.shared.u64 t, %1; cvt.u32.u64 %0, t; }" : "=r"(a) : "l"(p));
    return a;
}
__device__ __forceinline__ void split_bf16(float v, u16& hi, u16& lo) {
    __nv_bfloat16 h = __float2bfloat16_rn(v);
    float rem = v - __bfloat162float(h);
    __nv_bfloat16 l = __float2bfloat16_rn(rem);
    hi = __bfloat16_as_ushort(h);
    lo = __bfloat16_as_ushort(l);
}

#define LDMATRIX_X4(r0, r1, r2, r3, addr) \
    asm volatile("ldmatrix.sync.aligned.m8n8.x4.shared.b16 {%0,%1,%2,%3}, [%4];" \
        : "=r"(r0), "=r"(r1), "=r"(r2), "=r"(r3) : "r"(addr))

#define MMA_BF16(c, a, b0v, b1v) \
    asm volatile("mma.sync.aligned.m16n8k16.row.col.f32.bf16.bf16.f32 " \
        "{%0,%1,%2,%3}, {%4,%5,%6,%7}, {%8,%9}, {%0,%1,%2,%3};" \
        : "+f"((c)[0]), "+f"((c)[1]), "+f"((c)[2]), "+f"((c)[3]) \
        : "r"((a)[0]), "r"((a)[1]), "r"((a)[2]), "r"((a)[3]), "r"(b0v), "r"(b1v))

#define CP16(dst, src, sz) \
    asm volatile("cp.async.cg.shared.global [%0], [%1], 16, %2;" \
        :: "r"(dst), "l"(src), "r"(sz))
#define CP_COMMIT() asm volatile("cp.async.commit_group;")
#define CP_WAIT(n)  asm volatile("cp.async.wait_group %0;" :: "n"(n))

// ---------------- GEMM on pre-split bf16 planes ----------------
#define PADK 40
#define PLANE_B 10240           // 128*PADK*2
#define BUF_B   (4 * PLANE_B)   // 40960
#define TC_SMEM (2 * BUF_B)     // 81920

template<int BROWS>
__device__ __forceinline__ void load_tiles(
    uint32_t cbase,
    const u16* __restrict__ Ahi, const u16* __restrict__ Alo,
    const u16* __restrict__ Bhi, const u16* __restrict__ Blo,
    long aOff, long bOff, int lda, int ldb,
    int mBase, int nBase, int N, int kBase, int k0, int tid)
{
#pragma unroll
    for (int v = 0; v < 2; v++) {
        int vec = tid + v * 256;
        int row = vec >> 2, kq = (vec & 3) << 3;
        uint32_t d = cbase + (uint32_t)(row * PADK + kq) * 2;
        long offA = aOff + (long)(mBase + row) * lda + kBase + k0 + kq;
        CP16(d,           Ahi + offA, 16);
        CP16(d + PLANE_B, Alo + offA, 16);
    }
#pragma unroll
    for (int v = 0; v < BROWS / 64; v++) {
        int vec = tid + v * 256;
        int row = vec >> 2, kq = (vec & 3) << 3;
        uint32_t d = cbase + (uint32_t)(row * PADK + kq) * 2;
        int ok   = (nBase + row < N) ? 16 : 0;
        int brow = (nBase + row < N) ? row : 0;
        long offB = bOff + (long)(nBase + brow) * ldb + kBase + k0 + kq;
        CP16(d + 2 * PLANE_B, Bhi + offB, ok);
        CP16(d + 3 * PLANE_B, Blo + offB, ok);
    }
}

template<bool N64>
__global__ __launch_bounds__(256, 2) void tc_gemm(
    const u16* __restrict__ Ahi, const u16* __restrict__ Alo,
    const u16* __restrict__ Bhi, const u16* __restrict__ Blo,
    const float* __restrict__ bias, float* __restrict__ C,
    u16* __restrict__ Chi, u16* __restrict__ Clo,
    int M, int N, int K, int lda, int ldb, long sCm,
    int D1, int D2,
    long a0, long a1, long a2,
    long b0, long b1, long b2,
    long c0, long c1, long c2,
    float alpha, int flags, int ksplit, long cSeg)
{
    extern __shared__ __align__(16) char smem[];
    uint32_t sb = smem_u32(smem);

    int z = blockIdx.z;
    int seg = 0;
    if (ksplit > 1) { seg = z % ksplit; z /= ksplit; }
    int d2 = z % D2;
    int t  = z / D2;
    int d1 = t % D1;
    int d0 = t / D1;
    long aOff = (long)d0 * a0 + (long)d1 * a1 + (long)d2 * a2;
    long bOff = (long)d0 * b0 + (long)d1 * b1 + (long)d2 * b2;
    long cOff = (long)d0 * c0 + (long)d1 * c1 + (long)d2 * c2 + (long)seg * cSeg;
    int kBase = seg * K;

    int tid  = threadIdx.x;
    int lane = tid & 31;
    int wid  = tid >> 5;
    constexpr int MF = N64 ? 2 : 4;
    constexpr int MSTEP = N64 ? 32 : 64;
    constexpr int BR = N64 ? 64 : 128;
    int wm = N64 ? (wid & 3) : (wid & 1);
    int wn = N64 ? (wid >> 2) : (wid >> 1);
    int mBase = blockIdx.y * 128;
    int nBase = blockIdx.x * (N64 ? 64 : 128);

    const int nChunks = K >> 5;

    float acc[MF][4][4];
#pragma unroll
    for (int i = 0; i < MF; i++)
#pragma unroll
        for (int j = 0; j < 4; j++)
#pragma unroll
            for (int e = 0; e < 4; e++) acc[i][j][e] = 0.f;

    load_tiles<BR>(sb, Ahi, Alo, Bhi, Blo, aOff, bOff, lda, ldb,
                   mBase, nBase, N, kBase, 0, tid);
    CP_COMMIT();

    int lrow = lane & 15;
    int lcol = (lane >> 4) * 8;

    for (int ch = 0; ch < nChunks; ch++) {
        if (ch + 1 < nChunks) {
            load_tiles<BR>(sb + ((ch + 1) & 1) * BUF_B, Ahi, Alo, Bhi, Blo,
                           aOff, bOff, lda, ldb, mBase, nBase, N, kBase,
                           (ch + 1) << 5, tid);
            CP_COMMIT();
            CP_WAIT(1);
        } else {
            CP_WAIT(0);
        }
        __syncthreads();

        uint32_t cbase = sb + (ch & 1) * BUF_B;
#pragma unroll
        for (int kk = 0; kk < 2; kk++) {
            int kc = kk * 16 + lcol;
            uint32_t afh[MF][4], afl[MF][4], bh[2][4], bl[2][4];
#pragma unroll
            for (int mf = 0; mf < MF; mf++) {
                uint32_t ao = cbase + (uint32_t)((wm * MSTEP + mf * 16 + lrow) * PADK + kc) * 2;
                LDMATRIX_X4(afh[mf][0], afh[mf][1], afh[mf][2], afh[mf][3], ao);
                LDMATRIX_X4(afl[mf][0], afl[mf][1], afl[mf][2], afl[mf][3], ao + PLANE_B);
            }
#pragma unroll
            for (int g = 0; g < 2; g++) {
                uint32_t bo = cbase + 2 * PLANE_B
                            + (uint32_t)((wn * 32 + g * 16 + lrow) * PADK + kc) * 2;
                LDMATRIX_X4(bh[g][0], bh[g][1], bh[g][2], bh[g][3], bo);
            }
#pragma unroll
            for (int mf = 0; mf < MF; mf++)
#pragma unroll
                for (int nf = 0; nf < 4; nf++) {
                    int g = nf >> 1, o = nf & 1;
                    MMA_BF16(acc[mf][nf], afh[mf], bh[g][o], bh[g][o + 2]);
                }
#pragma unroll
            for (int mf = 0; mf < MF; mf++)
#pragma unroll
                for (int nf = 0; nf < 4; nf++) {
                    int g = nf >> 1, o = nf & 1;
                    MMA_BF16(acc[mf][nf], afl[mf], bh[g][o], bh[g][o + 2]);
                }
#pragma unroll
            for (int g = 0; g < 2; g++) {
                uint32_t bo = cbase + 3 * PLANE_B
                            + (uint32_t)((wn * 32 + g * 16 + lrow) * PADK + kc) * 2;
                LDMATRIX_X4(bl[g][0], bl[g][1], bl[g][2], bl[g][3], bo);
            }
#pragma unroll
            for (int mf = 0; mf < MF; mf++)
#pragma unroll
                for (int nf = 0; nf < 4; nf++) {
                    int g = nf >> 1, o = nf & 1;
                    MMA_BF16(acc[mf][nf], afh[mf], bl[g][o], bl[g][o + 2]);
                }
        }
        __syncthreads();
    }

    // epilogue
    int grp = lane >> 2, ct = lane & 3;
#pragma unroll
    for (int mf = 0; mf < MF; mf++) {
#pragma unroll
        for (int nf = 0; nf < 4; nf++) {
            int gr = mBase + wm * MSTEP + mf * 16 + grp;
            int gc = nBase + wn * 32 + nf * 8 + ct * 2;
#pragma unroll
            for (int e = 0; e < 4; e++) {
                int r = gr + ((e >> 1) ? 8 : 0);
                int c = gc + (e & 1);
                if (c < N) {
                    float v = alpha * acc[mf][nf][e];
                    if (bias) v += bias[c];
                    if (flags & F_GELU) v = gelu_f(v);
                    long off = cOff + (long)r * sCm + c;
                    if (flags & F_ACC) v += C[off];
                    if (flags & F_WANTC) C[off] = v;
                    if (Chi) {
                        u16 hh, ll;
                        split_bf16(v, hh, ll);
                        Chi[off] = hh; Clo[off] = ll;
                    }
                }
            }
        }
    }
}

// ---------------- split-K partial reduce (fixed order, deterministic) ----------------
__global__ __launch_bounds__(256) void seg_reduce(
    const float* __restrict__ part, float* __restrict__ out,
    long n, int segs, long segStride)
{
    long i = (long)blockIdx.x * 256 + threadIdx.x;
    if (i < n) {
        float s = 0.f;
        for (int j = 0; j < segs; j++) s += part[(long)j * segStride + i];
        out[i] = s;
    }
}

// ---------------- split-transpose: out[n][k] = in[k][n] ----------------
__global__ __launch_bounds__(256) void split_t(
    const float* __restrict__ in, u16* __restrict__ hi, u16* __restrict__ lo,
    int inRows, int inCols, long inBatch, long outBatch)
{
    __shared__ float tbuf[32][33];
    int z = blockIdx.z;
    const float* src = in + (long)z * inBatch;
    int kb = blockIdx.x * 32;
    int nb = blockIdx.y * 32;
    int tx = threadIdx.x & 31, ty = threadIdx.x >> 5;
#pragma unroll
    for (int j = 0; j < 4; j++) {
        int r = ty + j * 8;
        tbuf[r][tx] = src[(long)(kb + r) * inCols + nb + tx];
    }
    __syncthreads();
    u16* h = hi + (long)z * outBatch;
    u16* l = lo + (long)z * outBatch;
#pragma unroll
    for (int j = 0; j < 4; j++) {
        int r = ty + j * 8;
        float v = tbuf[tx][r];
        u16 hh, ll;
        split_bf16(v, hh, ll);
        long o = (long)(nb + r) * inRows + kb + tx;
        h[o] = hh; l[o] = ll;
    }
}

// ---- p transpose with fused softmax normalize: out = exp(v - M[col]) * I[col] ----
__global__ __launch_bounds__(256) void split_t_sm(
    const float* __restrict__ in, const float* __restrict__ stM,
    const float* __restrict__ stI,
    u16* __restrict__ hi, u16* __restrict__ lo,
    int inRows, int inCols, long inBatch, long outBatch)
{
    __shared__ float tbuf[32][33];
    int z = blockIdx.z;
    const float* src = in + (long)z * inBatch;
    int kb = blockIdx.x * 32;
    int nb = blockIdx.y * 32;
    int tx = threadIdx.x & 31, ty = threadIdx.x >> 5;
#pragma unroll
    for (int j = 0; j < 4; j++) {
        int r = ty + j * 8;
        tbuf[r][tx] = src[(long)(kb + r) * inCols + nb + tx];
    }
    __syncthreads();
    u16* h = hi + (long)z * outBatch;
    u16* l = lo + (long)z * outBatch;
#pragma unroll
    for (int j = 0; j < 4; j++) {
        int r = ty + j * 8;
        int col = nb + r;
        float M = stM[(long)z * inCols + col];
        float I = stI[(long)z * inCols + col];
        float v = __expf(tbuf[tx][r] - M) * I;
        u16 hh, ll;
        split_bf16(v, hh, ll);
        long o = (long)col * inRows + kb + tx;
        h[o] = hh; l[o] = ll;
    }
}

// ---------------- LayerNorm D=512 -> planes ----------------
__global__ __launch_bounds__(256) void ln512p(
    const float* __restrict__ in, const float* __restrict__ g,
    const float* __restrict__ b, u16* __restrict__ oHi, u16* __restrict__ oLo)
{
    long row = blockIdx.x;
    const float* x = in + row * Dd;
    int tid = threadIdx.x;
    float v0 = x[tid], v1 = x[tid + 256];
    __shared__ float red[256];
    red[tid] = v0 + v1;
    __syncthreads();
    for (int s = 128; s > 0; s >>= 1) { if (tid < s) red[tid] += red[tid + s]; __syncthreads(); }
    float mu = red[0] * (1.f / Dd);
    __syncthreads();
    float d0 = v0 - mu, d1 = v1 - mu;
    red[tid] = d0 * d0 + d1 * d1;
    __syncthreads();
    for (int s = 128; s > 0; s >>= 1) { if (tid < s) red[tid] += red[tid + s]; __syncthreads(); }
    float rs = rsqrtf(red[0] * (1.f / Dd) + 1e-5f);
    float r0 = d0 * rs * g[tid] + b[tid];
    float r1 = d1 * rs * g[tid + 256] + b[tid + 256];
    u16 h0, l0, h1, l1;
    split_bf16(r0, h0, l0);
    split_bf16(r1, h1, l1);
    long o = row * Dd;
    oHi[o + tid] = h0;       oLo[o + tid] = l0;
    oHi[o + tid + 256] = h1; oLo[o + tid + 256] = l1;
}

// ---------------- LayerNorm D=64, warp/row ----------------
__global__ __launch_bounds__(128) void ln64(
    const float* __restrict__ in, const float* __restrict__ g,
    const float* __restrict__ b, float* __restrict__ outF,
    u16* __restrict__ oHi, u16* __restrict__ oLo,
    int D1, int D2, long s0, long s1, long s2)
{
    long warp = ((long)blockIdx.x * blockDim.x + threadIdx.x) >> 5;
    int lane = threadIdx.x & 31;
    long d2 = warp % D2;
    long t  = warp / D2;
    long d1 = t % D1;
    long d0 = t / D1;
    const float* x = in + d0 * s0 + d1 * s1 + d2 * s2;
    float v0 = x[lane], v1 = x[lane + 32];
    float s = v0 + v1;
#pragma unroll
    for (int o = 16; o; o >>= 1) s += __shfl_xor_sync(0xffffffffu, s, o);
    float mu = s * (1.f / 64.f);
    float q0 = v0 - mu, q1 = v1 - mu;
    float q = q0 * q0 + q1 * q1;
#pragma unroll
    for (int o = 16; o; o >>= 1) q += __shfl_xor_sync(0xffffffffu, q, o);
    float rs = rsqrtf(q * (1.f / 64.f) + 1e-5f);
    float r0 = q0 * rs * g[lane] + b[lane];
    float r1 = q1 * rs * g[lane + 32] + b[lane + 32];
    long o = warp * 64;
    if (outF) { outF[o + lane] = r0; outF[o + lane + 32] = r1; }
    if (oHi) {
        u16 h0, l0, h1, l1;
        split_bf16(r0, h0, l0);
        split_bf16(r1, h1, l1);
        oHi[o + lane] = h0;      oLo[o + lane] = l0;
        oHi[o + lane + 32] = h1; oLo[o + lane + 32] = l1;
    }
}

// ---------------- embedding ----------------
__global__ void embed(const int* __restrict__ x, const float* __restrict__ tok,
                      const float* __restrict__ pos, float* __restrict__ h)
{
    long i = (long)blockIdx.x * blockDim.x + threadIdx.x;
    if (i >= (long)Bb * Nn * Dd) return;
    int d = i % Dd;
    long bn = i / Dd;
    int n = bn % Nn;
    int tokid = x[bn];
    h[i] = tok[(long)tokid * Dd + d] + pos[(long)n * Dd + d];
}

// ------- softmax stats over axis=2 (n) of p (BH, N, R): writes M and 1/S -------
__global__ __launch_bounds__(256) void softmax_stats(
    const float* __restrict__ p, float* __restrict__ stM, float* __restrict__ stI)
{
    int blk = blockIdx.x;
    int rb  = blk % (Rr / 64);
    int bh  = blk / (Rr / 64);
    int c   = threadIdx.x % 64;
    int stripe = threadIdx.x / 64;
    const float* base = p + (long)bh * Nn * Rr + rb * 64 + c;
    const int CH = Nn / 4;
    int n0 = stripe * CH;

    float m = -1e30f, s = 0.f;
    for (int n = n0; n < n0 + CH; n++) {
        float v = base[(long)n * Rr];
        float nm = fmaxf(m, v);
        s = s * __expf(m - nm) + __expf(v - nm);
        m = nm;
    }
    __shared__ float sm[4][64], ss[4][64];
    sm[stripe][c] = m; ss[stripe][c] = s;
    __syncthreads();
    if (stripe == 0) {
        float M = -1e30f;
#pragma unroll
        for (int j = 0; j < 4; j++) M = fmaxf(M, sm[j][c]);
        float S = 0.f;
#pragma unroll
        for (int j = 0; j < 4; j++) S += ss[j][c] * __expf(sm[j][c] - M);
        stM[(long)bh * Rr + rb * 64 + c] = M;
        stI[(long)bh * Rr + rb * 64 + c] = 1.f / S;
    }
}

// ---------------- softmax over 384-wide rows -> planes ----------------
__global__ __launch_bounds__(128) void softmax_row384(
    const float* __restrict__ s, u16* __restrict__ oHi, u16* __restrict__ oLo)
{
    const float* r = s + (long)blockIdx.x * (WS + Rr);
    int tid = threadIdx.x;
    float v0 = r[tid], v1 = r[tid + 128], v2 = r[tid + 256];
    __shared__ float red[128];
    red[tid] = fmaxf(v0, fmaxf(v1, v2));
    __syncthreads();
    for (int st = 64; st > 0; st >>= 1) { if (tid < st) red[tid] = fmaxf(red[tid], red[tid + st]); __syncthreads(); }
    float m = red[0];
    __syncthreads();
    float e0 = __expf(v0 - m), e1 = __expf(v1 - m), e2 = __expf(v2 - m);
    red[tid] = e0 + e1 + e2;
    __syncthreads();
    for (int st = 64; st > 0; st >>= 1) { if (tid < st) red[tid] += red[tid + st]; __syncthreads(); }
    float inv = 1.f / red[0];
    long o = (long)blockIdx.x * (WS + Rr);
    u16 h, l;
    split_bf16(e0 * inv, h, l); oHi[o + tid] = h;       oLo[o + tid] = l;
    split_bf16(e1 * inv, h, l); oHi[o + tid + 128] = h; oLo[o + tid + 128] = l;
    split_bf16(e2 * inv, h, l); oHi[o + tid + 256] = h; oLo[o + tid + 256] = l;
}

// ---------------- final head ----------------
__global__ __launch_bounds__(256) void head_partial(
    const float* __restrict__ logits, const float* __restrict__ Wfin,
    float* __restrict__ part)
{
    int b = blockIdx.y;
    long k0 = (long)blockIdx.x * 1024;
    const float* lrow = logits + (long)b * KFIN;
    float acc[Cc];
#pragma unroll
    for (int c = 0; c < Cc; c++) acc[c] = 0.f;
    for (int i = threadIdx.x; i < 1024; i += 256) {
        long k = k0 + i;
        float l = lrow[k];
        const float* w = Wfin + k * Cc;
#pragma unroll
        for (int c = 0; c < Cc; c++) acc[c] = fmaf(l, w[c], acc[c]);
    }
#pragma unroll
    for (int c = 0; c < Cc; c++)
#pragma unroll
        for (int o = 16; o; o >>= 1) acc[c] += __shfl_xor_sync(0xffffffffu, acc[c], o);
    __shared__ float sm[8][Cc];
    int warp = threadIdx.x >> 5, lane = threadIdx.x & 31;
    if (lane == 0)
#pragma unroll
        for (int c = 0; c < Cc; c++) sm[warp][c] = acc[c];
    __syncthreads();
    if (threadIdx.x < Cc) {
        float s = 0.f;
#pragma unroll
        for (int w = 0; w < 8; w++) s += sm[w][threadIdx.x];
        part[((long)b * NCHUNK + blockIdx.x) * Cc + threadIdx.x] = s;
    }
}

__global__ void head_reduce(const float* __restrict__ part,
                            const float* __restrict__ bfin, float* __restrict__ out)
{
    int t = threadIdx.x;
    if (t < Bb * Cc) {
        int b = t / Cc, c = t % Cc;
        float s = bfin[c];
        for (int j = 0; j < NCHUNK; j++) s += part[((long)b * NCHUNK + j) * Cc + c];
        out[b * Cc + c] = s;
    }
}

// ---------------- host ----------------
static void gemm(const u16* Ahi, const u16* Alo, int lda,
                 const u16* Bhi, const u16* Blo, int ldb,
                 const float* bias, float* C, u16* Chi, u16* Clo, long sCm,
                 int M, int N, int K,
                 int D0, int D1, int D2,
                 long a0, long a1, long a2,
                 long b0, long b1, long b2,
                 long c0, long c1, long c2,
                 float alpha, int flags, int ksplit = 1, long cSeg = 0)
{
    if (N == 64) {
        dim3 grid(1, M / 128, D0 * D1 * D2 * ksplit);
        tc_gemm<true><<<grid, 256, TC_SMEM>>>(Ahi, Alo, Bhi, Blo, bias, C, Chi, Clo,
            M, N, K, lda, ldb, sCm, D1, D2,
            a0, a1, a2, b0, b1, b2, c0, c1, c2, alpha, flags, ksplit, cSeg);
    } else {
        dim3 grid((N + 127) / 128, M / 128, D0 * D1 * D2 * ksplit);
        tc_gemm<false><<<grid, 256, TC_SMEM>>>(Ahi, Alo, Bhi, Blo, bias, C, Chi, Clo,
            M, N, K, lda, ldb, sCm, D1, D2,
            a0, a1, a2, b0, b1, b2, c0, c1, c2, alpha, flags, ksplit, cSeg);
    }
}

#define SYM(p, s) cudaGetSymbolAddress((void**)&p, s)

extern "C" void kernel_launch(void* const* d_in, const int* in_sizes, int n_in,
                              void* d_out, int out_size)
{
    const int*   x_in    = (const int*)  d_in[0];
    const float* tok_emb = (const float*)d_in[1];
    const float* pos_emb = (const float*)d_in[2];
    const float* ln1_g   = (const float*)d_in[3];
    const float* ln1_b   = (const float*)d_in[4];
    const float* Wq      = (const float*)d_in[5];
    const float* Wkv     = (const float*)d_in[6];
    const float* Wp      = (const float*)d_in[7];
    const float* lln_g   = (const float*)d_in[8];
    const float* lln_b   = (const float*)d_in[9];
    const float* gln_g   = (const float*)d_in[10];
    const float* gln_b   = (const float*)d_in[11];
    const float* Wo      = (const float*)d_in[12];
    const float* bo      = (const float*)d_in[13];
    const float* ln2_g   = (const float*)d_in[14];
    const float* ln2_b   = (const float*)d_in[15];
    const float* W1      = (const float*)d_in[16];
    const float* b1      = (const float*)d_in[17];
    const float* W2      = (const float*)d_in[18];
    const float* b2      = (const float*)d_in[19];
    const float* lnf_g   = (const float*)d_in[20];
    const float* lnf_b   = (const float*)d_in[21];
    const float* Wlog    = (const float*)d_in[22];
    const float* blog    = (const float*)d_in[23];
    const float* Wfin    = (const float*)d_in[24];
    const float* bfin    = (const float*)d_in[25];
    float* out = (float*)d_out;

    cudaFuncSetAttribute(tc_gemm<false>, cudaFuncAttributeMaxDynamicSharedMemorySize, TC_SMEM);
    cudaFuncSetAttribute(tc_gemm<true>,  cudaFuncAttributeMaxDynamicSharedMemorySize, TC_SMEM);

    float *ph, *pkv, *pp, *pgkv, *pgkp, *pgvn, *plv, *psim, *po, *plog, *ppart, *ppM, *ppI;
    SYM(ph, g_h); SYM(pkv, g_kv); SYM(pp, g_p); SYM(pgkv, g_gkv); SYM(pgkp, g_gkp);
    SYM(pgvn, g_gvn); SYM(plv, g_lv); SYM(psim, g_sim); SYM(po, g_o);
    SYM(plog, g_log); SYM(ppart, g_part); SYM(ppM, g_pM); SYM(ppI, g_pI);

    u16 *yAh,*yAl,*qAh,*qAl,*kvAh,*kvAl,*kvTh,*kvTl,*pTh,*pTl,*lkh,*lkl,
        *gknh,*gknl,*lvTh,*lvTl,*gvTh,*gvTl,*simh,*siml,*poAh,*poAl,
        *f1h,*f1l,*wBh,*wBl;
    SYM(yAh, g_yAhi);  SYM(yAl, g_yAlo);
    SYM(qAh, g_qAhi);  SYM(qAl, g_qAlo);
    SYM(kvAh, g_kvAhi); SYM(kvAl, g_kvAlo);
    SYM(kvTh, g_kvThi); SYM(kvTl, g_kvTlo);
    SYM(pTh, g_pThi);  SYM(pTl, g_pTlo);
    SYM(lkh, g_lkhi);  SYM(lkl, g_lklo);
    SYM(gknh, g_gknhi); SYM(gknl, g_gknlo);
    SYM(lvTh, g_lvThi); SYM(lvTl, g_lvTlo);
    SYM(gvTh, g_gvThi); SYM(gvTl, g_gvTlo);
    SYM(simh, g_simhi); SYM(siml, g_simlo);
    SYM(poAh, g_poAhi); SYM(poAl, g_poAlo);
    SYM(f1h, g_f1Ahi); SYM(f1l, g_f1Alo);
    SYM(wBh, g_wBhi);  SYM(wBl, g_wBlo);

    const long BND = (long)Bb * Nn * Dd;
    const int  MBN = Bb * Nn;
    const long GKV = (long)Bb * Hh * Rr * DH;   // 524288

    embed<<<(BND + 255) / 256, 256>>>(x_in, tok_emb, pos_emb, ph);

    for (int l = 0; l < Ll; l++) {
        const float* wq  = Wq  + (long)l * Dd * Hh * DH;
        const float* wkv = Wkv + (long)l * Dd * 2 * Hh * DH;
        const float* wp  = Wp  + (long)l * DH * Rr;
        const float* wo  = Wo  + (long)l * Hh * DH * Dd;
        const float* w1  = W1  + (long)l * Dd * FF;
        const float* w2  = W2  + (long)l * FF * Dd;

        // y = LN1(h) -> planes
        ln512p<<<MBN, 256>>>(ph, ln1_g + l * Dd, ln1_b + l * Dd, yAh, yAl);

        // q = y @ Wq * SCALE -> qA planes
        split_t<<<dim3(16, 16, 1), 256>>>(wq, wBh, wBl, 512, 512, 0, 0);
        gemm(yAh, yAl, 512, wBh, wBl, 512, nullptr, nullptr, qAh, qAl, 512,
             MBN, 512, 512, 1, 1, 1, 0,0,0, 0,0,0, 0,0,0, SCALE, 0);

        // kv = y @ Wkv -> float + kvA planes
        split_t<<<dim3(16, 32, 1), 256>>>(wkv, wBh, wBl, 512, 1024, 0, 0);
        gemm(yAh, yAl, 512, wBh, wBl, 512, nullptr, pkv, kvAh, kvAl, 1024,
             MBN, 1024, 512, 1, 1, 1, 0,0,0, 0,0,0, 0,0,0, 1.f, F_WANTC);

        // p = k @ Wp per (b,h) -> float (raw scores)
        split_t<<<dim3(2, 8, 1), 256>>>(wp, wBh, wBl, 64, 256, 0, 0);
        gemm(kvAh, kvAl, 1024, wBh, wBl, 64, nullptr, pp, nullptr, nullptr, Rr,
             Nn, Rr, DH, Bb, Hh, 1,
             (long)Nn * 1024, 64, 0,
             0, 0, 0,
             (long)Hh * Nn * Rr, (long)Nn * Rr, 0,
             1.f, F_WANTC);

        // softmax stats (M, 1/S per (bh,r))
        softmax_stats<<<Bb * Hh * (Rr / 64), 256>>>(pp, ppM, ppI);

        // pT planes with fused exp/normalize
        split_t_sm<<<dim3(128, 8, 32), 256>>>(pp, ppM, ppI, pTh, pTl,
                                              Nn, Rr, (long)Nn * Rr, (long)Nn * Rr);
        // kvT planes
        split_t<<<dim3(128, 32, 4), 256>>>(pkv, kvTh, kvTl, Nn, 1024, (long)Nn * 1024, (long)Nn * 1024);

        // gk|gv = p^T @ {k,v} per (b,h,kv), split-K x4 -> partials -> reduce
        gemm(pTh, pTl, Nn, kvTh, kvTl, Nn, nullptr, pgkp, nullptr, nullptr, DH,
             Rr, DH, 1024, Bb, Hh, 2,
             (long)Hh * Rr * Nn, (long)Rr * Nn, 0,
             (long)1024 * Nn, (long)64 * Nn, (long)512 * Nn,
             (long)Hh * Rr * DH, (long)Rr * DH, GKV,
             1.f, F_WANTC, 4, 2 * GKV);
        seg_reduce<<<(int)((2 * GKV + 255) / 256), 256>>>(pgkp, pgkv, 2 * GKV, 4, 2 * GKV);

        // gkn planes; gvn float -> transpose planes
        ln64<<<(Bb * Hh * Rr) / 4, 128>>>(pgkv, gln_g + l * DH, gln_b + l * DH,
                                          nullptr, gknh, gknl, 1, Bb * Hh * Rr, 0, 0, DH);
        ln64<<<(Bb * Hh * Rr) / 4, 128>>>(pgkv + GKV, gln_g + l * DH, gln_b + l * DH,
                                          pgvn, nullptr, nullptr, 1, Bb * Hh * Rr, 0, 0, DH);
        split_t<<<dim3(8, 2, 32), 256>>>(pgvn, gvTh, gvTl, Rr, DH, (long)Rr * DH, (long)Rr * DH);

        // lk planes; lv float -> transpose planes
        ln64<<<(Bb * Hh * Nn) / 4, 128>>>(pkv, lln_g + l * DH, lln_b + l * DH,
                                          nullptr, lkh, lkl,
                                          Hh, Nn, (long)Nn * 1024, DH, 1024);
        ln64<<<(Bb * Hh * Nn) / 4, 128>>>(pkv + Hh * DH, lln_g + l * DH, lln_b + l * DH,
                                          plv, nullptr, nullptr,
                                          Hh, Nn, (long)Nn * 1024, DH, 1024);
        split_t<<<dim3(128, 2, 32), 256>>>(plv, lvTh, lvTl, Nn, DH, (long)Nn * DH, (long)Nn * DH);

        // sim_l per (b,h,w)
        gemm(qAh, qAl, 512, lkh, lkl, 64, nullptr, psim, nullptr, nullptr, WS + Rr,
             WS, WS, DH, Bb, Hh, NW,
             (long)Nn * 512, 64, (long)WS * 512,
             (long)Hh * Nn * 64, (long)Nn * 64, (long)WS * 64,
             (long)Hh * Nn * (WS + Rr), (long)Nn * (WS + Rr), (long)WS * (WS + Rr),
             1.f, F_WANTC);

        // sim_g per (b,h)
        gemm(qAh, qAl, 512, gknh, gknl, 64, nullptr, psim + WS, nullptr, nullptr, WS + Rr,
             Nn, Rr, DH, Bb, Hh, 1,
             (long)Nn * 512, 64, 0,
             (long)Hh * Rr * 64, (long)Rr * 64, 0,
             (long)Hh * Nn * (WS + Rr), (long)Nn * (WS + Rr), 0,
             1.f, F_WANTC);

        // softmax -> simA planes
        softmax_row384<<<Bb * Hh * Nn, 128>>>(psim, simh, siml);

        // o = a_l @ lv per (b,h,w)  (N=64 path)
        gemm(simh, siml, WS + Rr, lvTh, lvTl, Nn, nullptr, po, nullptr, nullptr, 512,
             WS, DH, WS, Bb, Hh, NW,
             (long)Hh * Nn * (WS + Rr), (long)Nn * (WS + Rr), (long)WS * (WS + Rr),
             (long)Hh * DH * Nn, (long)DH * Nn, WS,
             (long)Nn * 512, 64, (long)WS * 512,
             1.f, F_WANTC);

        // o += a_g @ gvn per (b,h) -> poA planes  (N=64 path)
        gemm(simh + WS, siml + WS, WS + Rr, gvTh, gvTl, Rr, nullptr, po, poAh, poAl, 512,
             Nn, DH, Rr, Bb, Hh, 1,
             (long)Hh * Nn * (WS + Rr), (long)Nn * (WS + Rr), 0,
             (long)Hh * DH * Rr, (long)DH * Rr, 0,
             (long)Nn * 512, 64, 0,
             1.f, F_ACC);

        // h += o @ Wo + bo
        split_t<<<dim3(16, 16, 1), 256>>>(wo, wBh, wBl, 512, 512, 0, 0);
        gemm(poAh, poAl, 512, wBh, wBl, 512, bo + l * Dd, ph, nullptr, nullptr, 512,
             MBN, 512, 512, 1, 1, 1, 0,0,0, 0,0,0, 0,0,0, 1.f, F_ACC | F_WANTC);

        // y = LN2(h) -> planes
        ln512p<<<MBN, 256>>>(ph, ln2_g + l * Dd, ln2_b + l * Dd, yAh, yAl);

        // f1 = gelu(y @ W1 + b1) -> f1A planes
        split_t<<<dim3(16, 64, 1), 256>>>(w1, wBh, wBl, 512, 2048, 0, 0);
        gemm(yAh, yAl, 512, wBh, wBl, 512, b1 + (long)l * FF, nullptr, f1h, f1l, 2048,
             MBN, 2048, 512, 1, 1, 1, 0,0,0, 0,0,0, 0,0,0, 1.f, F_GELU);

        // h += f1 @ W2 + b2
        split_t<<<dim3(64, 16, 1), 256>>>(w2, wBh, wBl, 2048, 512, 0, 0);
        gemm(f1h, f1l, 2048, wBh, wBl, 2048, b2 + l * Dd, ph, nullptr, nullptr, 512,
             MBN, 512, 2048, 1, 1, 1, 0,0,0, 0,0,0, 0,0,0, 1.f, F_ACC | F_WANTC);
    }

    // final LN + vocab projection
    ln512p<<<MBN, 256>>>(ph, lnf_g, lnf_b, yAh, yAl);
    split_t<<<dim3(16, 16, 1), 256>>>(Wlog, wBh, wBl, 512, 512, 0, 0);
    gemm(yAh, yAl, 512, wBh, wBl, 512, blog, plog, nullptr, nullptr, 512,
         MBN, 512, 512, 1, 1, 1, 0,0,0, 0,0,0, 0,0,0, 1.f, F_WANTC);

    // head
    {
        dim3 grid(NCHUNK, Bb);
        head_partial<<<grid, 256>>>(plog, Wfin, ppart);
        head_reduce<<<1, 64>>>(ppart, bfin, out);
    }
}

// round 11
// speedup vs baseline: 3.4690x; 1.0042x over previous
#include <cuda_runtime.h>
#include <cuda_bf16.h>
#include <math.h>
#include <stdint.h>

typedef unsigned short u16;

// Problem constants
#define Bb   4
#define Nn   4096
#define Vv   512
#define Dd   512
#define Hh   8
#define DH   64
#define Ll   4
#define WS   128
#define Rr   256
#define Cc   10
#define FF   2048
#define NW   (Nn / WS)
#define SCALE 0.125f
#define KFIN ((long)Nn * Vv)
#define NCHUNK 2048

// flags
#define F_ACC   1
#define F_GELU  2
#define F_WANTC 4

// ---------------- scratch (device globals; no allocation) ----------------
__device__ float g_h   [(size_t)Bb * Nn * Dd];
__device__ float g_kv  [(size_t)Bb * Nn * 2 * Hh * DH];
__device__ float g_p   [(size_t)Bb * Hh * Nn * Rr];
__device__ float g_gkv [(size_t)2 * Bb * Hh * Rr * DH];
__device__ float g_gkp [(size_t)4 * 2 * Bb * Hh * Rr * DH];
__device__ float g_gvn [(size_t)Bb * Hh * Rr * DH];
__device__ float g_lv  [(size_t)Bb * Hh * Nn * DH];
__device__ float g_sim [(size_t)Bb * Hh * Nn * (WS + Rr)];
__device__ float g_o   [(size_t)Bb * Nn * Hh * DH];
__device__ float g_log [(size_t)Bb * Nn * Vv];
__device__ float g_part[(size_t)Bb * NCHUNK * Cc];
__device__ float g_pM  [Bb * Hh * Rr];
__device__ float g_pI  [Bb * Hh * Rr];

// bf16 hi/lo planes
__device__ u16 g_yAhi [8388608],  g_yAlo [8388608];
__device__ u16 g_qAhi [8388608],  g_qAlo [8388608];
__device__ u16 g_kvAhi[16777216], g_kvAlo[16777216];
__device__ u16 g_kvThi[16777216], g_kvTlo[16777216];
__device__ u16 g_pThi [33554432], g_pTlo [33554432];
__device__ u16 g_lkhi [8388608],  g_lklo [8388608];
__device__ u16 g_gknhi[524288],   g_gknlo[524288];
__device__ u16 g_lvThi[8388608],  g_lvTlo[8388608];
__device__ u16 g_gvThi[524288],   g_gvTlo[524288];
__device__ u16 g_simhi[50331648], g_simlo[50331648];
__device__ u16 g_poAhi[8388608],  g_poAlo[8388608];
__device__ u16 g_f1Ahi[33554432], g_f1Alo[33554432];
__device__ u16 g_wBhi [1048576],  g_wBlo [1048576];

// ---------------- helpers ----------------
__device__ __forceinline__ float gelu_f(float x) {
    const float k0 = 0.7978845608028654f, k1 = 0.044715f;
    return 0.5f * x * (1.f + tanhf(k0 * (x + k1 * x * x * x)));
}
__device__ __forceinline__ uint32_t smem_u32(const void* p) {
    uint32_t a;
    asm("{ .reg .u64 t; cvta.to.shared.u64 t, %1; cvt.u32.u64 %0, t; }" : "=r"(a) : "l"(p));
    return a;
}
__device__ __forceinline__ void split_bf16(float v, u16& hi, u16& lo) {
    __nv_bfloat16 h = __float2bfloat16_rn(v);
    float rem = v - __bfloat162float(h);
    __nv_bfloat16 l = __float2bfloat16_rn(rem);
    hi = __bfloat16_as_ushort(h);
    lo = __bfloat16_as_ushort(l);
}

#define LDMATRIX_X4(r0, r1, r2, r3, addr) \
    asm volatile("ldmatrix.sync.aligned.m8n8.x4.shared.b16 {%0,%1,%2,%3}, [%4];" \
        : "=r"(r0), "=r"(r1), "=r"(r2), "=r"(r3) : "r"(addr))

#define MMA_BF16(c, a, b0v, b1v) \
    asm volatile("mma.sync.aligned.m16n8k16.row.col.f32.bf16.bf16.f32 " \
        "{%0,%1,%2,%3}, {%4,%5,%6,%7}, {%8,%9}, {%0,%1,%2,%3};" \
        : "+f"((c)[0]), "+f"((c)[1]), "+f"((c)[2]), "+f"((c)[3]) \
        : "r"((a)[0]), "r"((a)[1]), "r"((a)[2]), "r"((a)[3]), "r"(b0v), "r"(b1v))

#define CP16(dst, src, sz) \
    asm volatile("cp.async.cg.shared.global [%0], [%1], 16, %2;" \
        :: "r"(dst), "l"(src), "r"(sz))
#define CP_COMMIT() asm volatile("cp.async.commit_group;")
#define CP_WAIT(n)  asm volatile("cp.async.wait_group %0;" :: "n"(n))

// ---------------- GEMM on pre-split bf16 planes ----------------
#define PADK 40
#define PLANE_B 10240           // 128*PADK*2
#define BUF_B   (4 * PLANE_B)   // 40960
#define TC_SMEM (2 * BUF_B)     // 81920

template<bool N64>
__global__ __launch_bounds__(256, 2) void tc_gemm(
    const u16* __restrict__ Ahi, const u16* __restrict__ Alo,
    const u16* __restrict__ Bhi, const u16* __restrict__ Blo,
    const float* __restrict__ bias, float* __restrict__ C,
    u16* __restrict__ Chi, u16* __restrict__ Clo,
    int M, int N, int K, int lda, int ldb, long sCm,
    int D1, int D2,
    long a0, long a1, long a2,
    long b0, long b1, long b2,
    long c0, long c1, long c2,
    float alpha, int flags, int ksplit, long cSeg)
{
    extern __shared__ __align__(16) char smem[];
    uint32_t sb = smem_u32(smem);

    int z = blockIdx.z;
    int seg = 0;
    if (ksplit > 1) { seg = z % ksplit; z /= ksplit; }
    int d2 = z % D2;
    int t  = z / D2;
    int d1 = t % D1;
    int d0 = t / D1;
    long aOff = (long)d0 * a0 + (long)d1 * a1 + (long)d2 * a2;
    long bOff = (long)d0 * b0 + (long)d1 * b1 + (long)d2 * b2;
    long cOff = (long)d0 * c0 + (long)d1 * c1 + (long)d2 * c2 + (long)seg * cSeg;
    int kBase = seg * K;

    int tid  = threadIdx.x;
    int lane = tid & 31;
    int wid  = tid >> 5;
    constexpr int MF = N64 ? 2 : 4;
    constexpr int MSTEP = N64 ? 32 : 64;
    constexpr int NBV = N64 ? 1 : 2;
    int wm = N64 ? (wid & 3) : (wid & 1);
    int wn = N64 ? (wid >> 2) : (wid >> 1);
    int mBase = blockIdx.y * 128;
    int nBase = blockIdx.x * (N64 ? 64 : 128);

    const int nChunks = K >> 5;     // always even (K multiple of 64)

    // ---- per-thread induction load descriptors ----
    const u16 *pAh[2], *pAl[2], *pBh[NBV], *pBl[NBV];
    uint32_t dA[2], dB[NBV];
    int okB[NBV];
#pragma unroll
    for (int v = 0; v < 2; v++) {
        int vec = tid + v * 256;
        int row = vec >> 2, kq = (vec & 3) << 3;
        dA[v] = (uint32_t)(row * PADK + kq) * 2;
        long off = aOff + (long)(mBase + row) * lda + kBase + kq;
        pAh[v] = Ahi + off;
        pAl[v] = Alo + off;
    }
#pragma unroll
    for (int v = 0; v < NBV; v++) {
        int vec = tid + v * 256;
        int row = vec >> 2, kq = (vec & 3) << 3;
        dB[v] = (uint32_t)(row * PADK + kq) * 2;
        okB[v] = (nBase + row < N) ? 16 : 0;
        int brow = (nBase + row < N) ? row : 0;
        long off = bOff + (long)(nBase + brow) * ldb + kBase + kq;
        pBh[v] = Bhi + off;
        pBl[v] = Blo + off;
    }

#define LOAD_TILES(BASE) do {                                   \
    _Pragma("unroll")                                           \
    for (int v = 0; v < 2; v++) {                               \
        CP16((BASE) + dA[v],           pAh[v], 16);             \
        CP16((BASE) + PLANE_B + dA[v], pAl[v], 16);             \
        pAh[v] += 32; pAl[v] += 32;                             \
    }                                                           \
    _Pragma("unroll")                                           \
    for (int v = 0; v < NBV; v++) {                             \
        CP16((BASE) + 2 * PLANE_B + dB[v], pBh[v], okB[v]);     \
        CP16((BASE) + 3 * PLANE_B + dB[v], pBl[v], okB[v]);     \
        pBh[v] += 32; pBl[v] += 32;                             \
    }                                                           \
    CP_COMMIT();                                                \
} while (0)

    float acc[MF][4][4];
#pragma unroll
    for (int i = 0; i < MF; i++)
#pragma unroll
        for (int j = 0; j < 4; j++)
#pragma unroll
            for (int e = 0; e < 4; e++) acc[i][j][e] = 0.f;

    int lrow = lane & 15;
    int lcol = (lane >> 4) * 8;

    auto compute = [&](uint32_t cbase) {
#pragma unroll
        for (int kk = 0; kk < 2; kk++) {
            int kc = kk * 16 + lcol;
            uint32_t afh[MF][4], afl[MF][4], bh[2][4], bl[2][4];
#pragma unroll
            for (int mf = 0; mf < MF; mf++) {
                uint32_t ao = cbase + (uint32_t)((wm * MSTEP + mf * 16 + lrow) * PADK + kc) * 2;
                LDMATRIX_X4(afh[mf][0], afh[mf][1], afh[mf][2], afh[mf][3], ao);
                LDMATRIX_X4(afl[mf][0], afl[mf][1], afl[mf][2], afl[mf][3], ao + PLANE_B);
            }
#pragma unroll
            for (int g = 0; g < 2; g++) {
                uint32_t bo = cbase + 2 * PLANE_B
                            + (uint32_t)((wn * 32 + g * 16 + lrow) * PADK + kc) * 2;
                LDMATRIX_X4(bh[g][0], bh[g][1], bh[g][2], bh[g][3], bo);
            }
#pragma unroll
            for (int mf = 0; mf < MF; mf++)
#pragma unroll
                for (int nf = 0; nf < 4; nf++) {
                    int g = nf >> 1, o = nf & 1;
                    MMA_BF16(acc[mf][nf], afh[mf], bh[g][o], bh[g][o + 2]);
                }
#pragma unroll
            for (int mf = 0; mf < MF; mf++)
#pragma unroll
                for (int nf = 0; nf < 4; nf++) {
                    int g = nf >> 1, o = nf & 1;
                    MMA_BF16(acc[mf][nf], afl[mf], bh[g][o], bh[g][o + 2]);
                }
#pragma unroll
            for (int g = 0; g < 2; g++) {
                uint32_t bo = cbase + 3 * PLANE_B
                            + (uint32_t)((wn * 32 + g * 16 + lrow) * PADK + kc) * 2;
                LDMATRIX_X4(bl[g][0], bl[g][1], bl[g][2], bl[g][3], bo);
            }
#pragma unroll
            for (int mf = 0; mf < MF; mf++)
#pragma unroll
                for (int nf = 0; nf < 4; nf++) {
                    int g = nf >> 1, o = nf & 1;
                    MMA_BF16(acc[mf][nf], afh[mf], bl[g][o], bl[g][o + 2]);
                }
        }
    };

    // prologue: chunk 0 -> buf0
    LOAD_TILES(sb);

    for (int ch = 0; ch < nChunks; ch += 2) {
        // chunk ch+1 -> buf1 (nChunks even, so ch+1 < nChunks always)
        LOAD_TILES(sb + BUF_B);
        CP_WAIT(1);
        __syncthreads();
        compute(sb);
        __syncthreads();
        if (ch + 2 < nChunks) {
            LOAD_TILES(sb);
            CP_WAIT(1);
        } else {
            CP_WAIT(0);
        }
        __syncthreads();
        compute(sb + BUF_B);
        __syncthreads();
    }
#undef LOAD_TILES

    // epilogue
    int grp = lane >> 2, ct = lane & 3;
#pragma unroll
    for (int mf = 0; mf < MF; mf++) {
#pragma unroll
        for (int nf = 0; nf < 4; nf++) {
            int gr = mBase + wm * MSTEP + mf * 16 + grp;
            int gc = nBase + wn * 32 + nf * 8 + ct * 2;
#pragma unroll
            for (int e = 0; e < 4; e++) {
                int r = gr + ((e >> 1) ? 8 : 0);
                int c = gc + (e & 1);
                if (c < N) {
                    float v = alpha * acc[mf][nf][e];
                    if (bias) v += bias[c];
                    if (flags & F_GELU) v = gelu_f(v);
                    long off = cOff + (long)r * sCm + c;
                    if (flags & F_ACC) v += C[off];
                    if (flags & F_WANTC) C[off] = v;
                    if (Chi) {
                        u16 hh, ll;
                        split_bf16(v, hh, ll);
                        Chi[off] = hh; Clo[off] = ll;
                    }
                }
            }
        }
    }
}

// ---------------- split-K partial reduce (fixed order, deterministic) ----------------
__global__ __launch_bounds__(256) void seg_reduce(
    const float* __restrict__ part, float* __restrict__ out,
    long n, int segs, long segStride)
{
    long i = (long)blockIdx.x * 256 + threadIdx.x;
    if (i < n) {
        float s = 0.f;
        for (int j = 0; j < segs; j++) s += part[(long)j * segStride + i];
        out[i] = s;
    }
}

// ---------------- split-transpose: out[n][k] = in[k][n] ----------------
__global__ __launch_bounds__(256) void split_t(
    const float* __restrict__ in, u16* __restrict__ hi, u16* __restrict__ lo,
    int inRows, int inCols, long inBatch, long outBatch)
{
    __shared__ float tbuf[32][33];
    int z = blockIdx.z;
    const float* src = in + (long)z * inBatch;
    int kb = blockIdx.x * 32;
    int nb = blockIdx.y * 32;
    int tx = threadIdx.x & 31, ty = threadIdx.x >> 5;
#pragma unroll
    for (int j = 0; j < 4; j++) {
        int r = ty + j * 8;
        tbuf[r][tx] = src[(long)(kb + r) * inCols + nb + tx];
    }
    __syncthreads();
    u16* h = hi + (long)z * outBatch;
    u16* l = lo + (long)z * outBatch;
#pragma unroll
    for (int j = 0; j < 4; j++) {
        int r = ty + j * 8;
        float v = tbuf[tx][r];
        u16 hh, ll;
        split_bf16(v, hh, ll);
        long o = (long)(nb + r) * inRows + kb + tx;
        h[o] = hh; l[o] = ll;
    }
}

// ---- p transpose with fused softmax normalize: out = exp(v - M[col]) * I[col] ----
__global__ __launch_bounds__(256) void split_t_sm(
    const float* __restrict__ in, const float* __restrict__ stM,
    const float* __restrict__ stI,
    u16* __restrict__ hi, u16* __restrict__ lo,
    int inRows, int inCols, long inBatch, long outBatch)
{
    __shared__ float tbuf[32][33];
    int z = blockIdx.z;
    const float* src = in + (long)z * inBatch;
    int kb = blockIdx.x * 32;
    int nb = blockIdx.y * 32;
    int tx = threadIdx.x & 31, ty = threadIdx.x >> 5;
#pragma unroll
    for (int j = 0; j < 4; j++) {
        int r = ty + j * 8;
        tbuf[r][tx] = src[(long)(kb + r) * inCols + nb + tx];
    }
    __syncthreads();
    u16* h = hi + (long)z * outBatch;
    u16* l = lo + (long)z * outBatch;
#pragma unroll
    for (int j = 0; j < 4; j++) {
        int r = ty + j * 8;
        int col = nb + r;
        float M = stM[(long)z * inCols + col];
        float I = stI[(long)z * inCols + col];
        float v = __expf(tbuf[tx][r] - M) * I;
        u16 hh, ll;
        split_bf16(v, hh, ll);
        long o = (long)col * inRows + kb + tx;
        h[o] = hh; l[o] = ll;
    }
}

// ---------------- LayerNorm D=512 -> planes ----------------
__global__ __launch_bounds__(256) void ln512p(
    const float* __restrict__ in, const float* __restrict__ g,
    const float* __restrict__ b, u16* __restrict__ oHi, u16* __restrict__ oLo)
{
    long row = blockIdx.x;
    const float* x = in + row * Dd;
    int tid = threadIdx.x;
    float v0 = x[tid], v1 = x[tid + 256];
    __shared__ float red[256];
    red[tid] = v0 + v1;
    __syncthreads();
    for (int s = 128; s > 0; s >>= 1) { if (tid < s) red[tid] += red[tid + s]; __syncthreads(); }
    float mu = red[0] * (1.f / Dd);
    __syncthreads();
    float d0 = v0 - mu, d1 = v1 - mu;
    red[tid] = d0 * d0 + d1 * d1;
    __syncthreads();
    for (int s = 128; s > 0; s >>= 1) { if (tid < s) red[tid] += red[tid + s]; __syncthreads(); }
    float rs = rsqrtf(red[0] * (1.f / Dd) + 1e-5f);
    float r0 = d0 * rs * g[tid] + b[tid];
    float r1 = d1 * rs * g[tid + 256] + b[tid + 256];
    u16 h0, l0, h1, l1;
    split_bf16(r0, h0, l0);
    split_bf16(r1, h1, l1);
    long o = row * Dd;
    oHi[o + tid] = h0;       oLo[o + tid] = l0;
    oHi[o + tid + 256] = h1; oLo[o + tid + 256] = l1;
}

// ---------------- LayerNorm D=64, warp/row ----------------
__global__ __launch_bounds__(128) void ln64(
    const float* __restrict__ in, const float* __restrict__ g,
    const float* __restrict__ b, float* __restrict__ outF,
    u16* __restrict__ oHi, u16* __restrict__ oLo,
    int D1, int D2, long s0, long s1, long s2)
{
    long warp = ((long)blockIdx.x * blockDim.x + threadIdx.x) >> 5;
    int lane = threadIdx.x & 31;
    long d2 = warp % D2;
    long t  = warp / D2;
    long d1 = t % D1;
    long d0 = t / D1;
    const float* x = in + d0 * s0 + d1 * s1 + d2 * s2;
    float v0 = x[lane], v1 = x[lane + 32];
    float s = v0 + v1;
#pragma unroll
    for (int o = 16; o; o >>= 1) s += __shfl_xor_sync(0xffffffffu, s, o);
    float mu = s * (1.f / 64.f);
    float q0 = v0 - mu, q1 = v1 - mu;
    float q = q0 * q0 + q1 * q1;
#pragma unroll
    for (int o = 16; o; o >>= 1) q += __shfl_xor_sync(0xffffffffu, q, o);
    float rs = rsqrtf(q * (1.f / 64.f) + 1e-5f);
    float r0 = q0 * rs * g[lane] + b[lane];
    float r1 = q1 * rs * g[lane + 32] + b[lane + 32];
    long o = warp * 64;
    if (outF) { outF[o + lane] = r0; outF[o + lane + 32] = r1; }
    if (oHi) {
        u16 h0, l0, h1, l1;
        split_bf16(r0, h0, l0);
        split_bf16(r1, h1, l1);
        oHi[o + lane] = h0;      oLo[o + lane] = l0;
        oHi[o + lane + 32] = h1; oLo[o + lane + 32] = l1;
    }
}

// ---------------- embedding ----------------
__global__ void embed(const int* __restrict__ x, const float* __restrict__ tok,
                      const float* __restrict__ pos, float* __restrict__ h)
{
    long i = (long)blockIdx.x * blockDim.x + threadIdx.x;
    if (i >= (long)Bb * Nn * Dd) return;
    int d = i % Dd;
    long bn = i / Dd;
    int n = bn % Nn;
    int tokid = x[bn];
    h[i] = tok[(long)tokid * Dd + d] + pos[(long)n * Dd + d];
}

// ------- softmax stats over axis=2 (n) of p (BH, N, R): writes M and 1/S -------
__global__ __launch_bounds__(256) void softmax_stats(
    const float* __restrict__ p, float* __restrict__ stM, float* __restrict__ stI)
{
    int blk = blockIdx.x;
    int rb  = blk % (Rr / 64);
    int bh  = blk / (Rr / 64);
    int c   = threadIdx.x % 64;
    int stripe = threadIdx.x / 64;
    const float* base = p + (long)bh * Nn * Rr + rb * 64 + c;
    const int CH = Nn / 4;
    int n0 = stripe * CH;

    float m = -1e30f, s = 0.f;
    for (int n = n0; n < n0 + CH; n++) {
        float v = base[(long)n * Rr];
        float nm = fmaxf(m, v);
        s = s * __expf(m - nm) + __expf(v - nm);
        m = nm;
    }
    __shared__ float sm[4][64], ss[4][64];
    sm[stripe][c] = m; ss[stripe][c] = s;
    __syncthreads();
    if (stripe == 0) {
        float M = -1e30f;
#pragma unroll
        for (int j = 0; j < 4; j++) M = fmaxf(M, sm[j][c]);
        float S = 0.f;
#pragma unroll
        for (int j = 0; j < 4; j++) S += ss[j][c] * __expf(sm[j][c] - M);
        stM[(long)bh * Rr + rb * 64 + c] = M;
        stI[(long)bh * Rr + rb * 64 + c] = 1.f / S;
    }
}

// ---------------- softmax over 384-wide rows -> planes ----------------
__global__ __launch_bounds__(128) void softmax_row384(
    const float* __restrict__ s, u16* __restrict__ oHi, u16* __restrict__ oLo)
{
    const float* r = s + (long)blockIdx.x * (WS + Rr);
    int tid = threadIdx.x;
    float v0 = r[tid], v1 = r[tid + 128], v2 = r[tid + 256];
    __shared__ float red[128];
    red[tid] = fmaxf(v0, fmaxf(v1, v2));
    __syncthreads();
    for (int st = 64; st > 0; st >>= 1) { if (tid < st) red[tid] = fmaxf(red[tid], red[tid + st]); __syncthreads(); }
    float m = red[0];
    __syncthreads();
    float e0 = __expf(v0 - m), e1 = __expf(v1 - m), e2 = __expf(v2 - m);
    red[tid] = e0 + e1 + e2;
    __syncthreads();
    for (int st = 64; st > 0; st >>= 1) { if (tid < st) red[tid] += red[tid + st]; __syncthreads(); }
    float inv = 1.f / red[0];
    long o = (long)blockIdx.x * (WS + Rr);
    u16 h, l;
    split_bf16(e0 * inv, h, l); oHi[o + tid] = h;       oLo[o + tid] = l;
    split_bf16(e1 * inv, h, l); oHi[o + tid + 128] = h; oLo[o + tid + 128] = l;
    split_bf16(e2 * inv, h, l); oHi[o + tid + 256] = h; oLo[o + tid + 256] = l;
}

// ---------------- final head ----------------
__global__ __launch_bounds__(256) void head_partial(
    const float* __restrict__ logits, const float* __restrict__ Wfin,
    float* __restrict__ part)
{
    int b = blockIdx.y;
    long k0 = (long)blockIdx.x * 1024;
    const float* lrow = logits + (long)b * KFIN;
    float acc[Cc];
#pragma unroll
    for (int c = 0; c < Cc; c++) acc[c] = 0.f;
    for (int i = threadIdx.x; i < 1024; i += 256) {
        long k = k0 + i;
        float l = lrow[k];
        const float* w = Wfin + k * Cc;
#pragma unroll
        for (int c = 0; c < Cc; c++) acc[c] = fmaf(l, w[c], acc[c]);
    }
#pragma unroll
    for (int c = 0; c < Cc; c++)
#pragma unroll
        for (int o = 16; o; o >>= 1) acc[c] += __shfl_xor_sync(0xffffffffu, acc[c], o);
    __shared__ float sm[8][Cc];
    int warp = threadIdx.x >> 5, lane = threadIdx.x & 31;
    if (lane == 0)
#pragma unroll
        for (int c = 0; c < Cc; c++) sm[warp][c] = acc[c];
    __syncthreads();
    if (threadIdx.x < Cc) {
        float s = 0.f;
#pragma unroll
        for (int w = 0; w < 8; w++) s += sm[w][threadIdx.x];
        part[((long)b * NCHUNK + blockIdx.x) * Cc + threadIdx.x] = s;
    }
}

__global__ void head_reduce(const float* __restrict__ part,
                            const float* __restrict__ bfin, float* __restrict__ out)
{
    int t = threadIdx.x;
    if (t < Bb * Cc) {
        int b = t / Cc, c = t % Cc;
        float s = bfin[c];
        for (int j = 0; j < NCHUNK; j++) s += part[((long)b * NCHUNK + j) * Cc + c];
        out[b * Cc + c] = s;
    }
}

// ---------------- host ----------------
static void gemm(const u16* Ahi, const u16* Alo, int lda,
                 const u16* Bhi, const u16* Blo, int ldb,
                 const float* bias, float* C, u16* Chi, u16* Clo, long sCm,
                 int M, int N, int K,
                 int D0, int D1, int D2,
                 long a0, long a1, long a2,
                 long b0, long b1, long b2,
                 long c0, long c1, long c2,
                 float alpha, int flags, int ksplit = 1, long cSeg = 0)
{
    if (N == 64) {
        dim3 grid(1, M / 128, D0 * D1 * D2 * ksplit);
        tc_gemm<true><<<grid, 256, TC_SMEM>>>(Ahi, Alo, Bhi, Blo, bias, C, Chi, Clo,
            M, N, K, lda, ldb, sCm, D1, D2,
            a0, a1, a2, b0, b1, b2, c0, c1, c2, alpha, flags, ksplit, cSeg);
    } else {
        dim3 grid((N + 127) / 128, M / 128, D0 * D1 * D2 * ksplit);
        tc_gemm<false><<<grid, 256, TC_SMEM>>>(Ahi, Alo, Bhi, Blo, bias, C, Chi, Clo,
            M, N, K, lda, ldb, sCm, D1, D2,
            a0, a1, a2, b0, b1, b2, c0, c1, c2, alpha, flags, ksplit, cSeg);
    }
}

#define SYM(p, s) cudaGetSymbolAddress((void**)&p, s)

extern "C" void kernel_launch(void* const* d_in, const int* in_sizes, int n_in,
                              void* d_out, int out_size)
{
    const int*   x_in    = (const int*)  d_in[0];
    const float* tok_emb = (const float*)d_in[1];
    const float* pos_emb = (const float*)d_in[2];
    const float* ln1_g   = (const float*)d_in[3];
    const float* ln1_b   = (const float*)d_in[4];
    const float* Wq      = (const float*)d_in[5];
    const float* Wkv     = (const float*)d_in[6];
    const float* Wp      = (const float*)d_in[7];
    const float* lln_g   = (const float*)d_in[8];
    const float* lln_b   = (const float*)d_in[9];
    const float* gln_g   = (const float*)d_in[10];
    const float* gln_b   = (const float*)d_in[11];
    const float* Wo      = (const float*)d_in[12];
    const float* bo      = (const float*)d_in[13];
    const float* ln2_g   = (const float*)d_in[14];
    const float* ln2_b   = (const float*)d_in[15];
    const float* W1      = (const float*)d_in[16];
    const float* b1      = (const float*)d_in[17];
    const float* W2      = (const float*)d_in[18];
    const float* b2      = (const float*)d_in[19];
    const float* lnf_g   = (const float*)d_in[20];
    const float* lnf_b   = (const float*)d_in[21];
    const float* Wlog    = (const float*)d_in[22];
    const float* blog    = (const float*)d_in[23];
    const float* Wfin    = (const float*)d_in[24];
    const float* bfin    = (const float*)d_in[25];
    float* out = (float*)d_out;

    cudaFuncSetAttribute(tc_gemm<false>, cudaFuncAttributeMaxDynamicSharedMemorySize, TC_SMEM);
    cudaFuncSetAttribute(tc_gemm<true>,  cudaFuncAttributeMaxDynamicSharedMemorySize, TC_SMEM);

    float *ph, *pkv, *pp, *pgkv, *pgkp, *pgvn, *plv, *psim, *po, *plog, *ppart, *ppM, *ppI;
    SYM(ph, g_h); SYM(pkv, g_kv); SYM(pp, g_p); SYM(pgkv, g_gkv); SYM(pgkp, g_gkp);
    SYM(pgvn, g_gvn); SYM(plv, g_lv); SYM(psim, g_sim); SYM(po, g_o);
    SYM(plog, g_log); SYM(ppart, g_part); SYM(ppM, g_pM); SYM(ppI, g_pI);

    u16 *yAh,*yAl,*qAh,*qAl,*kvAh,*kvAl,*kvTh,*kvTl,*pTh,*pTl,*lkh,*lkl,
        *gknh,*gknl,*lvTh,*lvTl,*gvTh,*gvTl,*simh,*siml,*poAh,*poAl,
        *f1h,*f1l,*wBh,*wBl;
    SYM(yAh, g_yAhi);  SYM(yAl, g_yAlo);
    SYM(qAh, g_qAhi);  SYM(qAl, g_qAlo);
    SYM(kvAh, g_kvAhi); SYM(kvAl, g_kvAlo);
    SYM(kvTh, g_kvThi); SYM(kvTl, g_kvTlo);
    SYM(pTh, g_pThi);  SYM(pTl, g_pTlo);
    SYM(lkh, g_lkhi);  SYM(lkl, g_lklo);
    SYM(gknh, g_gknhi); SYM(gknl, g_gknlo);
    SYM(lvTh, g_lvThi); SYM(lvTl, g_lvTlo);
    SYM(gvTh, g_gvThi); SYM(gvTl, g_gvTlo);
    SYM(simh, g_simhi); SYM(siml, g_simlo);
    SYM(poAh, g_poAhi); SYM(poAl, g_poAlo);
    SYM(f1h, g_f1Ahi); SYM(f1l, g_f1Alo);
    SYM(wBh, g_wBhi);  SYM(wBl, g_wBlo);

    const long BND = (long)Bb * Nn * Dd;
    const int  MBN = Bb * Nn;
    const long GKV = (long)Bb * Hh * Rr * DH;   // 524288

    embed<<<(BND + 255) / 256, 256>>>(x_in, tok_emb, pos_emb, ph);

    for (int l = 0; l < Ll; l++) {
        const float* wq  = Wq  + (long)l * Dd * Hh * DH;
        const float* wkv = Wkv + (long)l * Dd * 2 * Hh * DH;
        const float* wp  = Wp  + (long)l * DH * Rr;
        const float* wo  = Wo  + (long)l * Hh * DH * Dd;
        const float* w1  = W1  + (long)l * Dd * FF;
        const float* w2  = W2  + (long)l * FF * Dd;

        // y = LN1(h) -> planes
        ln512p<<<MBN, 256>>>(ph, ln1_g + l * Dd, ln1_b + l * Dd, yAh, yAl);

        // q = y @ Wq * SCALE -> qA planes
        split_t<<<dim3(16, 16, 1), 256>>>(wq, wBh, wBl, 512, 512, 0, 0);
        gemm(yAh, yAl, 512, wBh, wBl, 512, nullptr, nullptr, qAh, qAl, 512,
             MBN, 512, 512, 1, 1, 1, 0,0,0, 0,0,0, 0,0,0, SCALE, 0);

        // kv = y @ Wkv -> float + kvA planes
        split_t<<<dim3(16, 32, 1), 256>>>(wkv, wBh, wBl, 512, 1024, 0, 0);
        gemm(yAh, yAl, 512, wBh, wBl, 512, nullptr, pkv, kvAh, kvAl, 1024,
             MBN, 1024, 512, 1, 1, 1, 0,0,0, 0,0,0, 0,0,0, 1.f, F_WANTC);

        // p = k @ Wp per (b,h) -> float (raw scores)
        split_t<<<dim3(2, 8, 1), 256>>>(wp, wBh, wBl, 64, 256, 0, 0);
        gemm(kvAh, kvAl, 1024, wBh, wBl, 64, nullptr, pp, nullptr, nullptr, Rr,
             Nn, Rr, DH, Bb, Hh, 1,
             (long)Nn * 1024, 64, 0,
             0, 0, 0,
             (long)Hh * Nn * Rr, (long)Nn * Rr, 0,
             1.f, F_WANTC);

        // softmax stats (M, 1/S per (bh,r))
        softmax_stats<<<Bb * Hh * (Rr / 64), 256>>>(pp, ppM, ppI);

        // pT planes with fused exp/normalize
        split_t_sm<<<dim3(128, 8, 32), 256>>>(pp, ppM, ppI, pTh, pTl,
                                              Nn, Rr, (long)Nn * Rr, (long)Nn * Rr);
        // kvT planes
        split_t<<<dim3(128, 32, 4), 256>>>(pkv, kvTh, kvTl, Nn, 1024, (long)Nn * 1024, (long)Nn * 1024);

        // gk|gv = p^T @ {k,v} per (b,h,kv), split-K x4 -> partials -> reduce
        gemm(pTh, pTl, Nn, kvTh, kvTl, Nn, nullptr, pgkp, nullptr, nullptr, DH,
             Rr, DH, 1024, Bb, Hh, 2,
             (long)Hh * Rr * Nn, (long)Rr * Nn, 0,
             (long)1024 * Nn, (long)64 * Nn, (long)512 * Nn,
             (long)Hh * Rr * DH, (long)Rr * DH, GKV,
             1.f, F_WANTC, 4, 2 * GKV);
        seg_reduce<<<(int)((2 * GKV + 255) / 256), 256>>>(pgkp, pgkv, 2 * GKV, 4, 2 * GKV);

        // gkn planes; gvn float -> transpose planes
        ln64<<<(Bb * Hh * Rr) / 4, 128>>>(pgkv, gln_g + l * DH, gln_b + l * DH,
                                          nullptr, gknh, gknl, 1, Bb * Hh * Rr, 0, 0, DH);
        ln64<<<(Bb * Hh * Rr) / 4, 128>>>(pgkv + GKV, gln_g + l * DH, gln_b + l * DH,
                                          pgvn, nullptr, nullptr, 1, Bb * Hh * Rr, 0, 0, DH);
        split_t<<<dim3(8, 2, 32), 256>>>(pgvn, gvTh, gvTl, Rr, DH, (long)Rr * DH, (long)Rr * DH);

        // lk planes; lv float -> transpose planes
        ln64<<<(Bb * Hh * Nn) / 4, 128>>>(pkv, lln_g + l * DH, lln_b + l * DH,
                                          nullptr, lkh, lkl,
                                          Hh, Nn, (long)Nn * 1024, DH, 1024);
        ln64<<<(Bb * Hh * Nn) / 4, 128>>>(pkv + Hh * DH, lln_g + l * DH, lln_b + l * DH,
                                          plv, nullptr, nullptr,
                                          Hh, Nn, (long)Nn * 1024, DH, 1024);
        split_t<<<dim3(128, 2, 32), 256>>>(plv, lvTh, lvTl, Nn, DH, (long)Nn * DH, (long)Nn * DH);

        // sim_l per (b,h,w)
        gemm(qAh, qAl, 512, lkh, lkl, 64, nullptr, psim, nullptr, nullptr, WS + Rr,
             WS, WS, DH, Bb, Hh, NW,
             (long)Nn * 512, 64, (long)WS * 512,
             (long)Hh * Nn * 64, (long)Nn * 64, (long)WS * 64,
             (long)Hh * Nn * (WS + Rr), (long)Nn * (WS + Rr), (long)WS * (WS + Rr),
             1.f, F_WANTC);

        // sim_g per (b,h)
        gemm(qAh, qAl, 512, gknh, gknl, 64, nullptr, psim + WS, nullptr, nullptr, WS + Rr,
             Nn, Rr, DH, Bb, Hh, 1,
             (long)Nn * 512, 64, 0,
             (long)Hh * Rr * 64, (long)Rr * 64, 0,
             (long)Hh * Nn * (WS + Rr), (long)Nn * (WS + Rr), 0,
             1.f, F_WANTC);

        // softmax -> simA planes
        softmax_row384<<<Bb * Hh * Nn, 128>>>(psim, simh, siml);

        // o = a_l @ lv per (b,h,w)  (N=64 path)
        gemm(simh, siml, WS + Rr, lvTh, lvTl, Nn, nullptr, po, nullptr, nullptr, 512,
             WS, DH, WS, Bb, Hh, NW,
             (long)Hh * Nn * (WS + Rr), (long)Nn * (WS + Rr), (long)WS * (WS + Rr),
             (long)Hh * DH * Nn, (long)DH * Nn, WS,
             (long)Nn * 512, 64, (long)WS * 512,
             1.f, F_WANTC);

        // o += a_g @ gvn per (b,h) -> poA planes  (N=64 path)
        gemm(simh + WS, siml + WS, WS + Rr, gvTh, gvTl, Rr, nullptr, po, poAh, poAl, 512,
             Nn, DH, Rr, Bb, Hh, 1,
             (long)Hh * Nn * (WS + Rr), (long)Nn * (WS + Rr), 0,
             (long)Hh * DH * Rr, (long)DH * Rr, 0,
             (long)Nn * 512, 64, 0,
             1.f, F_ACC);

        // h += o @ Wo + bo
        split_t<<<dim3(16, 16, 1), 256>>>(wo, wBh, wBl, 512, 512, 0, 0);
        gemm(poAh, poAl, 512, wBh, wBl, 512, bo + l * Dd, ph, nullptr, nullptr, 512,
             MBN, 512, 512, 1, 1, 1, 0,0,0, 0,0,0, 0,0,0, 1.f, F_ACC | F_WANTC);

        // y = LN2(h) -> planes
        ln512p<<<MBN, 256>>>(ph, ln2_g + l * Dd, ln2_b + l * Dd, yAh, yAl);

        // f1 = gelu(y @ W1 + b1) -> f1A planes
        split_t<<<dim3(16, 64, 1), 256>>>(w1, wBh, wBl, 512, 2048, 0, 0);
        gemm(yAh, yAl, 512, wBh, wBl, 512, b1 + (long)l * FF, nullptr, f1h, f1l, 2048,
             MBN, 2048, 512, 1, 1, 1, 0,0,0, 0,0,0, 0,0,0, 1.f, F_GELU);

        // h += f1 @ W2 + b2
        split_t<<<dim3(64, 16, 1), 256>>>(w2, wBh, wBl, 2048, 512, 0, 0);
        gemm(f1h, f1l, 2048, wBh, wBl, 2048, b2 + l * Dd, ph, nullptr, nullptr, 512,
             MBN, 512, 2048, 1, 1, 1, 0,0,0, 0,0,0, 0,0,0, 1.f, F_ACC | F_WANTC);
    }

    // final LN + vocab projection
    ln512p<<<MBN, 256>>>(ph, lnf_g, lnf_b, yAh, yAl);
    split_t<<<dim3(16, 16, 1), 256>>>(Wlog, wBh, wBl, 512, 512, 0, 0);
    gemm(yAh, yAl, 512, wBh, wBl, 512, blog, plog, nullptr, nullptr, 512,
         MBN, 512, 512, 1, 1, 1, 0,0,0, 0,0,0, 0,0,0, 1.f, F_WANTC);

    // head
    {
        dim3 grid(NCHUNK, Bb);
        head_partial<<<grid, 256>>>(plog, Wfin, ppart);
        head_reduce<<<1, 64>>>(ppart, bfin, out);
    }
}

// round 12
// speedup vs baseline: 3.8641x; 1.1139x over previous
#include <cuda_runtime.h>
#include <cuda_bf16.h>
#include <math.h>
#include <stdint.h>

typedef unsigned short u16;

// Problem constants
#define Bb   4
#define Nn   4096
#define Vv   512
#define Dd   512
#define Hh   8
#define DH   64
#define Ll   4
#define WS   128
#define Rr   256
#define Cc   10
#define FF   2048
#define NW   (Nn / WS)
#define SCALE 0.125f
#define KFIN ((long)Nn * Vv)
#define NCHUNK 2048

// flags
#define F_ACC   1
#define F_GELU  2
#define F_WANTC 4

// ---------------- scratch (device globals; no allocation) ----------------
__device__ float g_h   [(size_t)Bb * Nn * Dd];
__device__ float g_kv  [(size_t)Bb * Nn * 2 * Hh * DH];
__device__ float g_p   [(size_t)Bb * Hh * Nn * Rr];
__device__ float g_gkv [(size_t)2 * Bb * Hh * Rr * DH];
__device__ float g_gkp [(size_t)4 * 2 * Bb * Hh * Rr * DH];
__device__ float g_gvn [(size_t)Bb * Hh * Rr * DH];
__device__ float g_lv  [(size_t)Bb * Hh * Nn * DH];
__device__ float g_sim [(size_t)Bb * Hh * Nn * (WS + Rr)];
__device__ float g_o   [(size_t)Bb * Nn * Hh * DH];
__device__ float g_log [(size_t)Bb * Nn * Vv];
__device__ float g_part[(size_t)Bb * NCHUNK * Cc];
__device__ float g_pM  [Bb * Hh * Rr];
__device__ float g_pI  [Bb * Hh * Rr];

// bf16 hi/lo planes
__device__ u16 g_yAhi [8388608],  g_yAlo [8388608];
__device__ u16 g_qAhi [8388608],  g_qAlo [8388608];
__device__ u16 g_kvAhi[16777216], g_kvAlo[16777216];
__device__ u16 g_kvThi[16777216], g_kvTlo[16777216];
__device__ u16 g_pThi [33554432], g_pTlo [33554432];
__device__ u16 g_lkhi [8388608],  g_lklo [8388608];
__device__ u16 g_gknhi[524288],   g_gknlo[524288];
__device__ u16 g_lvThi[8388608],  g_lvTlo[8388608];
__device__ u16 g_gvThi[524288],   g_gvTlo[524288];
__device__ u16 g_simhi[50331648], g_simlo[50331648];
__device__ u16 g_poAhi[8388608],  g_poAlo[8388608];
__device__ u16 g_f1Ahi[33554432], g_f1Alo[33554432];
__device__ u16 g_wBhi [1048576],  g_wBlo [1048576];

// ---------------- helpers ----------------
__device__ __forceinline__ float gelu_f(float x) {
    const float k0 = 0.7978845608028654f, k1 = 0.044715f;
    return 0.5f * x * (1.f + tanhf(k0 * (x + k1 * x * x * x)));
}
__device__ __forceinline__ uint32_t smem_u32(const void* p) {
    uint32_t a;
    asm("{ .reg .u64 t; cvta.to.shared.u64 t, %1; cvt.u32.u64 %0, t; }" : "=r"(a) : "l"(p));
    return a;
}
__device__ __forceinline__ void split_bf16(float v, u16& hi, u16& lo) {
    __nv_bfloat16 h = __float2bfloat16_rn(v);
    float rem = v - __bfloat162float(h);
    __nv_bfloat16 l = __float2bfloat16_rn(rem);
    hi = __bfloat16_as_ushort(h);
    lo = __bfloat16_as_ushort(l);
}
__device__ __forceinline__ uint32_t split_pack_hi(float v0, float v1, uint32_t& lo32) {
    u16 h0, l0, h1, l1;
    split_bf16(v0, h0, l0);
    split_bf16(v1, h1, l1);
    lo32 = (uint32_t)l0 | ((uint32_t)l1 << 16);
    return (uint32_t)h0 | ((uint32_t)h1 << 16);
}

#define LDMATRIX_X4(r0, r1, r2, r3, addr) \
    asm volatile("ldmatrix.sync.aligned.m8n8.x4.shared.b16 {%0,%1,%2,%3}, [%4];" \
        : "=r"(r0), "=r"(r1), "=r"(r2), "=r"(r3) : "r"(addr))

#define MMA_BF16(c, a, b0v, b1v) \
    asm volatile("mma.sync.aligned.m16n8k16.row.col.f32.bf16.bf16.f32 " \
        "{%0,%1,%2,%3}, {%4,%5,%6,%7}, {%8,%9}, {%0,%1,%2,%3};" \
        : "+f"((c)[0]), "+f"((c)[1]), "+f"((c)[2]), "+f"((c)[3]) \
        : "r"((a)[0]), "r"((a)[1]), "r"((a)[2]), "r"((a)[3]), "r"(b0v), "r"(b1v))

#define CP16(dst, src, sz) \
    asm volatile("cp.async.cg.shared.global [%0], [%1], 16, %2;" \
        :: "r"(dst), "l"(src), "r"(sz))
#define CP_COMMIT() asm volatile("cp.async.commit_group;")
#define CP_WAIT(n)  asm volatile("cp.async.wait_group %0;" :: "n"(n))

// ---------------- GEMM on pre-split bf16 planes ----------------
// A plane [m][k] stride lda; B plane [n][k] stride ldb. All N here are exact
// multiples of the N-tile (64 or 128), M multiple of 128, K multiple of 64.
#define PADK 40
#define PLANE_A 10240                       // 128*PADK*2
#define PB_OF(N64)   ((N64) ? 5120 : 10240) // B plane bytes (64 or 128 rows)
#define BUF_OF(N64)  (2 * PLANE_A + 2 * PB_OF(N64))
#define SMEM_OF(N64) (2 * BUF_OF(N64))      // 61440 (N64) / 81920

template<bool N64>
__device__ __forceinline__ void tc_gemm_body(
    const u16* __restrict__ Ahi, const u16* __restrict__ Alo,
    const u16* __restrict__ Bhi, const u16* __restrict__ Blo,
    const float* __restrict__ bias, float* __restrict__ C,
    u16* __restrict__ Chi, u16* __restrict__ Clo,
    int M, int N, int K, int lda, int ldb, long sCm,
    int D1, int D2,
    long a0, long a1, long a2,
    long b0, long b1, long b2,
    long c0, long c1, long c2,
    float alpha, int flags, int ksplit, long cSeg)
{
    extern __shared__ __align__(16) char smem[];
    uint32_t sb = smem_u32(smem);
    constexpr int PB  = PB_OF(N64);
    constexpr int BUF = BUF_OF(N64);

    int z = blockIdx.z;
    int seg = 0;
    if (ksplit > 1) { seg = z % ksplit; z /= ksplit; }
    int d2 = z % D2;
    int t  = z / D2;
    int d1 = t % D1;
    int d0 = t / D1;
    long aOff = (long)d0 * a0 + (long)d1 * a1 + (long)d2 * a2;
    long bOff = (long)d0 * b0 + (long)d1 * b1 + (long)d2 * b2;
    long cOff = (long)d0 * c0 + (long)d1 * c1 + (long)d2 * c2 + (long)seg * cSeg;
    int kBase = seg * K;

    int tid  = threadIdx.x;
    int lane = tid & 31;
    int wid  = tid >> 5;
    constexpr int MF = N64 ? 2 : 4;
    constexpr int MSTEP = N64 ? 32 : 64;
    constexpr int NBV = N64 ? 1 : 2;
    int wm = N64 ? (wid & 3) : (wid & 1);
    int wn = N64 ? (wid >> 2) : (wid >> 1);
    int mBase = blockIdx.y * 128;
    int nBase = blockIdx.x * (N64 ? 64 : 128);

    const int nChunks = K >> 5;     // even (K multiple of 64)

    // ---- per-thread induction load descriptors ----
    const u16 *pAh[2], *pAl[2], *pBh[NBV], *pBl[NBV];
    uint32_t dA[2], dB[NBV];
#pragma unroll
    for (int v = 0; v < 2; v++) {
        int vec = tid + v * 256;
        int row = vec >> 2, kq = (vec & 3) << 3;
        dA[v] = (uint32_t)(row * PADK + kq) * 2;
        long off = aOff + (long)(mBase + row) * lda + kBase + kq;
        pAh[v] = Ahi + off;
        pAl[v] = Alo + off;
    }
#pragma unroll
    for (int v = 0; v < NBV; v++) {
        int vec = tid + v * 256;
        int row = vec >> 2, kq = (vec & 3) << 3;
        dB[v] = (uint32_t)(row * PADK + kq) * 2;
        long off = bOff + (long)(nBase + row) * ldb + kBase + kq;
        pBh[v] = Bhi + off;
        pBl[v] = Blo + off;
    }

#define LOAD_TILES(BASE) do {                                   \
    _Pragma("unroll")                                           \
    for (int v = 0; v < 2; v++) {                               \
        CP16((BASE) + dA[v],           pAh[v], 16);             \
        CP16((BASE) + PLANE_A + dA[v], pAl[v], 16);             \
        pAh[v] += 32; pAl[v] += 32;                             \
    }                                                           \
    _Pragma("unroll")                                           \
    for (int v = 0; v < NBV; v++) {                             \
        CP16((BASE) + 2 * PLANE_A + dB[v],      pBh[v], 16);    \
        CP16((BASE) + 2 * PLANE_A + PB + dB[v], pBl[v], 16);    \
        pBh[v] += 32; pBl[v] += 32;                             \
    }                                                           \
    CP_COMMIT();                                                \
} while (0)

    float acc[MF][4][4];
#pragma unroll
    for (int i = 0; i < MF; i++)
#pragma unroll
        for (int j = 0; j < 4; j++)
#pragma unroll
            for (int e = 0; e < 4; e++) acc[i][j][e] = 0.f;

    int lrow = lane & 15;
    int lcol = (lane >> 4) * 8;

    auto compute = [&](uint32_t cbase) {
#pragma unroll
        for (int kk = 0; kk < 2; kk++) {
            int kc = kk * 16 + lcol;
            uint32_t afh[MF][4], afl[MF][4], bh[2][4], bl[2][4];
#pragma unroll
            for (int mf = 0; mf < MF; mf++) {
                uint32_t ao = cbase + (uint32_t)((wm * MSTEP + mf * 16 + lrow) * PADK + kc) * 2;
                LDMATRIX_X4(afh[mf][0], afh[mf][1], afh[mf][2], afh[mf][3], ao);
                LDMATRIX_X4(afl[mf][0], afl[mf][1], afl[mf][2], afl[mf][3], ao + PLANE_A);
            }
#pragma unroll
            for (int g = 0; g < 2; g++) {
                uint32_t bo = cbase + 2 * PLANE_A
                            + (uint32_t)((wn * 32 + g * 16 + lrow) * PADK + kc) * 2;
                LDMATRIX_X4(bh[g][0], bh[g][1], bh[g][2], bh[g][3], bo);
            }
#pragma unroll
            for (int mf = 0; mf < MF; mf++)
#pragma unroll
                for (int nf = 0; nf < 4; nf++) {
                    int g = nf >> 1, o = nf & 1;
                    MMA_BF16(acc[mf][nf], afh[mf], bh[g][o], bh[g][o + 2]);
                }
#pragma unroll
            for (int mf = 0; mf < MF; mf++)
#pragma unroll
                for (int nf = 0; nf < 4; nf++) {
                    int g = nf >> 1, o = nf & 1;
                    MMA_BF16(acc[mf][nf], afl[mf], bh[g][o], bh[g][o + 2]);
                }
#pragma unroll
            for (int g = 0; g < 2; g++) {
                uint32_t bo = cbase + 2 * PLANE_A + PB
                            + (uint32_t)((wn * 32 + g * 16 + lrow) * PADK + kc) * 2;
                LDMATRIX_X4(bl[g][0], bl[g][1], bl[g][2], bl[g][3], bo);
            }
#pragma unroll
            for (int mf = 0; mf < MF; mf++)
#pragma unroll
                for (int nf = 0; nf < 4; nf++) {
                    int g = nf >> 1, o = nf & 1;
                    MMA_BF16(acc[mf][nf], afh[mf], bl[g][o], bl[g][o + 2]);
                }
        }
    };

    // prologue: chunk 0 -> buf0
    LOAD_TILES(sb);

    for (int ch = 0; ch < nChunks; ch += 2) {
        LOAD_TILES(sb + BUF);
        CP_WAIT(1);
        __syncthreads();
        compute(sb);
        __syncthreads();
        if (ch + 2 < nChunks) {
            LOAD_TILES(sb);
            CP_WAIT(1);
        } else {
            CP_WAIT(0);
        }
        __syncthreads();
        compute(sb + BUF);
        __syncthreads();
    }
#undef LOAD_TILES

    // ---- epilogue: vectorized (N always multiple of tile -> no column guards) ----
    int grp = lane >> 2, ct = lane & 3;
#pragma unroll
    for (int mf = 0; mf < MF; mf++) {
#pragma unroll
        for (int nf = 0; nf < 4; nf++) {
            int gr = mBase + wm * MSTEP + mf * 16 + grp;
            int gc = nBase + wn * 32 + nf * 8 + ct * 2;
            float b0v = 0.f, b1v = 0.f;
            if (bias) { b0v = bias[gc]; b1v = bias[gc + 1]; }
#pragma unroll
            for (int half = 0; half < 2; half++) {
                int r = gr + half * 8;
                float v0 = alpha * acc[mf][nf][half * 2 + 0] + b0v;
                float v1 = alpha * acc[mf][nf][half * 2 + 1] + b1v;
                if (flags & F_GELU) { v0 = gelu_f(v0); v1 = gelu_f(v1); }
                long off = cOff + (long)r * sCm + gc;
                if (flags & F_ACC) {
                    float2 old = *(const float2*)(C + off);
                    v0 += old.x; v1 += old.y;
                }
                if (flags & F_WANTC) *(float2*)(C + off) = make_float2(v0, v1);
                if (Chi) {
                    uint32_t lo32, hi32 = split_pack_hi(v0, v1, lo32);
                    *(uint32_t*)(Chi + off) = hi32;
                    *(uint32_t*)(Clo + off) = lo32;
                }
            }
        }
    }
}

#define TC_ARGS_DECL \
    const u16* __restrict__ Ahi, const u16* __restrict__ Alo, \
    const u16* __restrict__ Bhi, const u16* __restrict__ Blo, \
    const float* __restrict__ bias, float* __restrict__ C, \
    u16* __restrict__ Chi, u16* __restrict__ Clo, \
    int M, int N, int K, int lda, int ldb, long sCm, \
    int D1, int D2, \
    long a0, long a1, long a2, \
    long b0, long b1, long b2, \
    long c0, long c1, long c2, \
    float alpha, int flags, int ksplit, long cSeg
#define TC_ARGS_PASS \
    Ahi, Alo, Bhi, Blo, bias, C, Chi, Clo, M, N, K, lda, ldb, sCm, D1, D2, \
    a0, a1, a2, b0, b1, b2, c0, c1, c2, alpha, flags, ksplit, cSeg

__global__ __launch_bounds__(256, 2) void tc_gemm128(TC_ARGS_DECL) {
    tc_gemm_body<false>(TC_ARGS_PASS);
}
__global__ __launch_bounds__(256, 3) void tc_gemm64(TC_ARGS_DECL) {
    tc_gemm_body<true>(TC_ARGS_PASS);
}

// ---------------- split-K partial reduce (fixed order, deterministic) ----------------
__global__ __launch_bounds__(256) void seg_reduce(
    const float* __restrict__ part, float* __restrict__ out,
    long n, int segs, long segStride)
{
    long i = (long)blockIdx.x * 256 + threadIdx.x;
    if (i < n) {
        float s = 0.f;
        for (int j = 0; j < segs; j++) s += part[(long)j * segStride + i];
        out[i] = s;
    }
}

// ---------------- split-transpose: out[n][k] = in[k][n] ----------------
__global__ __launch_bounds__(256) void split_t(
    const float* __restrict__ in, u16* __restrict__ hi, u16* __restrict__ lo,
    int inRows, int inCols, long inBatch, long outBatch)
{
    __shared__ float tbuf[32][33];
    int z = blockIdx.z;
    const float* src = in + (long)z * inBatch;
    int kb = blockIdx.x * 32;
    int nb = blockIdx.y * 32;
    int tx = threadIdx.x & 31, ty = threadIdx.x >> 5;
#pragma unroll
    for (int j = 0; j < 4; j++) {
        int r = ty + j * 8;
        tbuf[r][tx] = src[(long)(kb + r) * inCols + nb + tx];
    }
    __syncthreads();
    u16* h = hi + (long)z * outBatch;
    u16* l = lo + (long)z * outBatch;
#pragma unroll
    for (int j = 0; j < 4; j++) {
        int r = ty + j * 8;
        float v = tbuf[tx][r];
        u16 hh, ll;
        split_bf16(v, hh, ll);
        long o = (long)(nb + r) * inRows + kb + tx;
        h[o] = hh; l[o] = ll;
    }
}

// ---- p transpose with fused softmax normalize: out = exp(v - M[col]) * I[col] ----
__global__ __launch_bounds__(256) void split_t_sm(
    const float* __restrict__ in, const float* __restrict__ stM,
    const float* __restrict__ stI,
    u16* __restrict__ hi, u16* __restrict__ lo,
    int inRows, int inCols, long inBatch, long outBatch)
{
    __shared__ float tbuf[32][33];
    int z = blockIdx.z;
    const float* src = in + (long)z * inBatch;
    int kb = blockIdx.x * 32;
    int nb = blockIdx.y * 32;
    int tx = threadIdx.x & 31, ty = threadIdx.x >> 5;
#pragma unroll
    for (int j = 0; j < 4; j++) {
        int r = ty + j * 8;
        tbuf[r][tx] = src[(long)(kb + r) * inCols + nb + tx];
    }
    __syncthreads();
    u16* h = hi + (long)z * outBatch;
    u16* l = lo + (long)z * outBatch;
#pragma unroll
    for (int j = 0; j < 4; j++) {
        int r = ty + j * 8;
        int col = nb + r;
        float M = stM[(long)z * inCols + col];
        float I = stI[(long)z * inCols + col];
        float v = __expf(tbuf[tx][r] - M) * I;
        u16 hh, ll;
        split_bf16(v, hh, ll);
        long o = (long)col * inRows + kb + tx;
        h[o] = hh; l[o] = ll;
    }
}

// ---------------- LayerNorm D=512 -> planes ----------------
__global__ __launch_bounds__(256) void ln512p(
    const float* __restrict__ in, const float* __restrict__ g,
    const float* __restrict__ b, u16* __restrict__ oHi, u16* __restrict__ oLo)
{
    long row = blockIdx.x;
    const float* x = in + row * Dd;
    int tid = threadIdx.x;
    float v0 = x[tid], v1 = x[tid + 256];
    __shared__ float red[256];
    red[tid] = v0 + v1;
    __syncthreads();
    for (int s = 128; s > 0; s >>= 1) { if (tid < s) red[tid] += red[tid + s]; __syncthreads(); }
    float mu = red[0] * (1.f / Dd);
    __syncthreads();
    float d0 = v0 - mu, d1 = v1 - mu;
    red[tid] = d0 * d0 + d1 * d1;
    __syncthreads();
    for (int s = 128; s > 0; s >>= 1) { if (tid < s) red[tid] += red[tid + s]; __syncthreads(); }
    float rs = rsqrtf(red[0] * (1.f / Dd) + 1e-5f);
    float r0 = d0 * rs * g[tid] + b[tid];
    float r1 = d1 * rs * g[tid + 256] + b[tid + 256];
    u16 h0, l0, h1, l1;
    split_bf16(r0, h0, l0);
    split_bf16(r1, h1, l1);
    long o = row * Dd;
    oHi[o + tid] = h0;       oLo[o + tid] = l0;
    oHi[o + tid + 256] = h1; oLo[o + tid + 256] = l1;
}

// ---------------- LayerNorm D=64, warp/row ----------------
__global__ __launch_bounds__(128) void ln64(
    const float* __restrict__ in, const float* __restrict__ g,
    const float* __restrict__ b, float* __restrict__ outF,
    u16* __restrict__ oHi, u16* __restrict__ oLo,
    int D1, int D2, long s0, long s1, long s2)
{
    long warp = ((long)blockIdx.x * blockDim.x + threadIdx.x) >> 5;
    int lane = threadIdx.x & 31;
    long d2 = warp % D2;
    long t  = warp / D2;
    long d1 = t % D1;
    long d0 = t / D1;
    const float* x = in + d0 * s0 + d1 * s1 + d2 * s2;
    float v0 = x[lane], v1 = x[lane + 32];
    float s = v0 + v1;
#pragma unroll
    for (int o = 16; o; o >>= 1) s += __shfl_xor_sync(0xffffffffu, s, o);
    float mu = s * (1.f / 64.f);
    float q0 = v0 - mu, q1 = v1 - mu;
    float q = q0 * q0 + q1 * q1;
#pragma unroll
    for (int o = 16; o; o >>= 1) q += __shfl_xor_sync(0xffffffffu, q, o);
    float rs = rsqrtf(q * (1.f / 64.f) + 1e-5f);
    float r0 = q0 * rs * g[lane] + b[lane];
    float r1 = q1 * rs * g[lane + 32] + b[lane + 32];
    long o = warp * 64;
    if (outF) { outF[o + lane] = r0; outF[o + lane + 32] = r1; }
    if (oHi) {
        u16 h0, l0, h1, l1;
        split_bf16(r0, h0, l0);
        split_bf16(r1, h1, l1);
        oHi[o + lane] = h0;      oLo[o + lane] = l0;
        oHi[o + lane + 32] = h1; oLo[o + lane + 32] = l1;
    }
}

// ---------------- embedding ----------------
__global__ void embed(const int* __restrict__ x, const float* __restrict__ tok,
                      const float* __restrict__ pos, float* __restrict__ h)
{
    long i = (long)blockIdx.x * blockDim.x + threadIdx.x;
    if (i >= (long)Bb * Nn * Dd) return;
    int d = i % Dd;
    long bn = i / Dd;
    int n = bn % Nn;
    int tokid = x[bn];
    h[i] = tok[(long)tokid * Dd + d] + pos[(long)n * Dd + d];
}

// ------- softmax stats over axis=2 (n) of p (BH, N, R): writes M and 1/S -------
__global__ __launch_bounds__(256) void softmax_stats(
    const float* __restrict__ p, float* __restrict__ stM, float* __restrict__ stI)
{
    int blk = blockIdx.x;
    int rb  = blk % (Rr / 64);
    int bh  = blk / (Rr / 64);
    int c   = threadIdx.x % 64;
    int stripe = threadIdx.x / 64;
    const float* base = p + (long)bh * Nn * Rr + rb * 64 + c;
    const int CH = Nn / 4;
    int n0 = stripe * CH;

    float m = -1e30f, s = 0.f;
    for (int n = n0; n < n0 + CH; n++) {
        float v = base[(long)n * Rr];
        float nm = fmaxf(m, v);
        s = s * __expf(m - nm) + __expf(v - nm);
        m = nm;
    }
    __shared__ float sm[4][64], ss[4][64];
    sm[stripe][c] = m; ss[stripe][c] = s;
    __syncthreads();
    if (stripe == 0) {
        float M = -1e30f;
#pragma unroll
        for (int j = 0; j < 4; j++) M = fmaxf(M, sm[j][c]);
        float S = 0.f;
#pragma unroll
        for (int j = 0; j < 4; j++) S += ss[j][c] * __expf(sm[j][c] - M);
        stM[(long)bh * Rr + rb * 64 + c] = M;
        stI[(long)bh * Rr + rb * 64 + c] = 1.f / S;
    }
}

// ---------------- softmax over 384-wide rows -> planes ----------------
__global__ __launch_bounds__(128) void softmax_row384(
    const float* __restrict__ s, u16* __restrict__ oHi, u16* __restrict__ oLo)
{
    const float* r = s + (long)blockIdx.x * (WS + Rr);
    int tid = threadIdx.x;
    float v0 = r[tid], v1 = r[tid + 128], v2 = r[tid + 256];
    __shared__ float red[128];
    red[tid] = fmaxf(v0, fmaxf(v1, v2));
    __syncthreads();
    for (int st = 64; st > 0; st >>= 1) { if (tid < st) red[tid] = fmaxf(red[tid], red[tid + st]); __syncthreads(); }
    float m = red[0];
    __syncthreads();
    float e0 = __expf(v0 - m), e1 = __expf(v1 - m), e2 = __expf(v2 - m);
    red[tid] = e0 + e1 + e2;
    __syncthreads();
    for (int st = 64; st > 0; st >>= 1) { if (tid < st) red[tid] += red[tid + st]; __syncthreads(); }
    float inv = 1.f / red[0];
    long o = (long)blockIdx.x * (WS + Rr);
    u16 h, l;
    split_bf16(e0 * inv, h, l); oHi[o + tid] = h;       oLo[o + tid] = l;
    split_bf16(e1 * inv, h, l); oHi[o + tid + 128] = h; oLo[o + tid + 128] = l;
    split_bf16(e2 * inv, h, l); oHi[o + tid + 256] = h; oLo[o + tid + 256] = l;
}

// ---------------- final head ----------------
__global__ __launch_bounds__(256) void head_partial(
    const float* __restrict__ logits, const float* __restrict__ Wfin,
    float* __restrict__ part)
{
    int b = blockIdx.y;
    long k0 = (long)blockIdx.x * 1024;
    const float* lrow = logits + (long)b * KFIN;
    float acc[Cc];
#pragma unroll
    for (int c = 0; c < Cc; c++) acc[c] = 0.f;
    for (int i = threadIdx.x; i < 1024; i += 256) {
        long k = k0 + i;
        float l = lrow[k];
        const float* w = Wfin + k * Cc;
#pragma unroll
        for (int c = 0; c < Cc; c++) acc[c] = fmaf(l, w[c], acc[c]);
    }
#pragma unroll
    for (int c = 0; c < Cc; c++)
#pragma unroll
        for (int o = 16; o; o >>= 1) acc[c] += __shfl_xor_sync(0xffffffffu, acc[c], o);
    __shared__ float sm[8][Cc];
    int warp = threadIdx.x >> 5, lane = threadIdx.x & 31;
    if (lane == 0)
#pragma unroll
        for (int c = 0; c < Cc; c++) sm[warp][c] = acc[c];
    __syncthreads();
    if (threadIdx.x < Cc) {
        float s = 0.f;
#pragma unroll
        for (int w = 0; w < 8; w++) s += sm[w][threadIdx.x];
        part[((long)b * NCHUNK + blockIdx.x) * Cc + threadIdx.x] = s;
    }
}

__global__ void head_reduce(const float* __restrict__ part,
                            const float* __restrict__ bfin, float* __restrict__ out)
{
    int t = threadIdx.x;
    if (t < Bb * Cc) {
        int b = t / Cc, c = t % Cc;
        float s = bfin[c];
        for (int j = 0; j < NCHUNK; j++) s += part[((long)b * NCHUNK + j) * Cc + c];
        out[b * Cc + c] = s;
    }
}

// ---------------- host ----------------
static void gemm(const u16* Ahi, const u16* Alo, int lda,
                 const u16* Bhi, const u16* Blo, int ldb,
                 const float* bias, float* C, u16* Chi, u16* Clo, long sCm,
                 int M, int N, int K,
                 int D0, int D1, int D2,
                 long a0, long a1, long a2,
                 long b0, long b1, long b2,
                 long c0, long c1, long c2,
                 float alpha, int flags, int ksplit = 1, long cSeg = 0)
{
    if (N == 64) {
        dim3 grid(1, M / 128, D0 * D1 * D2 * ksplit);
        tc_gemm64<<<grid, 256, SMEM_OF(true)>>>(Ahi, Alo, Bhi, Blo, bias, C, Chi, Clo,
            M, N, K, lda, ldb, sCm, D1, D2,
            a0, a1, a2, b0, b1, b2, c0, c1, c2, alpha, flags, ksplit, cSeg);
    } else {
        dim3 grid(N / 128, M / 128, D0 * D1 * D2 * ksplit);
        tc_gemm128<<<grid, 256, SMEM_OF(false)>>>(Ahi, Alo, Bhi, Blo, bias, C, Chi, Clo,
            M, N, K, lda, ldb, sCm, D1, D2,
            a0, a1, a2, b0, b1, b2, c0, c1, c2, alpha, flags, ksplit, cSeg);
    }
}

#define SYM(p, s) cudaGetSymbolAddress((void**)&p, s)

extern "C" void kernel_launch(void* const* d_in, const int* in_sizes, int n_in,
                              void* d_out, int out_size)
{
    const int*   x_in    = (const int*)  d_in[0];
    const float* tok_emb = (const float*)d_in[1];
    const float* pos_emb = (const float*)d_in[2];
    const float* ln1_g   = (const float*)d_in[3];
    const float* ln1_b   = (const float*)d_in[4];
    const float* Wq      = (const float*)d_in[5];
    const float* Wkv     = (const float*)d_in[6];
    const float* Wp      = (const float*)d_in[7];
    const float* lln_g   = (const float*)d_in[8];
    const float* lln_b   = (const float*)d_in[9];
    const float* gln_g   = (const float*)d_in[10];
    const float* gln_b   = (const float*)d_in[11];
    const float* Wo      = (const float*)d_in[12];
    const float* bo      = (const float*)d_in[13];
    const float* ln2_g   = (const float*)d_in[14];
    const float* ln2_b   = (const float*)d_in[15];
    const float* W1      = (const float*)d_in[16];
    const float* b1      = (const float*)d_in[17];
    const float* W2      = (const float*)d_in[18];
    const float* b2      = (const float*)d_in[19];
    const float* lnf_g   = (const float*)d_in[20];
    const float* lnf_b   = (const float*)d_in[21];
    const float* Wlog    = (const float*)d_in[22];
    const float* blog    = (const float*)d_in[23];
    const float* Wfin    = (const float*)d_in[24];
    const float* bfin    = (const float*)d_in[25];
    float* out = (float*)d_out;

    cudaFuncSetAttribute(tc_gemm128, cudaFuncAttributeMaxDynamicSharedMemorySize, SMEM_OF(false));
    cudaFuncSetAttribute(tc_gemm64,  cudaFuncAttributeMaxDynamicSharedMemorySize, SMEM_OF(true));

    float *ph, *pkv, *pp, *pgkv, *pgkp, *pgvn, *plv, *psim, *po, *plog, *ppart, *ppM, *ppI;
    SYM(ph, g_h); SYM(pkv, g_kv); SYM(pp, g_p); SYM(pgkv, g_gkv); SYM(pgkp, g_gkp);
    SYM(pgvn, g_gvn); SYM(plv, g_lv); SYM(psim, g_sim); SYM(po, g_o);
    SYM(plog, g_log); SYM(ppart, g_part); SYM(ppM, g_pM); SYM(ppI, g_pI);

    u16 *yAh,*yAl,*qAh,*qAl,*kvAh,*kvAl,*kvTh,*kvTl,*pTh,*pTl,*lkh,*lkl,
        *gknh,*gknl,*lvTh,*lvTl,*gvTh,*gvTl,*simh,*siml,*poAh,*poAl,
        *f1h,*f1l,*wBh,*wBl;
    SYM(yAh, g_yAhi);  SYM(yAl, g_yAlo);
    SYM(qAh, g_qAhi);  SYM(qAl, g_qAlo);
    SYM(kvAh, g_kvAhi); SYM(kvAl, g_kvAlo);
    SYM(kvTh, g_kvThi); SYM(kvTl, g_kvTlo);
    SYM(pTh, g_pThi);  SYM(pTl, g_pTlo);
    SYM(lkh, g_lkhi);  SYM(lkl, g_lklo);
    SYM(gknh, g_gknhi); SYM(gknl, g_gknlo);
    SYM(lvTh, g_lvThi); SYM(lvTl, g_lvTlo);
    SYM(gvTh, g_gvThi); SYM(gvTl, g_gvTlo);
    SYM(simh, g_simhi); SYM(siml, g_simlo);
    SYM(poAh, g_poAhi); SYM(poAl, g_poAlo);
    SYM(f1h, g_f1Ahi); SYM(f1l, g_f1Alo);
    SYM(wBh, g_wBhi);  SYM(wBl, g_wBlo);

    const long BND = (long)Bb * Nn * Dd;
    const int  MBN = Bb * Nn;
    const long GKV = (long)Bb * Hh * Rr * DH;   // 524288

    embed<<<(BND + 255) / 256, 256>>>(x_in, tok_emb, pos_emb, ph);

    for (int l = 0; l < Ll; l++) {
        const float* wq  = Wq  + (long)l * Dd * Hh * DH;
        const float* wkv = Wkv + (long)l * Dd * 2 * Hh * DH;
        const float* wp  = Wp  + (long)l * DH * Rr;
        const float* wo  = Wo  + (long)l * Hh * DH * Dd;
        const float* w1  = W1  + (long)l * Dd * FF;
        const float* w2  = W2  + (long)l * FF * Dd;

        // y = LN1(h) -> planes
        ln512p<<<MBN, 256>>>(ph, ln1_g + l * Dd, ln1_b + l * Dd, yAh, yAl);

        // q = y @ Wq * SCALE -> qA planes
        split_t<<<dim3(16, 16, 1), 256>>>(wq, wBh, wBl, 512, 512, 0, 0);
        gemm(yAh, yAl, 512, wBh, wBl, 512, nullptr, nullptr, qAh, qAl, 512,
             MBN, 512, 512, 1, 1, 1, 0,0,0, 0,0,0, 0,0,0, SCALE, 0);

        // kv = y @ Wkv -> float + kvA planes
        split_t<<<dim3(16, 32, 1), 256>>>(wkv, wBh, wBl, 512, 1024, 0, 0);
        gemm(yAh, yAl, 512, wBh, wBl, 512, nullptr, pkv, kvAh, kvAl, 1024,
             MBN, 1024, 512, 1, 1, 1, 0,0,0, 0,0,0, 0,0,0, 1.f, F_WANTC);

        // p = k @ Wp per (b,h) -> float (raw scores)
        split_t<<<dim3(2, 8, 1), 256>>>(wp, wBh, wBl, 64, 256, 0, 0);
        gemm(kvAh, kvAl, 1024, wBh, wBl, 64, nullptr, pp, nullptr, nullptr, Rr,
             Nn, Rr, DH, Bb, Hh, 1,
             (long)Nn * 1024, 64, 0,
             0, 0, 0,
             (long)Hh * Nn * Rr, (long)Nn * Rr, 0,
             1.f, F_WANTC);

        // softmax stats (M, 1/S per (bh,r))
        softmax_stats<<<Bb * Hh * (Rr / 64), 256>>>(pp, ppM, ppI);

        // pT planes with fused exp/normalize
        split_t_sm<<<dim3(128, 8, 32), 256>>>(pp, ppM, ppI, pTh, pTl,
                                              Nn, Rr, (long)Nn * Rr, (long)Nn * Rr);
        // kvT planes
        split_t<<<dim3(128, 32, 4), 256>>>(pkv, kvTh, kvTl, Nn, 1024, (long)Nn * 1024, (long)Nn * 1024);

        // gk|gv = p^T @ {k,v} per (b,h,kv), split-K x4 -> partials -> reduce
        gemm(pTh, pTl, Nn, kvTh, kvTl, Nn, nullptr, pgkp, nullptr, nullptr, DH,
             Rr, DH, 1024, Bb, Hh, 2,
             (long)Hh * Rr * Nn, (long)Rr * Nn, 0,
             (long)1024 * Nn, (long)64 * Nn, (long)512 * Nn,
             (long)Hh * Rr * DH, (long)Rr * DH, GKV,
             1.f, F_WANTC, 4, 2 * GKV);
        seg_reduce<<<(int)((2 * GKV + 255) / 256), 256>>>(pgkp, pgkv, 2 * GKV, 4, 2 * GKV);

        // gkn planes; gvn float -> transpose planes
        ln64<<<(Bb * Hh * Rr) / 4, 128>>>(pgkv, gln_g + l * DH, gln_b + l * DH,
                                          nullptr, gknh, gknl, 1, Bb * Hh * Rr, 0, 0, DH);
        ln64<<<(Bb * Hh * Rr) / 4, 128>>>(pgkv + GKV, gln_g + l * DH, gln_b + l * DH,
                                          pgvn, nullptr, nullptr, 1, Bb * Hh * Rr, 0, 0, DH);
        split_t<<<dim3(8, 2, 32), 256>>>(pgvn, gvTh, gvTl, Rr, DH, (long)Rr * DH, (long)Rr * DH);

        // lk planes; lv float -> transpose planes
        ln64<<<(Bb * Hh * Nn) / 4, 128>>>(pkv, lln_g + l * DH, lln_b + l * DH,
                                          nullptr, lkh, lkl,
                                          Hh, Nn, (long)Nn * 1024, DH, 1024);
        ln64<<<(Bb * Hh * Nn) / 4, 128>>>(pkv + Hh * DH, lln_g + l * DH, lln_b + l * DH,
                                          plv, nullptr, nullptr,
                                          Hh, Nn, (long)Nn * 1024, DH, 1024);
        split_t<<<dim3(128, 2, 32), 256>>>(plv, lvTh, lvTl, Nn, DH, (long)Nn * DH, (long)Nn * DH);

        // sim_l per (b,h,w)
        gemm(qAh, qAl, 512, lkh, lkl, 64, nullptr, psim, nullptr, nullptr, WS + Rr,
             WS, WS, DH, Bb, Hh, NW,
             (long)Nn * 512, 64, (long)WS * 512,
             (long)Hh * Nn * 64, (long)Nn * 64, (long)WS * 64,
             (long)Hh * Nn * (WS + Rr), (long)Nn * (WS + Rr), (long)WS * (WS + Rr),
             1.f, F_WANTC);

        // sim_g per (b,h)
        gemm(qAh, qAl, 512, gknh, gknl, 64, nullptr, psim + WS, nullptr, nullptr, WS + Rr,
             Nn, Rr, DH, Bb, Hh, 1,
             (long)Nn * 512, 64, 0,
             (long)Hh * Rr * 64, (long)Rr * 64, 0,
             (long)Hh * Nn * (WS + Rr), (long)Nn * (WS + Rr), 0,
             1.f, F_WANTC);

        // softmax -> simA planes
        softmax_row384<<<Bb * Hh * Nn, 128>>>(psim, simh, siml);

        // o = a_l @ lv per (b,h,w)  (N=64 path)
        gemm(simh, siml, WS + Rr, lvTh, lvTl, Nn, nullptr, po, nullptr, nullptr, 512,
             WS, DH, WS, Bb, Hh, NW,
             (long)Hh * Nn * (WS + Rr), (long)Nn * (WS + Rr), (long)WS * (WS + Rr),
             (long)Hh * DH * Nn, (long)DH * Nn, WS,
             (long)Nn * 512, 64, (long)WS * 512,
             1.f, F_WANTC);

        // o += a_g @ gvn per (b,h) -> poA planes  (N=64 path)
        gemm(simh + WS, siml + WS, WS + Rr, gvTh, gvTl, Rr, nullptr, po, poAh, poAl, 512,
             Nn, DH, Rr, Bb, Hh, 1,
             (long)Hh * Nn * (WS + Rr), (long)Nn * (WS + Rr), 0,
             (long)Hh * DH * Rr, (long)DH * Rr, 0,
             (long)Nn * 512, 64, 0,
             1.f, F_ACC);

        // h += o @ Wo + bo
        split_t<<<dim3(16, 16, 1), 256>>>(wo, wBh, wBl, 512, 512, 0, 0);
        gemm(poAh, poAl, 512, wBh, wBl, 512, bo + l * Dd, ph, nullptr, nullptr, 512,
             MBN, 512, 512, 1, 1, 1, 0,0,0, 0,0,0, 0,0,0, 1.f, F_ACC | F_WANTC);

        // y = LN2(h) -> planes
        ln512p<<<MBN, 256>>>(ph, ln2_g + l * Dd, ln2_b + l * Dd, yAh, yAl);

        // f1 = gelu(y @ W1 + b1) -> f1A planes
        split_t<<<dim3(16, 64, 1), 256>>>(w1, wBh, wBl, 512, 2048, 0, 0);
        gemm(yAh, yAl, 512, wBh, wBl, 512, b1 + (long)l * FF, nullptr, f1h, f1l, 2048,
             MBN, 2048, 512, 1, 1, 1, 0,0,0, 0,0,0, 0,0,0, 1.f, F_GELU);

        // h += f1 @ W2 + b2
        split_t<<<dim3(64, 16, 1), 256>>>(w2, wBh, wBl, 2048, 512, 0, 0);
        gemm(f1h, f1l, 2048, wBh, wBl, 2048, b2 + l * Dd, ph, nullptr, nullptr, 512,
             MBN, 512, 2048, 1, 1, 1, 0,0,0, 0,0,0, 0,0,0, 1.f, F_ACC | F_WANTC);
    }

    // final LN + vocab projection
    ln512p<<<MBN, 256>>>(ph, lnf_g, lnf_b, yAh, yAl);
    split_t<<<dim3(16, 16, 1), 256>>>(Wlog, wBh, wBl, 512, 512, 0, 0);
    gemm(yAh, yAl, 512, wBh, wBl, 512, blog, plog, nullptr, nullptr, 512,
         MBN, 512, 512, 1, 1, 1, 0,0,0, 0,0,0, 0,0,0, 1.f, F_WANTC);

    // head
    {
        dim3 grid(NCHUNK, Bb);
        head_partial<<<grid, 256>>>(plog, Wfin, ppart);
        head_reduce<<<1, 64>>>(ppart, bfin, out);
    }
}

// round 16
// speedup vs baseline: 3.9789x; 1.0297x over previous
#include <cuda_runtime.h>
#include <cuda_bf16.h>
#include <math.h>
#include <stdint.h>

typedef unsigned short u16;

// Problem constants
#define Bb   4
#define Nn   4096
#define Vv   512
#define Dd   512
#define Hh   8
#define DH   64
#define Ll   4
#define WS   128
#define Rr   256
#define Cc   10
#define FF   2048
#define NW   (Nn / WS)
#define SCALE 0.125f
#define KFIN ((long)Nn * Vv)
#define NCHUNK 2048

// flags
#define F_ACC   1
#define F_GELU  2
#define F_WANTC 4

// ---------------- scratch (device globals; no allocation) ----------------
__device__ float g_h   [(size_t)Bb * Nn * Dd];
__device__ float g_kv  [(size_t)Bb * Nn * 2 * Hh * DH];
__device__ float g_p   [(size_t)Bb * Hh * Nn * Rr];
__device__ float g_gkv [(size_t)2 * Bb * Hh * Rr * DH];
__device__ float g_gkp [(size_t)4 * 2 * Bb * Hh * Rr * DH];
__device__ float g_gvn [(size_t)Bb * Hh * Rr * DH];
__device__ float g_lv  [(size_t)Bb * Hh * Nn * DH];
__device__ float g_sim [(size_t)Bb * Hh * Nn * (WS + Rr)];
__device__ float g_o   [(size_t)Bb * Nn * Hh * DH];
__device__ float g_log [(size_t)Bb * Nn * Vv];
__device__ float g_part[(size_t)Bb * NCHUNK * Cc];
__device__ float g_pM  [Bb * Hh * Rr];
__device__ float g_pI  [Bb * Hh * Rr];

// bf16 hi/lo planes
__device__ u16 g_yAhi [8388608],  g_yAlo [8388608];
__device__ u16 g_qAhi [8388608],  g_qAlo [8388608];
__device__ u16 g_kvAhi[16777216], g_kvAlo[16777216];
__device__ u16 g_kvThi[16777216], g_kvTlo[16777216];
__device__ u16 g_pThi [33554432], g_pTlo [33554432];
__device__ u16 g_lkhi [8388608],  g_lklo [8388608];
__device__ u16 g_gknhi[524288],   g_gknlo[524288];
__device__ u16 g_lvThi[8388608],  g_lvTlo[8388608];
__device__ u16 g_gvThi[524288],   g_gvTlo[524288];
__device__ u16 g_simhi[50331648], g_simlo[50331648];
__device__ u16 g_poAhi[8388608],  g_poAlo[8388608];
__device__ u16 g_f1Ahi[33554432], g_f1Alo[33554432];
__device__ u16 g_wBhi [1048576],  g_wBlo [1048576];

// ---------------- helpers ----------------
__device__ __forceinline__ float gelu_f(float x) {
    const float k0 = 0.7978845608028654f, k1 = 0.044715f;
    return 0.5f * x * (1.f + tanhf(k0 * (x + k1 * x * x * x)));
}
__device__ __forceinline__ uint32_t smem_u32(const void* p) {
    uint32_t a;
    asm("{ .reg .u64 t; cvta.to.shared.u64 t, %1; cvt.u32.u64 %0, t; }" : "=r"(a) : "l"(p));
    return a;
}
__device__ __forceinline__ void split_bf16(float v, u16& hi, u16& lo) {
    __nv_bfloat16 h = __float2bfloat16_rn(v);
    float rem = v - __bfloat162float(h);
    __nv_bfloat16 l = __float2bfloat16_rn(rem);
    hi = __bfloat16_as_ushort(h);
    lo = __bfloat16_as_ushort(l);
}
__device__ __forceinline__ uint32_t split_pack_hi(float v0, float v1, uint32_t& lo32) {
    u16 h0, l0, h1, l1;
    split_bf16(v0, h0, l0);
    split_bf16(v1, h1, l1);
    lo32 = (uint32_t)l0 | ((uint32_t)l1 << 16);
    return (uint32_t)h0 | ((uint32_t)h1 << 16);
}

#define LDMATRIX_X4(r0, r1, r2, r3, addr) \
    asm volatile("ldmatrix.sync.aligned.m8n8.x4.shared.b16 {%0,%1,%2,%3}, [%4];" \
        : "=r"(r0), "=r"(r1), "=r"(r2), "=r"(r3) : "r"(addr))

#define MMA_BF16(c, a, b0v, b1v) \
    asm volatile("mma.sync.aligned.m16n8k16.row.col.f32.bf16.bf16.f32 " \
        "{%0,%1,%2,%3}, {%4,%5,%6,%7}, {%8,%9}, {%0,%1,%2,%3};" \
        : "+f"((c)[0]), "+f"((c)[1]), "+f"((c)[2]), "+f"((c)[3]) \
        : "r"((a)[0]), "r"((a)[1]), "r"((a)[2]), "r"((a)[3]), "r"(b0v), "r"(b1v))

#define CP16(dst, src, sz) \
    asm volatile("cp.async.cg.shared.global [%0], [%1], 16, %2;" \
        :: "r"(dst), "l"(src), "r"(sz))
#define CP_COMMIT() asm volatile("cp.async.commit_group;")
#define CP_WAIT(n)  asm volatile("cp.async.wait_group %0;" :: "n"(n))

// ---------------- GEMM on pre-split bf16 planes ----------------
#define PADK 40
#define PLANE_A 10240                       // 128*PADK*2
#define PB_OF(N64)   ((N64) ? 5120 : 10240)
#define BUF_OF(N64)  (2 * PLANE_A + 2 * PB_OF(N64))
#define SMEM_OF(N64) (2 * BUF_OF(N64))      // 61440 (N64) / 81920

template<bool N64>
__device__ __forceinline__ void tc_gemm_body(
    const u16* __restrict__ Ahi, const u16* __restrict__ Alo,
    const u16* __restrict__ Bhi, const u16* __restrict__ Blo,
    const float* __restrict__ bias, float* __restrict__ C,
    u16* __restrict__ Chi, u16* __restrict__ Clo,
    int M, int N, int K, int lda, int ldb, long sCm,
    int D1, int D2,
    long a0, long a1, long a2,
    long b0, long b1, long b2,
    long c0, long c1, long c2,
    float alpha, int flags, int ksplit, long cSeg)
{
    extern __shared__ __align__(16) char smem[];
    uint32_t sb = smem_u32(smem);
    constexpr int PB  = PB_OF(N64);
    constexpr int BUF = BUF_OF(N64);

    int z = blockIdx.z;
    int seg = 0;
    if (ksplit > 1) { seg = z % ksplit; z /= ksplit; }
    int d2 = z % D2;
    int t  = z / D2;
    int d1 = t % D1;
    int d0 = t / D1;
    long aOff = (long)d0 * a0 + (long)d1 * a1 + (long)d2 * a2;
    long bOff = (long)d0 * b0 + (long)d1 * b1 + (long)d2 * b2;
    long cOff = (long)d0 * c0 + (long)d1 * c1 + (long)d2 * c2 + (long)seg * cSeg;
    int kBase = seg * K;

    int tid  = threadIdx.x;
    int lane = tid & 31;
    int wid  = tid >> 5;
    constexpr int MF = N64 ? 2 : 4;
    constexpr int MSTEP = N64 ? 32 : 64;
    constexpr int NBV = N64 ? 1 : 2;
    int wm = N64 ? (wid & 3) : (wid & 1);
    int wn = N64 ? (wid >> 2) : (wid >> 1);
    int mBase = blockIdx.y * 128;
    int nBase = blockIdx.x * (N64 ? 64 : 128);

    const int nChunks = K >> 5;     // even (K multiple of 64)

    const u16 *pAh[2], *pAl[2], *pBh[NBV], *pBl[NBV];
    uint32_t dA[2], dB[NBV];
#pragma unroll
    for (int v = 0; v < 2; v++) {
        int vec = tid + v * 256;
        int row = vec >> 2, kq = (vec & 3) << 3;
        dA[v] = (uint32_t)(row * PADK + kq) * 2;
        long off = aOff + (long)(mBase + row) * lda + kBase + kq;
        pAh[v] = Ahi + off;
        pAl[v] = Alo + off;
    }
#pragma unroll
    for (int v = 0; v < NBV; v++) {
        int vec = tid + v * 256;
        int row = vec >> 2, kq = (vec & 3) << 3;
        dB[v] = (uint32_t)(row * PADK + kq) * 2;
        long off = bOff + (long)(nBase + row) * ldb + kBase + kq;
        pBh[v] = Bhi + off;
        pBl[v] = Blo + off;
    }

#define LOAD_TILES(BASE) do {                                   \
    _Pragma("unroll")                                           \
    for (int v = 0; v < 2; v++) {                               \
        CP16((BASE) + dA[v],           pAh[v], 16);             \
        CP16((BASE) + PLANE_A + dA[v], pAl[v], 16);             \
        pAh[v] += 32; pAl[v] += 32;                             \
    }                                                           \
    _Pragma("unroll")                                           \
    for (int v = 0; v < NBV; v++) {                             \
        CP16((BASE) + 2 * PLANE_A + dB[v],      pBh[v], 16);    \
        CP16((BASE) + 2 * PLANE_A + PB + dB[v], pBl[v], 16);    \
        pBh[v] += 32; pBl[v] += 32;                             \
    }                                                           \
    CP_COMMIT();                                                \
} while (0)

    float acc[MF][4][4];
#pragma unroll
    for (int i = 0; i < MF; i++)
#pragma unroll
        for (int j = 0; j < 4; j++)
#pragma unroll
            for (int e = 0; e < 4; e++) acc[i][j][e] = 0.f;

    int lrow = lane & 15;
    int lcol = (lane >> 4) * 8;

    auto compute = [&](uint32_t cbase) {
#pragma unroll
        for (int kk = 0; kk < 2; kk++) {
            int kc = kk * 16 + lcol;
            uint32_t afh[MF][4], afl[MF][4], bh[2][4], bl[2][4];
#pragma unroll
            for (int mf = 0; mf < MF; mf++) {
                uint32_t ao = cbase + (uint32_t)((wm * MSTEP + mf * 16 + lrow) * PADK + kc) * 2;
                LDMATRIX_X4(afh[mf][0], afh[mf][1], afh[mf][2], afh[mf][3], ao);
                LDMATRIX_X4(afl[mf][0], afl[mf][1], afl[mf][2], afl[mf][3], ao + PLANE_A);
            }
#pragma unroll
            for (int g = 0; g < 2; g++) {
                uint32_t bo = cbase + 2 * PLANE_A
                            + (uint32_t)((wn * 32 + g * 16 + lrow) * PADK + kc) * 2;
                LDMATRIX_X4(bh[g][0], bh[g][1], bh[g][2], bh[g][3], bo);
            }
#pragma unroll
            for (int mf = 0; mf < MF; mf++)
#pragma unroll
                for (int nf = 0; nf < 4; nf++) {
                    int g = nf >> 1, o = nf & 1;
                    MMA_BF16(acc[mf][nf], afh[mf], bh[g][o], bh[g][o + 2]);
                }
#pragma unroll
            for (int mf = 0; mf < MF; mf++)
#pragma unroll
                for (int nf = 0; nf < 4; nf++) {
                    int g = nf >> 1, o = nf & 1;
                    MMA_BF16(acc[mf][nf], afl[mf], bh[g][o], bh[g][o + 2]);
                }
#pragma unroll
            for (int g = 0; g < 2; g++) {
                uint32_t bo = cbase + 2 * PLANE_A + PB
                            + (uint32_t)((wn * 32 + g * 16 + lrow) * PADK + kc) * 2;
                LDMATRIX_X4(bl[g][0], bl[g][1], bl[g][2], bl[g][3], bo);
            }
#pragma unroll
            for (int mf = 0; mf < MF; mf++)
#pragma unroll
                for (int nf = 0; nf < 4; nf++) {
                    int g = nf >> 1, o = nf & 1;
                    MMA_BF16(acc[mf][nf], afh[mf], bl[g][o], bl[g][o + 2]);
                }
        }
    };

    LOAD_TILES(sb);

    for (int ch = 0; ch < nChunks; ch += 2) {
        LOAD_TILES(sb + BUF);
        CP_WAIT(1);
        __syncthreads();
        compute(sb);
        __syncthreads();
        if (ch + 2 < nChunks) {
            LOAD_TILES(sb);
            CP_WAIT(1);
        } else {
            CP_WAIT(0);
        }
        __syncthreads();
        compute(sb + BUF);
        __syncthreads();
    }
#undef LOAD_TILES

    // ---- epilogue: vectorized ----
    int grp = lane >> 2, ct = lane & 3;
#pragma unroll
    for (int mf = 0; mf < MF; mf++) {
#pragma unroll
        for (int nf = 0; nf < 4; nf++) {
            int gr = mBase + wm * MSTEP + mf * 16 + grp;
            int gc = nBase + wn * 32 + nf * 8 + ct * 2;
            float b0v = 0.f, b1v = 0.f;
            if (bias) { b0v = bias[gc]; b1v = bias[gc + 1]; }
#pragma unroll
            for (int half = 0; half < 2; half++) {
                int r = gr + half * 8;
                float v0 = alpha * acc[mf][nf][half * 2 + 0] + b0v;
                float v1 = alpha * acc[mf][nf][half * 2 + 1] + b1v;
                if (flags & F_GELU) { v0 = gelu_f(v0); v1 = gelu_f(v1); }
                long off = cOff + (long)r * sCm + gc;
                if (flags & F_ACC) {
                    float2 old = *(const float2*)(C + off);
                    v0 += old.x; v1 += old.y;
                }
                if (flags & F_WANTC) *(float2*)(C + off) = make_float2(v0, v1);
                if (Chi) {
                    uint32_t lo32, hi32 = split_pack_hi(v0, v1, lo32);
                    *(uint32_t*)(Chi + off) = hi32;
                    *(uint32_t*)(Clo + off) = lo32;
                }
            }
        }
    }
}

#define TC_ARGS_DECL \
    const u16* __restrict__ Ahi, const u16* __restrict__ Alo, \
    const u16* __restrict__ Bhi, const u16* __restrict__ Blo, \
    const float* __restrict__ bias, float* __restrict__ C, \
    u16* __restrict__ Chi, u16* __restrict__ Clo, \
    int M, int N, int K, int lda, int ldb, long sCm, \
    int D1, int D2, \
    long a0, long a1, long a2, \
    long b0, long b1, long b2, \
    long c0, long c1, long c2, \
    float alpha, int flags, int ksplit, long cSeg
#define TC_ARGS_PASS \
    Ahi, Alo, Bhi, Blo, bias, C, Chi, Clo, M, N, K, lda, ldb, sCm, D1, D2, \
    a0, a1, a2, b0, b1, b2, c0, c1, c2, alpha, flags, ksplit, cSeg

__global__ __launch_bounds__(256, 2) void tc_gemm128(TC_ARGS_DECL) {
    tc_gemm_body<false>(TC_ARGS_PASS);
}
__global__ __launch_bounds__(256, 3) void tc_gemm64(TC_ARGS_DECL) {
    tc_gemm_body<true>(TC_ARGS_PASS);
}

// ---------------- split-K partial reduce ----------------
__global__ __launch_bounds__(256) void seg_reduce(
    const float* __restrict__ part, float* __restrict__ out,
    long n, int segs, long segStride)
{
    long i = (long)blockIdx.x * 256 + threadIdx.x;
    if (i < n) {
        float s = 0.f;
        for (int j = 0; j < segs; j++) s += part[(long)j * segStride + i];
        out[i] = s;
    }
}

// ---------------- split-transpose: out[n][k] = in[k][n], u32 packed stores ----------------
// tile: 64 k-rows x 32 n-cols. grid: (inRows/64, inCols/32, batch)
__global__ __launch_bounds__(256) void split_t(
    const float* __restrict__ in, u16* __restrict__ hi, u16* __restrict__ lo,
    int inRows, int inCols, long inBatch, long outBatch)
{
    __shared__ float tbuf[64][33];
    int z = blockIdx.z;
    const float* src = in + (long)z * inBatch;
    int kb = blockIdx.x * 64;
    int nb = blockIdx.y * 32;
    int tx = threadIdx.x & 31, ty = threadIdx.x >> 5;
#pragma unroll
    for (int j = 0; j < 8; j++) {
        int k = ty + j * 8;
        tbuf[k][tx] = src[(long)(kb + k) * inCols + nb + tx];
    }
    __syncthreads();
    u16* h = hi + (long)z * outBatch;
    u16* l = lo + (long)z * outBatch;
#pragma unroll
    for (int j = 0; j < 4; j++) {
        int r = ty + j * 8;                 // n index
        float v0 = tbuf[2 * tx][r];
        float v1 = tbuf[2 * tx + 1][r];
        uint32_t lo32, hi32 = split_pack_hi(v0, v1, lo32);
        long o = (long)(nb + r) * inRows + kb + 2 * tx;
        *(uint32_t*)(h + o) = hi32;
        *(uint32_t*)(l + o) = lo32;
    }
}

// ---- p transpose with fused softmax normalize ----
__global__ __launch_bounds__(256) void split_t_sm(
    const float* __restrict__ in, const float* __restrict__ stM,
    const float* __restrict__ stI,
    u16* __restrict__ hi, u16* __restrict__ lo,
    int inRows, int inCols, long inBatch, long outBatch)
{
    __shared__ float tbuf[64][33];
    int z = blockIdx.z;
    const float* src = in + (long)z * inBatch;
    int kb = blockIdx.x * 64;
    int nb = blockIdx.y * 32;
    int tx = threadIdx.x & 31, ty = threadIdx.x >> 5;
#pragma unroll
    for (int j = 0; j < 8; j++) {
        int k = ty + j * 8;
        tbuf[k][tx] = src[(long)(kb + k) * inCols + nb + tx];
    }
    __syncthreads();
    u16* h = hi + (long)z * outBatch;
    u16* l = lo + (long)z * outBatch;
#pragma unroll
    for (int j = 0; j < 4; j++) {
        int r = ty + j * 8;
        int col = nb + r;
        float M = stM[(long)z * inCols + col];
        float I = stI[(long)z * inCols + col];
        float v0 = __expf(tbuf[2 * tx][r] - M) * I;
        float v1 = __expf(tbuf[2 * tx + 1][r] - M) * I;
        uint32_t lo32, hi32 = split_pack_hi(v0, v1, lo32);
        long o = (long)col * inRows + kb + 2 * tx;
        *(uint32_t*)(h + o) = hi32;
        *(uint32_t*)(l + o) = lo32;
    }
}

// ---------------- LayerNorm D=512 -> planes (paired, u32 stores) ----------------
__global__ __launch_bounds__(256) void ln512p(
    const float* __restrict__ in, const float* __restrict__ g,
    const float* __restrict__ b, u16* __restrict__ oHi, u16* __restrict__ oLo)
{
    long row = blockIdx.x;
    const float* x = in + row * Dd;
    int tid = threadIdx.x;
    float2 xv = *(const float2*)(x + 2 * tid);
    __shared__ float red[256];
    red[tid] = xv.x + xv.y;
    __syncthreads();
    for (int s = 128; s > 0; s >>= 1) { if (tid < s) red[tid] += red[tid + s]; __syncthreads(); }
    float mu = red[0] * (1.f / Dd);
    __syncthreads();
    float d0 = xv.x - mu, d1 = xv.y - mu;
    red[tid] = d0 * d0 + d1 * d1;
    __syncthreads();
    for (int s = 128; s > 0; s >>= 1) { if (tid < s) red[tid] += red[tid + s]; __syncthreads(); }
    float rs = rsqrtf(red[0] * (1.f / Dd) + 1e-5f);
    float2 gv = *(const float2*)(g + 2 * tid);
    float2 bv = *(const float2*)(b + 2 * tid);
    float r0 = d0 * rs * gv.x + bv.x;
    float r1 = d1 * rs * gv.y + bv.y;
    uint32_t lo32, hi32 = split_pack_hi(r0, r1, lo32);
    long o = row * Dd + 2 * tid;
    *(uint32_t*)(oHi + o) = hi32;
    *(uint32_t*)(oLo + o) = lo32;
}

// ---------------- LayerNorm D=64, warp/row (paired) ----------------
__global__ __launch_bounds__(128) void ln64(
    const float* __restrict__ in, const float* __restrict__ g,
    const float* __restrict__ b, float* __restrict__ outF,
    u16* __restrict__ oHi, u16* __restrict__ oLo,
    int D1, int D2, long s0, long s1, long s2)
{
    long warp = ((long)blockIdx.x * blockDim.x + threadIdx.x) >> 5;
    int lane = threadIdx.x & 31;
    long d2 = warp % D2;
    long t  = warp / D2;
    long d1 = t % D1;
    long d0 = t / D1;
    const float* x = in + d0 * s0 + d1 * s1 + d2 * s2;
    float2 xv = *(const float2*)(x + 2 * lane);
    float s = xv.x + xv.y;
#pragma unroll
    for (int o = 16; o; o >>= 1) s += __shfl_xor_sync(0xffffffffu, s, o);
    float mu = s * (1.f / 64.f);
    float q0 = xv.x - mu, q1 = xv.y - mu;
    float q = q0 * q0 + q1 * q1;
#pragma unroll
    for (int o = 16; o; o >>= 1) q += __shfl_xor_sync(0xffffffffu, q, o);
    float rs = rsqrtf(q * (1.f / 64.f) + 1e-5f);
    float2 gv = *(const float2*)(g + 2 * lane);
    float2 bv = *(const float2*)(b + 2 * lane);
    float r0 = q0 * rs * gv.x + bv.x;
    float r1 = q1 * rs * gv.y + bv.y;
    long o = warp * 64 + 2 * lane;
    if (outF) *(float2*)(outF + o) = make_float2(r0, r1);
    if (oHi) {
        uint32_t lo32, hi32 = split_pack_hi(r0, r1, lo32);
        *(uint32_t*)(oHi + o) = hi32;
        *(uint32_t*)(oLo + o) = lo32;
    }
}

// ---------------- embedding ----------------
__global__ void embed(const int* __restrict__ x, const float* __restrict__ tok,
                      const float* __restrict__ pos, float* __restrict__ h)
{
    long i = (long)blockIdx.x * blockDim.x + threadIdx.x;
    if (i >= (long)Bb * Nn * Dd) return;
    int d = i % Dd;
    long bn = i / Dd;
    int n = bn % Nn;
    int tokid = x[bn];
    h[i] = tok[(long)tokid * Dd + d] + pos[(long)n * Dd + d];
}

// ------- softmax stats over axis=2 (n) of p (BH, N, R) -------
__global__ __launch_bounds__(256) void softmax_stats(
    const float* __restrict__ p, float* __restrict__ stM, float* __restrict__ stI)
{
    int blk = blockIdx.x;
    int rb  = blk % (Rr / 64);
    int bh  = blk / (Rr / 64);
    int c   = threadIdx.x % 64;
    int stripe = threadIdx.x / 64;
    const float* base = p + (long)bh * Nn * Rr + rb * 64 + c;
    const int CH = Nn / 4;
    int n0 = stripe * CH;

    float m = -1e30f, s = 0.f;
    for (int n = n0; n < n0 + CH; n++) {
        float v = base[(long)n * Rr];
        float nm = fmaxf(m, v);
        s = s * __expf(m - nm) + __expf(v - nm);
        m = nm;
    }
    __shared__ float sm[4][64], ss[4][64];
    sm[stripe][c] = m; ss[stripe][c] = s;
    __syncthreads();
    if (stripe == 0) {
        float M = -1e30f;
#pragma unroll
        for (int j = 0; j < 4; j++) M = fmaxf(M, sm[j][c]);
        float S = 0.f;
#pragma unroll
        for (int j = 0; j < 4; j++) S += ss[j][c] * __expf(sm[j][c] - M);
        stM[(long)bh * Rr + rb * 64 + c] = M;
        stI[(long)bh * Rr + rb * 64 + c] = 1.f / S;
    }
}

// ---------------- softmax over 384-wide rows -> planes (192 thr, paired) ----------------
__global__ __launch_bounds__(192) void softmax_row384(
    const float* __restrict__ s, u16* __restrict__ oHi, u16* __restrict__ oLo)
{
    const float* r = s + (long)blockIdx.x * (WS + Rr);
    int t = threadIdx.x;
    int w = t >> 5, ln = t & 31;
    float2 v = *(const float2*)(r + 2 * t);

    float m = fmaxf(v.x, v.y);
#pragma unroll
    for (int o = 16; o; o >>= 1) m = fmaxf(m, __shfl_xor_sync(0xffffffffu, m, o));
    __shared__ float wm[6], ws[6];
    if (ln == 0) wm[w] = m;
    __syncthreads();
    float M = wm[0];
#pragma unroll
    for (int j = 1; j < 6; j++) M = fmaxf(M, wm[j]);

    float e0 = __expf(v.x - M), e1 = __expf(v.y - M);
    float ssum = e0 + e1;
#pragma unroll
    for (int o = 16; o; o >>= 1) ssum += __shfl_xor_sync(0xffffffffu, ssum, o);
    if (ln == 0) ws[w] = ssum;
    __syncthreads();
    float S = 0.f;
#pragma unroll
    for (int j = 0; j < 6; j++) S += ws[j];
    float inv = 1.f / S;

    long o = (long)blockIdx.x * (WS + Rr) + 2 * t;
    uint32_t lo32, hi32 = split_pack_hi(e0 * inv, e1 * inv, lo32);
    *(uint32_t*)(oHi + o) = hi32;
    *(uint32_t*)(oLo + o) = lo32;
}

// ---------------- final head: one CTA per k-chunk, all 4 batches ----------------
__global__ __launch_bounds__(256) void head_partial(
    const float* __restrict__ logits, const float* __restrict__ Wfin,
    float* __restrict__ part)
{
    long k0 = (long)blockIdx.x * 1024;
    float acc[Bb][Cc];
#pragma unroll
    for (int b = 0; b < Bb; b++)
#pragma unroll
        for (int c = 0; c < Cc; c++) acc[b][c] = 0.f;

    for (int i = threadIdx.x; i < 1024; i += 256) {
        long k = k0 + i;
        const float* w = Wfin + k * Cc;
        float wv[Cc];
#pragma unroll
        for (int c = 0; c < Cc; c++) wv[c] = w[c];
#pragma unroll
        for (int b = 0; b < Bb; b++) {
            float l = logits[(long)b * KFIN + k];
#pragma unroll
            for (int c = 0; c < Cc; c++) acc[b][c] = fmaf(l, wv[c], acc[b][c]);
        }
    }
#pragma unroll
    for (int b = 0; b < Bb; b++)
#pragma unroll
        for (int c = 0; c < Cc; c++)
#pragma unroll
            for (int o = 16; o; o >>= 1)
                acc[b][c] += __shfl_xor_sync(0xffffffffu, acc[b][c], o);

    __shared__ float sm[8][Bb * Cc];
    int warp = threadIdx.x >> 5, lane = threadIdx.x & 31;
    if (lane == 0)
#pragma unroll
        for (int b = 0; b < Bb; b++)
#pragma unroll
            for (int c = 0; c < Cc; c++) sm[warp][b * Cc + c] = acc[b][c];
    __syncthreads();
    if (threadIdx.x < Bb * Cc) {
        int b = threadIdx.x / Cc, c = threadIdx.x % Cc;
        float s = 0.f;
#pragma unroll
        for (int w = 0; w < 8; w++) s += sm[w][threadIdx.x];
        part[((long)b * NCHUNK + blockIdx.x) * Cc + c] = s;
    }
}

__global__ void head_reduce(const float* __restrict__ part,
                            const float* __restrict__ bfin, float* __restrict__ out)
{
    int t = threadIdx.x;
    if (t < Bb * Cc) {
        int b = t / Cc, c = t % Cc;
        float s = bfin[c];
        for (int j = 0; j < NCHUNK; j++) s += part[((long)b * NCHUNK + j) * Cc + c];
        out[b * Cc + c] = s;
    }
}

// ---------------- host ----------------
static void gemm(const u16* Ahi, const u16* Alo, int lda,
                 const u16* Bhi, const u16* Blo, int ldb,
                 const float* bias, float* C, u16* Chi, u16* Clo, long sCm,
                 int M, int N, int K,
                 int D0, int D1, int D2,
                 long a0, long a1, long a2,
                 long b0, long b1, long b2,
                 long c0, long c1, long c2,
                 float alpha, int flags, int ksplit = 1, long cSeg = 0)
{
    if (N == 64) {
        dim3 grid(1, M / 128, D0 * D1 * D2 * ksplit);
        tc_gemm64<<<grid, 256, SMEM_OF(true)>>>(Ahi, Alo, Bhi, Blo, bias, C, Chi, Clo,
            M, N, K, lda, ldb, sCm, D1, D2,
            a0, a1, a2, b0, b1, b2, c0, c1, c2, alpha, flags, ksplit, cSeg);
    } else {
        dim3 grid(N / 128, M / 128, D0 * D1 * D2 * ksplit);
        tc_gemm128<<<grid, 256, SMEM_OF(false)>>>(Ahi, Alo, Bhi, Blo, bias, C, Chi, Clo,
            M, N, K, lda, ldb, sCm, D1, D2,
            a0, a1, a2, b0, b1, b2, c0, c1, c2, alpha, flags, ksplit, cSeg);
    }
}

#define SYM(p, s) cudaGetSymbolAddress((void**)&p, s)

extern "C" void kernel_launch(void* const* d_in, const int* in_sizes, int n_in,
                              void* d_out, int out_size)
{
    const int*   x_in    = (const int*)  d_in[0];
    const float* tok_emb = (const float*)d_in[1];
    const float* pos_emb = (const float*)d_in[2];
    const float* ln1_g   = (const float*)d_in[3];
    const float* ln1_b   = (const float*)d_in[4];
    const float* Wq      = (const float*)d_in[5];
    const float* Wkv     = (const float*)d_in[6];
    const float* Wp      = (const float*)d_in[7];
    const float* lln_g   = (const float*)d_in[8];
    const float* lln_b   = (const float*)d_in[9];
    const float* gln_g   = (const float*)d_in[10];
    const float* gln_b   = (const float*)d_in[11];
    const float* Wo      = (const float*)d_in[12];
    const float* bo      = (const float*)d_in[13];
    const float* ln2_g   = (const float*)d_in[14];
    const float* ln2_b   = (const float*)d_in[15];
    const float* W1      = (const float*)d_in[16];
    const float* b1      = (const float*)d_in[17];
    const float* W2      = (const float*)d_in[18];
    const float* b2      = (const float*)d_in[19];
    const float* lnf_g   = (const float*)d_in[20];
    const float* lnf_b   = (const float*)d_in[21];
    const float* Wlog    = (const float*)d_in[22];
    const float* blog    = (const float*)d_in[23];
    const float* Wfin    = (const float*)d_in[24];
    const float* bfin    = (const float*)d_in[25];
    float* out = (float*)d_out;

    cudaFuncSetAttribute(tc_gemm128, cudaFuncAttributeMaxDynamicSharedMemorySize, SMEM_OF(false));
    cudaFuncSetAttribute(tc_gemm64,  cudaFuncAttributeMaxDynamicSharedMemorySize, SMEM_OF(true));

    float *ph, *pkv, *pp, *pgkv, *pgkp, *pgvn, *plv, *psim, *po, *plog, *ppart, *ppM, *ppI;
    SYM(ph, g_h); SYM(pkv, g_kv); SYM(pp, g_p); SYM(pgkv, g_gkv); SYM(pgkp, g_gkp);
    SYM(pgvn, g_gvn); SYM(plv, g_lv); SYM(psim, g_sim); SYM(po, g_o);
    SYM(plog, g_log); SYM(ppart, g_part); SYM(ppM, g_pM); SYM(ppI, g_pI);

    u16 *yAh,*yAl,*qAh,*qAl,*kvAh,*kvAl,*kvTh,*kvTl,*pTh,*pTl,*lkh,*lkl,
        *gknh,*gknl,*lvTh,*lvTl,*gvTh,*gvTl,*simh,*siml,*poAh,*poAl,
        *f1h,*f1l,*wBh,*wBl;
    SYM(yAh, g_yAhi);  SYM(yAl, g_yAlo);
    SYM(qAh, g_qAhi);  SYM(qAl, g_qAlo);
    SYM(kvAh, g_kvAhi); SYM(kvAl, g_kvAlo);
    SYM(kvTh, g_kvThi); SYM(kvTl, g_kvTlo);
    SYM(pTh, g_pThi);  SYM(pTl, g_pTlo);
    SYM(lkh, g_lkhi);  SYM(lkl, g_lklo);
    SYM(gknh, g_gknhi); SYM(gknl, g_gknlo);
    SYM(lvTh, g_lvThi); SYM(lvTl, g_lvTlo);
    SYM(gvTh, g_gvThi); SYM(gvTl, g_gvTlo);
    SYM(simh, g_simhi); SYM(siml, g_simlo);
    SYM(poAh, g_poAhi); SYM(poAl, g_poAlo);
    SYM(f1h, g_f1Ahi); SYM(f1l, g_f1Alo);
    SYM(wBh, g_wBhi);  SYM(wBl, g_wBlo);

    const long BND = (long)Bb * Nn * Dd;
    const int  MBN = Bb * Nn;
    const long GKV = (long)Bb * Hh * Rr * DH;   // 524288

    embed<<<(BND + 255) / 256, 256>>>(x_in, tok_emb, pos_emb, ph);

    for (int l = 0; l < Ll; l++) {
        const float* wq  = Wq  + (long)l * Dd * Hh * DH;
        const float* wkv = Wkv + (long)l * Dd * 2 * Hh * DH;
        const float* wp  = Wp  + (long)l * DH * Rr;
        const float* wo  = Wo  + (long)l * Hh * DH * Dd;
        const float* w1  = W1  + (long)l * Dd * FF;
        const float* w2  = W2  + (long)l * FF * Dd;

        // y = LN1(h) -> planes
        ln512p<<<MBN, 256>>>(ph, ln1_g + l * Dd, ln1_b + l * Dd, yAh, yAl);

        // q = y @ Wq * SCALE -> qA planes
        split_t<<<dim3(8, 16, 1), 256>>>(wq, wBh, wBl, 512, 512, 0, 0);
        gemm(yAh, yAl, 512, wBh, wBl, 512, nullptr, nullptr, qAh, qAl, 512,
             MBN, 512, 512, 1, 1, 1, 0,0,0, 0,0,0, 0,0,0, SCALE, 0);

        // kv = y @ Wkv -> float + kvA planes
        split_t<<<dim3(8, 32, 1), 256>>>(wkv, wBh, wBl, 512, 1024, 0, 0);
        gemm(yAh, yAl, 512, wBh, wBl, 512, nullptr, pkv, kvAh, kvAl, 1024,
             MBN, 1024, 512, 1, 1, 1, 0,0,0, 0,0,0, 0,0,0, 1.f, F_WANTC);

        // p = k @ Wp per (b,h) -> float (raw scores)
        split_t<<<dim3(1, 8, 1), 256>>>(wp, wBh, wBl, 64, 256, 0, 0);
        gemm(kvAh, kvAl, 1024, wBh, wBl, 64, nullptr, pp, nullptr, nullptr, Rr,
             Nn, Rr, DH, Bb, Hh, 1,
             (long)Nn * 1024, 64, 0,
             0, 0, 0,
             (long)Hh * Nn * Rr, (long)Nn * Rr, 0,
             1.f, F_WANTC);

        // softmax stats
        softmax_stats<<<Bb * Hh * (Rr / 64), 256>>>(pp, ppM, ppI);

        // pT planes with fused exp/normalize
        split_t_sm<<<dim3(64, 8, 32), 256>>>(pp, ppM, ppI, pTh, pTl,
                                             Nn, Rr, (long)Nn * Rr, (long)Nn * Rr);
        // kvT planes
        split_t<<<dim3(64, 32, 4), 256>>>(pkv, kvTh, kvTl, Nn, 1024, (long)Nn * 1024, (long)Nn * 1024);

        // gk|gv = p^T @ {k,v} per (b,h,kv), split-K x4 -> partials -> reduce
        gemm(pTh, pTl, Nn, kvTh, kvTl, Nn, nullptr, pgkp, nullptr, nullptr, DH,
             Rr, DH, 1024, Bb, Hh, 2,
             (long)Hh * Rr * Nn, (long)Rr * Nn, 0,
             (long)1024 * Nn, (long)64 * Nn, (long)512 * Nn,
             (long)Hh * Rr * DH, (long)Rr * DH, GKV,
             1.f, F_WANTC, 4, 2 * GKV);
        seg_reduce<<<(int)((2 * GKV + 255) / 256), 256>>>(pgkp, pgkv, 2 * GKV, 4, 2 * GKV);

        // gkn planes; gvn float -> transpose planes
        ln64<<<(Bb * Hh * Rr) / 4, 128>>>(pgkv, gln_g + l * DH, gln_b + l * DH,
                                          nullptr, gknh, gknl, 1, Bb * Hh * Rr, 0, 0, DH);
        ln64<<<(Bb * Hh * Rr) / 4, 128>>>(pgkv + GKV, gln_g + l * DH, gln_b + l * DH,
                                          pgvn, nullptr, nullptr, 1, Bb * Hh * Rr, 0, 0, DH);
        split_t<<<dim3(4, 2, 32), 256>>>(pgvn, gvTh, gvTl, Rr, DH, (long)Rr * DH, (long)Rr * DH);

        // lk planes; lv float -> transpose planes
        ln64<<<(Bb * Hh * Nn) / 4, 128>>>(pkv, lln_g + l * DH, lln_b + l * DH,
                                          nullptr, lkh, lkl,
                                          Hh, Nn, (long)Nn * 1024, DH, 1024);
        ln64<<<(Bb * Hh * Nn) / 4, 128>>>(pkv + Hh * DH, lln_g + l * DH, lln_b + l * DH,
                                          plv, nullptr, nullptr,
                                          Hh, Nn, (long)Nn * 1024, DH, 1024);
        split_t<<<dim3(64, 2, 32), 256>>>(plv, lvTh, lvTl, Nn, DH, (long)Nn * DH, (long)Nn * DH);

        // sim_l per (b,h,w)
        gemm(qAh, qAl, 512, lkh, lkl, 64, nullptr, psim, nullptr, nullptr, WS + Rr,
             WS, WS, DH, Bb, Hh, NW,
             (long)Nn * 512, 64, (long)WS * 512,
             (long)Hh * Nn * 64, (long)Nn * 64, (long)WS * 64,
             (long)Hh * Nn * (WS + Rr), (long)Nn * (WS + Rr), (long)WS * (WS + Rr),
             1.f, F_WANTC);

        // sim_g per (b,h)
        gemm(qAh, qAl, 512, gknh, gknl, 64, nullptr, psim + WS, nullptr, nullptr, WS + Rr,
             Nn, Rr, DH, Bb, Hh, 1,
             (long)Nn * 512, 64, 0,
             (long)Hh * Rr * 64, (long)Rr * 64, 0,
             (long)Hh * Nn * (WS + Rr), (long)Nn * (WS + Rr), 0,
             1.f, F_WANTC);

        // softmax -> simA planes
        softmax_row384<<<Bb * Hh * Nn, 192>>>(psim, simh, siml);

        // o = a_l @ lv per (b,h,w)  (N=64 path)
        gemm(simh, siml, WS + Rr, lvTh, lvTl, Nn, nullptr, po, nullptr, nullptr, 512,
             WS, DH, WS, Bb, Hh, NW,
             (long)Hh * Nn * (WS + Rr), (long)Nn * (WS + Rr), (long)WS * (WS + Rr),
             (long)Hh * DH * Nn, (long)DH * Nn, WS,
             (long)Nn * 512, 64, (long)WS * 512,
             1.f, F_WANTC);

        // o += a_g @ gvn per (b,h) -> poA planes  (N=64 path)
        gemm(simh + WS, siml + WS, WS + Rr, gvTh, gvTl, Rr, nullptr, po, poAh, poAl, 512,
             Nn, DH, Rr, Bb, Hh, 1,
             (long)Hh * Nn * (WS + Rr), (long)Nn * (WS + Rr), 0,
             (long)Hh * DH * Rr, (long)DH * Rr, 0,
             (long)Nn * 512, 64, 0,
             1.f, F_ACC);

        // h += o @ Wo + bo
        split_t<<<dim3(8, 16, 1), 256>>>(wo, wBh, wBl, 512, 512, 0, 0);
        gemm(poAh, poAl, 512, wBh, wBl, 512, bo + l * Dd, ph, nullptr, nullptr, 512,
             MBN, 512, 512, 1, 1, 1, 0,0,0, 0,0,0, 0,0,0, 1.f, F_ACC | F_WANTC);

        // y = LN2(h) -> planes
        ln512p<<<MBN, 256>>>(ph, ln2_g + l * Dd, ln2_b + l * Dd, yAh, yAl);

        // f1 = gelu(y @ W1 + b1) -> f1A planes
        split_t<<<dim3(8, 64, 1), 256>>>(w1, wBh, wBl, 512, 2048, 0, 0);
        gemm(yAh, yAl, 512, wBh, wBl, 512, b1 + (long)l * FF, nullptr, f1h, f1l, 2048,
             MBN, 2048, 512, 1, 1, 1, 0,0,0, 0,0,0, 0,0,0, 1.f, F_GELU);

        // h += f1 @ W2 + b2
        split_t<<<dim3(32, 16, 1), 256>>>(w2, wBh, wBl, 2048, 512, 0, 0);
        gemm(f1h, f1l, 2048, wBh, wBl, 2048, b2 + l * Dd, ph, nullptr, nullptr, 512,
             MBN, 512, 2048, 1, 1, 1, 0,0,0, 0,0,0, 0,0,0, 1.f, F_ACC | F_WANTC);
    }

    // final LN + vocab projection
    ln512p<<<MBN, 256>>>(ph, lnf_g, lnf_b, yAh, yAl);
    split_t<<<dim3(8, 16, 1), 256>>>(Wlog, wBh, wBl, 512, 512, 0, 0);
    gemm(yAh, yAl, 512, wBh, wBl, 512, blog, plog, nullptr, nullptr, 512,
         MBN, 512, 512, 1, 1, 1, 0,0,0, 0,0,0, 0,0,0, 1.f, F_WANTC);

    // head
    head_partial<<<NCHUNK, 256>>>(plog, Wfin, ppart);
    head_reduce<<<1, 64>>>(ppart, bfin, out);
}